// round 9
// baseline (speedup 1.0000x reference)
#include <cuda_runtime.h>
#include <cuda_bf16.h>
#include <cuda_fp16.h>
#include <math.h>
#include <stdint.h>

#define B_   2
#define S_   2048
#define NH_  16
#define NKV_ 8
#define HD_  128
#define MROWS (B_ * S_)          // 4096

// ---------------- scratch (device globals; no allocation allowed) ----------
__device__ float g_q[(size_t)B_ * S_ * NH_ * HD_];
__device__ float g_k[(size_t)B_ * S_ * NKV_ * HD_];
__device__ float g_v[(size_t)B_ * S_ * NKV_ * HD_];
__device__ float g_cos[S_ * 64];
__device__ float g_sin[S_ * 64];
// pre-split fp16 copies (A-side: hi+lo; B-side: hi only)
__device__ __half g_hid_h[(size_t)MROWS * 1024];
__device__ __half g_hid_l[(size_t)MROWS * 1024];
__device__ __half g_wq_h[(size_t)1024 * 2048];
__device__ __half g_wk_h[(size_t)1024 * 1024];
__device__ __half g_wv_h[(size_t)1024 * 1024];
__device__ __half g_wo_h[(size_t)2048 * 1024];
__device__ __half g_at_h[(size_t)MROWS * 2048];
__device__ __half g_at_l[(size_t)MROWS * 2048];

// ---------------- helpers ---------------------------------------------------
__device__ __forceinline__ uint32_t smem_u32(const void* p) {
    uint32_t a;
    asm("{ .reg .u64 t; cvta.to.shared.u64 t, %1; cvt.u32.u64 %0, t; }"
        : "=r"(a) : "l"(p));
    return a;
}
__device__ __forceinline__ void ldsm4(uint32_t* r, uint32_t addr) {
    asm volatile("ldmatrix.sync.aligned.m8n8.x4.shared.b16 {%0,%1,%2,%3}, [%4];"
                 : "=r"(r[0]), "=r"(r[1]), "=r"(r[2]), "=r"(r[3]) : "r"(addr));
}
__device__ __forceinline__ void ldsm4t(uint32_t* r, uint32_t addr) {
    asm volatile("ldmatrix.sync.aligned.m8n8.x4.trans.shared.b16 {%0,%1,%2,%3}, [%4];"
                 : "=r"(r[0]), "=r"(r[1]), "=r"(r[2]), "=r"(r[3]) : "r"(addr));
}
// fp16 mma, f32 accum
__device__ __forceinline__ void mma16816h(float* c, const uint32_t* a,
                                          uint32_t b0, uint32_t b1) {
    asm volatile(
        "mma.sync.aligned.m16n8k16.row.col.f32.f16.f16.f32 "
        "{%0,%1,%2,%3}, {%4,%5,%6,%7}, {%8,%9}, {%0,%1,%2,%3};"
        : "+f"(c[0]), "+f"(c[1]), "+f"(c[2]), "+f"(c[3])
        : "r"(a[0]), "r"(a[1]), "r"(a[2]), "r"(a[3]), "r"(b0), "r"(b1));
}
__device__ __forceinline__ void sts128(uint32_t addr, uint32_t a, uint32_t b,
                                       uint32_t c, uint32_t d) {
    asm volatile("st.shared.v4.b32 [%0], {%1, %2, %3, %4};"
                 :: "r"(addr), "r"(a), "r"(b), "r"(c), "r"(d));
}
// fp16 hi/lo split (packed half2)
__device__ __forceinline__ void split2h(float a, float b, uint32_t& hi, uint32_t& lo) {
    __half2 h = __floats2half2_rn(a, b);
    float2 hf = __half22float2(h);
    __half2 l = __floats2half2_rn(a - hf.x, b - hf.y);
    hi = *(uint32_t*)&h;
    lo = *(uint32_t*)&l;
}
__device__ __forceinline__ uint32_t cvt2h(float a, float b) {
    __half2 h = __floats2half2_rn(a, b);
    return *(uint32_t*)&h;
}
// fast 2^y on the FMA pipe (no MUFU)
__device__ __forceinline__ float exp2fast(float y) {
    y = fmaxf(y, -126.0f);
    float r = y + 12582912.0f;
    float kf = r - 12582912.0f;
    float f = y - kf;
    float p = 1.3333558146e-3f;
    p = fmaf(p, f, 9.6181291076e-3f);
    p = fmaf(p, f, 5.5504108664e-2f);
    p = fmaf(p, f, 2.4022650696e-1f);
    p = fmaf(p, f, 6.9314718056e-1f);
    p = fmaf(p, f, 1.0f);
    return __int_as_float(__float_as_int(p) + (__float_as_int(r) << 23));
}

#define CP_ASYNC16(dst, src) \
    asm volatile("cp.async.cg.shared.global [%0], [%1], 16;" \
                 :: "r"(dst), "l"(src))
#define CP_COMMIT() asm volatile("cp.async.commit_group;" ::: "memory")
#define CP_WAIT1()  asm volatile("cp.async.wait_group 1;" ::: "memory")

// ============================================================================
// split kernels: fp32 -> fp16 hi (+ lo)
// ============================================================================
__global__ void split_hl_kernel(const float* __restrict__ in,
                                __half* __restrict__ hi,
                                __half* __restrict__ lo, int n8) {
    int idx = blockIdx.x * blockDim.x + threadIdx.x;
    if (idx >= n8) return;
    const float4 x0 = ((const float4*)in)[2 * idx];
    const float4 x1 = ((const float4*)in)[2 * idx + 1];
    uint4 h, l;
    split2h(x0.x, x0.y, h.x, l.x);
    split2h(x0.z, x0.w, h.y, l.y);
    split2h(x1.x, x1.y, h.z, l.z);
    split2h(x1.z, x1.w, h.w, l.w);
    ((uint4*)hi)[idx] = h;
    ((uint4*)lo)[idx] = l;
}

__global__ void split_h_kernel(const float* __restrict__ in,
                               __half* __restrict__ hi, int n8) {
    int idx = blockIdx.x * blockDim.x + threadIdx.x;
    if (idx >= n8) return;
    const float4 x0 = ((const float4*)in)[2 * idx];
    const float4 x1 = ((const float4*)in)[2 * idx + 1];
    uint4 h;
    h.x = cvt2h(x0.x, x0.y);
    h.y = cvt2h(x0.z, x0.w);
    h.z = cvt2h(x1.x, x1.y);
    h.w = cvt2h(x1.z, x1.w);
    ((uint4*)hi)[idx] = h;
}

// ============================================================================
// GEMM core (fp16 2-term Ah*Bh + Al*Bh), shared by QKV-fused and Wo kernels.
// CTA tile 128x128, KC=32, cp.async 3 stages, 256 threads, 2 CTAs/SM.
// ============================================================================
#define STG_SZ 29184u

__device__ __forceinline__ void gemm_body(
    const __half* __restrict__ Ah, const __half* __restrict__ Al,
    const __half* __restrict__ Bh, float* __restrict__ C,
    int m0, int n0, int N, int K, uint32_t sbase) {

    const int tid  = threadIdx.x;
    const int lane = tid & 31;
    const int wid  = tid >> 5;
    const int wm = (wid >> 2) * 64;
    const int wn = (wid & 3) * 32;

    float acc[4][4][4];
#pragma unroll
    for (int i = 0; i < 4; i++)
#pragma unroll
        for (int j = 0; j < 4; j++)
#pragma unroll
            for (int r = 0; r < 4; r++) acc[i][j][r] = 0.0f;

    const int a_row = tid >> 1;
    const int a_off = (tid & 1) * 16;
    const int b_kr  = tid >> 3;
    const int b_off = (tid & 7) * 16;

    const int nch = K >> 5;

#pragma unroll
    for (int c = 0; c < 2; c++) {
        const uint32_t st = sbase + (uint32_t)c * STG_SZ;
        const __half* ah = Ah + (size_t)(m0 + a_row) * K + c * 32 + a_off;
        const __half* al = Al + (size_t)(m0 + a_row) * K + c * 32 + a_off;
        uint32_t da = st + (uint32_t)(a_row * 80 + a_off * 2);
        CP_ASYNC16(da, ah);
        CP_ASYNC16(da + 16, ah + 8);
        CP_ASYNC16(da + 10240, al);
        CP_ASYNC16(da + 10256, al + 8);
        const __half* bh = Bh + (size_t)(c * 32 + b_kr) * N + n0 + b_off;
        uint32_t db = st + 20480u + (uint32_t)(b_kr * 272 + b_off * 2);
        CP_ASYNC16(db, bh);
        CP_ASYNC16(db + 16, bh + 8);
        CP_COMMIT();
    }

    for (int c = 0; c < nch; c++) {
        CP_WAIT1();
        __syncthreads();

        const uint32_t st = sbase + (uint32_t)(c % 3) * STG_SZ;
#pragma unroll
        for (int ks = 0; ks < 2; ks++) {
            uint32_t ah[4][4], al[4][4], bh[2][4];
            const uint32_t aoff =
                st + (uint32_t)((wm + (lane & 15)) * 80 +
                                (ks * 16 + ((lane >> 4) << 3)) * 2);
#pragma unroll
            for (int mt = 0; mt < 4; mt++) {
                ldsm4(ah[mt], aoff + mt * 16 * 80);
                ldsm4(al[mt], aoff + mt * 16 * 80 + 10240);
            }
            const uint32_t bbase =
                st + 20480u + (uint32_t)((ks * 16 + (lane & 15)) * 272 +
                                         (wn + ((lane >> 4) << 3)) * 2);
#pragma unroll
            for (int ng = 0; ng < 2; ng++)
                ldsm4t(bh[ng], bbase + ng * 32);
#pragma unroll
            for (int mt = 0; mt < 4; mt++)
#pragma unroll
                for (int nt = 0; nt < 4; nt++) {
                    const int ng = nt >> 1;
                    const int hf = (nt & 1) * 2;
                    mma16816h(acc[mt][nt], ah[mt], bh[ng][hf], bh[ng][hf + 1]);
                    mma16816h(acc[mt][nt], al[mt], bh[ng][hf], bh[ng][hf + 1]);
                }
        }
        __syncthreads();

        const int nc = c + 2;
        if (nc < nch) {
            const uint32_t st2 = sbase + (uint32_t)(nc % 3) * STG_SZ;
            const __half* ahp = Ah + (size_t)(m0 + a_row) * K + nc * 32 + a_off;
            const __half* alp = Al + (size_t)(m0 + a_row) * K + nc * 32 + a_off;
            uint32_t da = st2 + (uint32_t)(a_row * 80 + a_off * 2);
            CP_ASYNC16(da, ahp);
            CP_ASYNC16(da + 16, ahp + 8);
            CP_ASYNC16(da + 10240, alp);
            CP_ASYNC16(da + 10256, alp + 8);
            const __half* bhp = Bh + (size_t)(nc * 32 + b_kr) * N + n0 + b_off;
            uint32_t db = st2 + 20480u + (uint32_t)(b_kr * 272 + b_off * 2);
            CP_ASYNC16(db, bhp);
            CP_ASYNC16(db + 16, bhp + 8);
        }
        CP_COMMIT();
    }

#pragma unroll
    for (int mt = 0; mt < 4; mt++)
#pragma unroll
        for (int nt = 0; nt < 4; nt++) {
            int row = m0 + wm + mt * 16 + (lane >> 2);
            int col = n0 + wn + nt * 8 + (lane & 3) * 2;
            *(float2*)&C[(size_t)row * N + col] =
                make_float2(acc[mt][nt][0], acc[mt][nt][1]);
            *(float2*)&C[(size_t)(row + 8) * N + col] =
                make_float2(acc[mt][nt][2], acc[mt][nt][3]);
        }
}

// Fused QKV: blockIdx.x spans concatenated N space [Wq 2048 | Wk 1024 | Wv 1024]
__global__ __launch_bounds__(256, 2)
void qkv_gemm_kernel(const __half* __restrict__ Ah,
                     const __half* __restrict__ Al,
                     const __half* __restrict__ Wq,
                     const __half* __restrict__ Wk,
                     const __half* __restrict__ Wv,
                     float* __restrict__ q, float* __restrict__ k,
                     float* __restrict__ v) {
    extern __shared__ __align__(16) char dsm[];
    const int n0g = blockIdx.x * 128;
    const __half* Bh;
    float* C;
    int N, n0;
    if (n0g < 2048)      { Bh = Wq; C = q; N = 2048; n0 = n0g; }
    else if (n0g < 3072) { Bh = Wk; C = k; N = 1024; n0 = n0g - 2048; }
    else                 { Bh = Wv; C = v; N = 1024; n0 = n0g - 3072; }
    gemm_body(Ah, Al, Bh, C, blockIdx.y * 128, n0, N, 1024, smem_u32(dsm));
}

// Wo projection
__global__ __launch_bounds__(256, 2)
void wo_gemm_kernel(const __half* __restrict__ Ah,
                    const __half* __restrict__ Al,
                    const __half* __restrict__ Bh,
                    float* __restrict__ C) {
    extern __shared__ __align__(16) char dsm[];
    gemm_body(Ah, Al, Bh, C, blockIdx.y * 128, blockIdx.x * 128, 1024, 2048,
              smem_u32(dsm));
}

// ============================================================================
// RoPE cos/sin table
// ============================================================================
__global__ void rope_table_kernel(const int* __restrict__ pos,
                                  float* __restrict__ ctab,
                                  float* __restrict__ stab) {
    int idx = blockIdx.x * blockDim.x + threadIdx.x;
    if (idx >= S_ * 64) return;
    int s  = idx >> 6;
    int fi = idx & 63;
    float inv = (float)exp(-13.815510557964274 * (double)fi / 64.0);
    float ang = (float)pos[s] * inv;
    float c, sn;
    sincosf(ang, &sn, &c);
    ctab[idx] = c;
    stab[idx] = sn;
}

// ============================================================================
// RMSNorm + RoPE in-place over g_q and g_k.
// ============================================================================
__global__ void norm_rope_kernel(float* __restrict__ q, float* __restrict__ k,
                                 const float* __restrict__ qw,
                                 const float* __restrict__ kw,
                                 const float* __restrict__ ctab,
                                 const float* __restrict__ stab) {
    const int warp = (blockIdx.x * blockDim.x + threadIdx.x) >> 5;
    const int lane = threadIdx.x & 31;
    const int QROWS = B_ * S_ * NH_;

    float* ptr;
    const float* w;
    int s;
    if (warp < QROWS) {
        ptr = q + (size_t)warp * HD_;
        w = qw;
        s = (warp / NH_) % S_;
    } else {
        int r = warp - QROWS;
        ptr = k + (size_t)r * HD_;
        w = kw;
        s = (r / NKV_) % S_;
    }

    float4 x = ((const float4*)ptr)[lane];
    float ss = x.x * x.x + x.y * x.y + x.z * x.z + x.w * x.w;
#pragma unroll
    for (int off = 16; off; off >>= 1)
        ss += __shfl_xor_sync(0xffffffffu, ss, off);
    float rms = rsqrtf(ss * (1.0f / 128.0f) + 1e-6f);

    const int d0 = lane * 4;
    float xn[4];
    xn[0] = x.x * rms * w[d0 + 0];
    xn[1] = x.y * rms * w[d0 + 1];
    xn[2] = x.z * rms * w[d0 + 2];
    xn[3] = x.w * rms * w[d0 + 3];

    float out[4];
#pragma unroll
    for (int j = 0; j < 4; j++) {
        int fi = (d0 + j) & 63;
        float c  = ctab[s * 64 + fi];
        float sn = stab[s * 64 + fi];
        float partner = __shfl_xor_sync(0xffffffffu, xn[j], 16);
        out[j] = (lane < 16) ? (xn[j] * c - partner * sn)
                             : (xn[j] * c + partner * sn);
    }
    ((float4*)ptr)[lane] = make_float4(out[0], out[1], out[2], out[3]);
}

// ============================================================================
// Flash attention, fp16 2-term (unchanged R8 math), now 2 CTAs/SM.
// SMEM: Qh@0 Ql@34816 | Kh@69632 | Vh@87040  => 104448 B.
// ============================================================================
#define ASTRIDE 272

__global__ __launch_bounds__(256, 2)
void attn_mma_kernel(const float* __restrict__ qg, const float* __restrict__ kg,
                     const float* __restrict__ vg,
                     __half* __restrict__ oh, __half* __restrict__ ol) {
    extern __shared__ __align__(16) char asmem[];
    const uint32_t sb = smem_u32(asmem);
    const uint32_t Qh = sb, Ql = sb + 34816u;
    const uint32_t Kh = sb + 69632u;
    const uint32_t Vh = sb + 87040u;

    const int tid = threadIdx.x;
    const int lane = tid & 31;
    const int wid = tid >> 5;
    const int bh = blockIdx.y;
    const int b  = bh >> 4;
    const int h  = bh & 15;
    const int hk = h >> 1;
    const int qt = gridDim.x - 1 - blockIdx.x;
    const int q0 = qt * 128;
    const int wr = wid * 16;
    const float qscale = 0.1275174985f;   // 1/sqrt(128) * log2(e)

    // ---- load Q tile (pre-scaled, fp16 hi/lo)
    {
        const int r = tid >> 1;
        const int hf = (tid & 1) * 64;
        const float* qp = &qg[((size_t)(b * S_ + q0 + r) * NH_ + h) * HD_ + hf];
        const uint32_t off = (uint32_t)(r * ASTRIDE + hf * 2);
#pragma unroll
        for (int j = 0; j < 8; j++) {
            float4 x0 = ((const float4*)qp)[2 * j];
            float4 x1 = ((const float4*)qp)[2 * j + 1];
            uint32_t h0, h1, h2, h3, l0, l1, l2, l3;
            split2h(x0.x * qscale, x0.y * qscale, h0, l0);
            split2h(x0.z * qscale, x0.w * qscale, h1, l1);
            split2h(x1.x * qscale, x1.y * qscale, h2, l2);
            split2h(x1.z * qscale, x1.w * qscale, h3, l3);
            sts128(Qh + off + j * 16, h0, h1, h2, h3);
            sts128(Ql + off + j * 16, l0, l1, l2, l3);
        }
    }

    float oa[16][4];
    float m_i[2], l_i[2];
#pragma unroll
    for (int nt = 0; nt < 16; nt++)
#pragma unroll
        for (int r = 0; r < 4; r++) oa[nt][r] = 0.0f;
    m_i[0] = m_i[1] = -1e30f;
    l_i[0] = l_i[1] = 0.0f;

    const int nkt = 2 * (qt + 1);
    for (int kt = 0; kt < nkt; kt++) {
        const int k0 = kt * 64;
        __syncthreads();
        // ---- load K,V tiles (fp16 hi only)
        {
            const int r = tid >> 2;
            const int qd = (tid & 3) * 32;
            const size_t gro = ((size_t)(b * S_ + k0 + r) * NKV_ + hk) * HD_ + qd;
            const uint32_t off = (uint32_t)(r * ASTRIDE + qd * 2);
            const float* kp = &kg[gro];
            const float* vp = &vg[gro];
#pragma unroll
            for (int j = 0; j < 4; j++) {
                float4 x0 = ((const float4*)kp)[2 * j];
                float4 x1 = ((const float4*)kp)[2 * j + 1];
                sts128(Kh + off + j * 16,
                       cvt2h(x0.x, x0.y), cvt2h(x0.z, x0.w),
                       cvt2h(x1.x, x1.y), cvt2h(x1.z, x1.w));
            }
#pragma unroll
            for (int j = 0; j < 4; j++) {
                float4 x0 = ((const float4*)vp)[2 * j];
                float4 x1 = ((const float4*)vp)[2 * j + 1];
                sts128(Vh + off + j * 16,
                       cvt2h(x0.x, x0.y), cvt2h(x0.z, x0.w),
                       cvt2h(x1.x, x1.y), cvt2h(x1.z, x1.w));
            }
        }
        __syncthreads();

        // ---- S = (Qh+Ql) @ Kh^T
        float sc[8][4];
#pragma unroll
        for (int nt = 0; nt < 8; nt++)
#pragma unroll
            for (int r = 0; r < 4; r++) sc[nt][r] = 0.0f;

#pragma unroll
        for (int kc = 0; kc < 8; kc++) {
            const uint32_t aoff =
                (uint32_t)((wr + (lane & 15)) * ASTRIDE +
                           (kc * 16 + ((lane >> 4) << 3)) * 2);
            uint32_t qh4[4], ql4[4];
            ldsm4(qh4, Qh + aoff);
            ldsm4(ql4, Ql + aoff);
            const uint32_t bbase =
                (uint32_t)((((lane >> 4) << 3) + (lane & 7)) * ASTRIDE +
                           (kc * 16 + ((lane >> 3) & 1) * 8) * 2);
#pragma unroll
            for (int bg = 0; bg < 4; bg++) {
                const uint32_t boff = bbase + (uint32_t)(bg * 16 * ASTRIDE);
                uint32_t kh4[4];
                ldsm4(kh4, Kh + boff);
                mma16816h(sc[2 * bg], qh4, kh4[0], kh4[1]);
                mma16816h(sc[2 * bg], ql4, kh4[0], kh4[1]);
                mma16816h(sc[2 * bg + 1], qh4, kh4[2], kh4[3]);
                mma16816h(sc[2 * bg + 1], ql4, kh4[2], kh4[3]);
            }
        }

        // ---- causal mask (diagonal tiles only)
        const int row0 = q0 + wr + (lane >> 2);
        const int row1 = row0 + 8;
        if (kt >= 2 * qt) {
#pragma unroll
            for (int nt = 0; nt < 8; nt++) {
                int cb = k0 + nt * 8 + (lane & 3) * 2;
                if (cb > row0) sc[nt][0] = -1e30f;
                if (cb + 1 > row0) sc[nt][1] = -1e30f;
                if (cb > row1) sc[nt][2] = -1e30f;
                if (cb + 1 > row1) sc[nt][3] = -1e30f;
            }
        }

        // ---- online softmax (base-2, poly exp2)
        float mx0 = sc[0][0], mx1 = sc[0][2];
#pragma unroll
        for (int nt = 0; nt < 8; nt++) {
            mx0 = fmaxf(mx0, fmaxf(sc[nt][0], sc[nt][1]));
            mx1 = fmaxf(mx1, fmaxf(sc[nt][2], sc[nt][3]));
        }
        mx0 = fmaxf(mx0, __shfl_xor_sync(0xffffffffu, mx0, 1));
        mx0 = fmaxf(mx0, __shfl_xor_sync(0xffffffffu, mx0, 2));
        mx1 = fmaxf(mx1, __shfl_xor_sync(0xffffffffu, mx1, 1));
        mx1 = fmaxf(mx1, __shfl_xor_sync(0xffffffffu, mx1, 2));
        const float mn0 = fmaxf(m_i[0], mx0);
        const float mn1 = fmaxf(m_i[1], mx1);
        const float alpha0 = exp2fast(m_i[0] - mn0);
        const float alpha1 = exp2fast(m_i[1] - mn1);
        m_i[0] = mn0;
        m_i[1] = mn1;

        float rs0 = 0.0f, rs1 = 0.0f;
#pragma unroll
        for (int nt = 0; nt < 8; nt++) {
            sc[nt][0] = exp2fast(sc[nt][0] - mn0);
            sc[nt][1] = exp2fast(sc[nt][1] - mn0);
            sc[nt][2] = exp2fast(sc[nt][2] - mn1);
            sc[nt][3] = exp2fast(sc[nt][3] - mn1);
            rs0 += sc[nt][0] + sc[nt][1];
            rs1 += sc[nt][2] + sc[nt][3];
        }
        rs0 += __shfl_xor_sync(0xffffffffu, rs0, 1);
        rs0 += __shfl_xor_sync(0xffffffffu, rs0, 2);
        rs1 += __shfl_xor_sync(0xffffffffu, rs1, 1);
        rs1 += __shfl_xor_sync(0xffffffffu, rs1, 2);
        l_i[0] = l_i[0] * alpha0 + rs0;
        l_i[1] = l_i[1] * alpha1 + rs1;
#pragma unroll
        for (int nt = 0; nt < 16; nt++) {
            oa[nt][0] *= alpha0;
            oa[nt][1] *= alpha0;
            oa[nt][2] *= alpha1;
            oa[nt][3] *= alpha1;
        }

        // ---- O += (Ph+Pl) @ Vh
#pragma unroll
        for (int kc = 0; kc < 4; kc++) {
            uint32_t ph[4], pl[4];
            split2h(sc[2 * kc][0], sc[2 * kc][1], ph[0], pl[0]);
            split2h(sc[2 * kc][2], sc[2 * kc][3], ph[1], pl[1]);
            split2h(sc[2 * kc + 1][0], sc[2 * kc + 1][1], ph[2], pl[2]);
            split2h(sc[2 * kc + 1][2], sc[2 * kc + 1][3], ph[3], pl[3]);
            const uint32_t vbase =
                (uint32_t)((kc * 16 + (lane & 15)) * ASTRIDE +
                           (((lane >> 4) << 3)) * 2);
#pragma unroll
            for (int dg = 0; dg < 8; dg++) {
                const uint32_t voff = vbase + (uint32_t)(dg * 32);
                uint32_t vh4[4];
                ldsm4t(vh4, Vh + voff);
                mma16816h(oa[2 * dg], ph, vh4[0], vh4[1]);
                mma16816h(oa[2 * dg], pl, vh4[0], vh4[1]);
                mma16816h(oa[2 * dg + 1], ph, vh4[2], vh4[3]);
                mma16816h(oa[2 * dg + 1], pl, vh4[2], vh4[3]);
            }
        }
    }

    // ---- epilogue: O /= l, write fp16 hi/lo directly (Wo-GEMM input layout)
    const float inv0 = 1.0f / l_i[0];
    const float inv1 = 1.0f / l_i[1];
    const int row0 = q0 + wr + (lane >> 2);
#pragma unroll
    for (int nt = 0; nt < 16; nt++) {
        const int d = nt * 8 + (lane & 3) * 2;
        const size_t i0 = (size_t)(b * S_ + row0) * 2048 + h * 128 + d;
        const size_t i1 = (size_t)(b * S_ + row0 + 8) * 2048 + h * 128 + d;
        uint32_t hh, hl;
        split2h(oa[nt][0] * inv0, oa[nt][1] * inv0, hh, hl);
        *(uint32_t*)&oh[i0] = hh;
        *(uint32_t*)&ol[i0] = hl;
        split2h(oa[nt][2] * inv1, oa[nt][3] * inv1, hh, hl);
        *(uint32_t*)&oh[i1] = hh;
        *(uint32_t*)&ol[i1] = hl;
    }
}

// ============================================================================
// launch
// ============================================================================
extern "C" void kernel_launch(void* const* d_in, const int* in_sizes, int n_in,
                              void* d_out, int out_size) {
    const float* hidden = (const float*)d_in[0];
    const int*   pos    = (const int*)d_in[1];
    const float* Wq     = (const float*)d_in[2];
    const float* Wk     = (const float*)d_in[3];
    const float* Wv     = (const float*)d_in[4];
    const float* Wo     = (const float*)d_in[5];
    const float* qw     = (const float*)d_in[6];
    const float* kw     = (const float*)d_in[7];
    float* out = (float*)d_out;

    float *q, *k, *v, *ct, *st;
    cudaGetSymbolAddress((void**)&q,  g_q);
    cudaGetSymbolAddress((void**)&k,  g_k);
    cudaGetSymbolAddress((void**)&v,  g_v);
    cudaGetSymbolAddress((void**)&ct, g_cos);
    cudaGetSymbolAddress((void**)&st, g_sin);

    __half *hidh, *hidl, *wqh, *wkh, *wvh, *woh, *ath, *atl;
    cudaGetSymbolAddress((void**)&hidh, g_hid_h);
    cudaGetSymbolAddress((void**)&hidl, g_hid_l);
    cudaGetSymbolAddress((void**)&wqh,  g_wq_h);
    cudaGetSymbolAddress((void**)&wkh,  g_wk_h);
    cudaGetSymbolAddress((void**)&wvh,  g_wv_h);
    cudaGetSymbolAddress((void**)&woh,  g_wo_h);
    cudaGetSymbolAddress((void**)&ath,  g_at_h);
    cudaGetSymbolAddress((void**)&atl,  g_at_l);

    // ---- pre-split inputs
    {
        int n8;
        n8 = MROWS * 1024 / 8;
        split_hl_kernel<<<(n8 + 255) / 256, 256>>>(hidden, hidh, hidl, n8);
        n8 = 1024 * 2048 / 8;
        split_h_kernel<<<(n8 + 255) / 256, 256>>>(Wq, wqh, n8);
        n8 = 1024 * 1024 / 8;
        split_h_kernel<<<(n8 + 255) / 256, 256>>>(Wk, wkh, n8);
        split_h_kernel<<<(n8 + 255) / 256, 256>>>(Wv, wvh, n8);
        n8 = 2048 * 1024 / 8;
        split_h_kernel<<<(n8 + 255) / 256, 256>>>(Wo, woh, n8);
    }

    const int gemm_smem = 3 * (int)STG_SZ;   // 87552
    cudaFuncSetAttribute(qkv_gemm_kernel,
                         cudaFuncAttributeMaxDynamicSharedMemorySize, gemm_smem);
    cudaFuncSetAttribute(wo_gemm_kernel,
                         cudaFuncAttributeMaxDynamicSharedMemorySize, gemm_smem);

    // fused QKV projection (one launch; concatenated N = 4096)
    qkv_gemm_kernel<<<dim3(4096 / 128, MROWS / 128), 256, gemm_smem>>>(
        hidh, hidl, wqh, wkh, wvh, q, k, v);

    // RoPE table + RMSNorm/RoPE
    rope_table_kernel<<<(S_ * 64 + 255) / 256, 256>>>(pos, ct, st);
    {
        int total_warps = B_ * S_ * (NH_ + NKV_);
        norm_rope_kernel<<<total_warps / 8, 256>>>(q, k, qw, kw, ct, st);
    }

    // attention (fp16 2-term; 2 CTAs/SM)
    {
        const int attn_smem = 104448;
        cudaFuncSetAttribute(attn_mma_kernel,
                             cudaFuncAttributeMaxDynamicSharedMemorySize,
                             attn_smem);
        attn_mma_kernel<<<dim3(S_ / 128, B_ * NH_), 256, attn_smem>>>(
            q, k, v, ath, atl);
    }

    // output projection (fp16 2-term)
    wo_gemm_kernel<<<dim3(1024 / 128, MROWS / 128), 256, gemm_smem>>>(
        ath, atl, woh, out);
}

// round 10
// speedup vs baseline: 1.1410x; 1.1410x over previous
#include <cuda_runtime.h>
#include <cuda_bf16.h>
#include <cuda_fp16.h>
#include <math.h>
#include <stdint.h>

#define B_   2
#define S_   2048
#define NH_  16
#define NKV_ 8
#define HD_  128
#define MROWS (B_ * S_)          // 4096

// ---------------- scratch (device globals; no allocation allowed) ----------
__device__ float g_q[(size_t)B_ * S_ * NH_ * HD_];
__device__ float g_k[(size_t)B_ * S_ * NKV_ * HD_];
__device__ float g_v[(size_t)B_ * S_ * NKV_ * HD_];
__device__ float g_cos[S_ * 64];
__device__ float g_sin[S_ * 64];
// pre-split fp16 copies (A-side: hi+lo; B-side: hi only)
__device__ __half g_hid_h[(size_t)MROWS * 1024];
__device__ __half g_hid_l[(size_t)MROWS * 1024];
__device__ __half g_wq_h[(size_t)1024 * 2048];
__device__ __half g_wk_h[(size_t)1024 * 1024];
__device__ __half g_wv_h[(size_t)1024 * 1024];
__device__ __half g_wo_h[(size_t)2048 * 1024];
__device__ __half g_at_h[(size_t)MROWS * 2048];
__device__ __half g_at_l[(size_t)MROWS * 2048];

// ---------------- helpers ---------------------------------------------------
__device__ __forceinline__ uint32_t smem_u32(const void* p) {
    uint32_t a;
    asm("{ .reg .u64 t; cvta.to.shared.u64 t, %1; cvt.u32.u64 %0, t; }"
        : "=r"(a) : "l"(p));
    return a;
}
__device__ __forceinline__ void ldsm4(uint32_t* r, uint32_t addr) {
    asm volatile("ldmatrix.sync.aligned.m8n8.x4.shared.b16 {%0,%1,%2,%3}, [%4];"
                 : "=r"(r[0]), "=r"(r[1]), "=r"(r[2]), "=r"(r[3]) : "r"(addr));
}
__device__ __forceinline__ void ldsm4t(uint32_t* r, uint32_t addr) {
    asm volatile("ldmatrix.sync.aligned.m8n8.x4.trans.shared.b16 {%0,%1,%2,%3}, [%4];"
                 : "=r"(r[0]), "=r"(r[1]), "=r"(r[2]), "=r"(r[3]) : "r"(addr));
}
// fp16 mma, f32 accum
__device__ __forceinline__ void mma16816h(float* c, const uint32_t* a,
                                          uint32_t b0, uint32_t b1) {
    asm volatile(
        "mma.sync.aligned.m16n8k16.row.col.f32.f16.f16.f32 "
        "{%0,%1,%2,%3}, {%4,%5,%6,%7}, {%8,%9}, {%0,%1,%2,%3};"
        : "+f"(c[0]), "+f"(c[1]), "+f"(c[2]), "+f"(c[3])
        : "r"(a[0]), "r"(a[1]), "r"(a[2]), "r"(a[3]), "r"(b0), "r"(b1));
}
__device__ __forceinline__ void sts128(uint32_t addr, uint32_t a, uint32_t b,
                                       uint32_t c, uint32_t d) {
    asm volatile("st.shared.v4.b32 [%0], {%1, %2, %3, %4};"
                 :: "r"(addr), "r"(a), "r"(b), "r"(c), "r"(d));
}
// fp16 hi/lo split (packed half2)
__device__ __forceinline__ void split2h(float a, float b, uint32_t& hi, uint32_t& lo) {
    __half2 h = __floats2half2_rn(a, b);
    float2 hf = __half22float2(h);
    __half2 l = __floats2half2_rn(a - hf.x, b - hf.y);
    hi = *(uint32_t*)&h;
    lo = *(uint32_t*)&l;
}
__device__ __forceinline__ uint32_t cvt2h(float a, float b) {
    __half2 h = __floats2half2_rn(a, b);
    return *(uint32_t*)&h;
}
// fast 2^y on the FMA pipe (no MUFU)
__device__ __forceinline__ float exp2fast(float y) {
    y = fmaxf(y, -126.0f);
    float r = y + 12582912.0f;
    float kf = r - 12582912.0f;
    float f = y - kf;
    float p = 1.3333558146e-3f;
    p = fmaf(p, f, 9.6181291076e-3f);
    p = fmaf(p, f, 5.5504108664e-2f);
    p = fmaf(p, f, 2.4022650696e-1f);
    p = fmaf(p, f, 6.9314718056e-1f);
    p = fmaf(p, f, 1.0f);
    return __int_as_float(__float_as_int(p) + (__float_as_int(r) << 23));
}

#define CP_ASYNC16(dst, src) \
    asm volatile("cp.async.cg.shared.global [%0], [%1], 16;" \
                 :: "r"(dst), "l"(src))
#define CP_COMMIT() asm volatile("cp.async.commit_group;" ::: "memory")
#define CP_WAIT1()  asm volatile("cp.async.wait_group 1;" ::: "memory")

// ============================================================================
// split kernels: fp32 -> fp16 hi (+ lo)
// ============================================================================
__global__ void split_hl_kernel(const float* __restrict__ in,
                                __half* __restrict__ hi,
                                __half* __restrict__ lo, int n8) {
    int idx = blockIdx.x * blockDim.x + threadIdx.x;
    if (idx >= n8) return;
    const float4 x0 = ((const float4*)in)[2 * idx];
    const float4 x1 = ((const float4*)in)[2 * idx + 1];
    uint4 h, l;
    split2h(x0.x, x0.y, h.x, l.x);
    split2h(x0.z, x0.w, h.y, l.y);
    split2h(x1.x, x1.y, h.z, l.z);
    split2h(x1.z, x1.w, h.w, l.w);
    ((uint4*)hi)[idx] = h;
    ((uint4*)lo)[idx] = l;
}

// all four weight matrices converted in ONE launch (segmented index space)
// segments (in n8 = 8-element units): Wq 256K | Wk 128K | Wv 128K | Wo 256K
__global__ void split_weights_kernel(const float* __restrict__ Wq,
                                     const float* __restrict__ Wk,
                                     const float* __restrict__ Wv,
                                     const float* __restrict__ Wo,
                                     __half* __restrict__ wqh,
                                     __half* __restrict__ wkh,
                                     __half* __restrict__ wvh,
                                     __half* __restrict__ woh) {
    int idx = blockIdx.x * blockDim.x + threadIdx.x;
    const int NQ = 1024 * 2048 / 8;   // 262144
    const int NK = 1024 * 1024 / 8;   // 131072
    const float* in;
    __half* outp;
    int li;
    if (idx < NQ)                  { in = Wq; outp = wqh; li = idx; }
    else if (idx < NQ + NK)        { in = Wk; outp = wkh; li = idx - NQ; }
    else if (idx < NQ + 2 * NK)    { in = Wv; outp = wvh; li = idx - NQ - NK; }
    else if (idx < 2 * NQ + 2 * NK){ in = Wo; outp = woh; li = idx - NQ - 2 * NK; }
    else return;
    const float4 x0 = ((const float4*)in)[2 * li];
    const float4 x1 = ((const float4*)in)[2 * li + 1];
    uint4 h;
    h.x = cvt2h(x0.x, x0.y);
    h.y = cvt2h(x0.z, x0.w);
    h.z = cvt2h(x1.x, x1.y);
    h.w = cvt2h(x1.z, x1.w);
    ((uint4*)outp)[li] = h;
}

// ============================================================================
// GEMM core (fp16 2-term Ah*Bh + Al*Bh), shared by QKV-fused and Wo kernels.
// CTA tile 128x128, KC=32, cp.async 3 stages, 256 threads, 2 CTAs/SM.
// ============================================================================
#define STG_SZ 29184u

__device__ __forceinline__ void gemm_body(
    const __half* __restrict__ Ah, const __half* __restrict__ Al,
    const __half* __restrict__ Bh, float* __restrict__ C,
    int m0, int n0, int N, int K, uint32_t sbase) {

    const int tid  = threadIdx.x;
    const int lane = tid & 31;
    const int wid  = tid >> 5;
    const int wm = (wid >> 2) * 64;
    const int wn = (wid & 3) * 32;

    float acc[4][4][4];
#pragma unroll
    for (int i = 0; i < 4; i++)
#pragma unroll
        for (int j = 0; j < 4; j++)
#pragma unroll
            for (int r = 0; r < 4; r++) acc[i][j][r] = 0.0f;

    const int a_row = tid >> 1;
    const int a_off = (tid & 1) * 16;
    const int b_kr  = tid >> 3;
    const int b_off = (tid & 7) * 16;

    const int nch = K >> 5;

#pragma unroll
    for (int c = 0; c < 2; c++) {
        const uint32_t st = sbase + (uint32_t)c * STG_SZ;
        const __half* ah = Ah + (size_t)(m0 + a_row) * K + c * 32 + a_off;
        const __half* al = Al + (size_t)(m0 + a_row) * K + c * 32 + a_off;
        uint32_t da = st + (uint32_t)(a_row * 80 + a_off * 2);
        CP_ASYNC16(da, ah);
        CP_ASYNC16(da + 16, ah + 8);
        CP_ASYNC16(da + 10240, al);
        CP_ASYNC16(da + 10256, al + 8);
        const __half* bh = Bh + (size_t)(c * 32 + b_kr) * N + n0 + b_off;
        uint32_t db = st + 20480u + (uint32_t)(b_kr * 272 + b_off * 2);
        CP_ASYNC16(db, bh);
        CP_ASYNC16(db + 16, bh + 8);
        CP_COMMIT();
    }

    for (int c = 0; c < nch; c++) {
        CP_WAIT1();
        __syncthreads();

        const uint32_t st = sbase + (uint32_t)(c % 3) * STG_SZ;
#pragma unroll
        for (int ks = 0; ks < 2; ks++) {
            uint32_t ah[4][4], al[4][4], bh[2][4];
            const uint32_t aoff =
                st + (uint32_t)((wm + (lane & 15)) * 80 +
                                (ks * 16 + ((lane >> 4) << 3)) * 2);
#pragma unroll
            for (int mt = 0; mt < 4; mt++) {
                ldsm4(ah[mt], aoff + mt * 16 * 80);
                ldsm4(al[mt], aoff + mt * 16 * 80 + 10240);
            }
            const uint32_t bbase =
                st + 20480u + (uint32_t)((ks * 16 + (lane & 15)) * 272 +
                                         (wn + ((lane >> 4) << 3)) * 2);
#pragma unroll
            for (int ng = 0; ng < 2; ng++)
                ldsm4t(bh[ng], bbase + ng * 32);
#pragma unroll
            for (int mt = 0; mt < 4; mt++)
#pragma unroll
                for (int nt = 0; nt < 4; nt++) {
                    const int ng = nt >> 1;
                    const int hf = (nt & 1) * 2;
                    mma16816h(acc[mt][nt], ah[mt], bh[ng][hf], bh[ng][hf + 1]);
                    mma16816h(acc[mt][nt], al[mt], bh[ng][hf], bh[ng][hf + 1]);
                }
        }
        __syncthreads();

        const int nc = c + 2;
        if (nc < nch) {
            const uint32_t st2 = sbase + (uint32_t)(nc % 3) * STG_SZ;
            const __half* ahp = Ah + (size_t)(m0 + a_row) * K + nc * 32 + a_off;
            const __half* alp = Al + (size_t)(m0 + a_row) * K + nc * 32 + a_off;
            uint32_t da = st2 + (uint32_t)(a_row * 80 + a_off * 2);
            CP_ASYNC16(da, ahp);
            CP_ASYNC16(da + 16, ahp + 8);
            CP_ASYNC16(da + 10240, alp);
            CP_ASYNC16(da + 10256, alp + 8);
            const __half* bhp = Bh + (size_t)(nc * 32 + b_kr) * N + n0 + b_off;
            uint32_t db = st2 + 20480u + (uint32_t)(b_kr * 272 + b_off * 2);
            CP_ASYNC16(db, bhp);
            CP_ASYNC16(db + 16, bhp + 8);
        }
        CP_COMMIT();
    }

#pragma unroll
    for (int mt = 0; mt < 4; mt++)
#pragma unroll
        for (int nt = 0; nt < 4; nt++) {
            int row = m0 + wm + mt * 16 + (lane >> 2);
            int col = n0 + wn + nt * 8 + (lane & 3) * 2;
            *(float2*)&C[(size_t)row * N + col] =
                make_float2(acc[mt][nt][0], acc[mt][nt][1]);
            *(float2*)&C[(size_t)(row + 8) * N + col] =
                make_float2(acc[mt][nt][2], acc[mt][nt][3]);
        }
}

// Fused QKV: blockIdx.x spans concatenated N space [Wq 2048 | Wk 1024 | Wv 1024]
__global__ __launch_bounds__(256, 2)
void qkv_gemm_kernel(const __half* __restrict__ Ah,
                     const __half* __restrict__ Al,
                     const __half* __restrict__ Wq,
                     const __half* __restrict__ Wk,
                     const __half* __restrict__ Wv,
                     float* __restrict__ q, float* __restrict__ k,
                     float* __restrict__ v) {
    extern __shared__ __align__(16) char dsm[];
    const int n0g = blockIdx.x * 128;
    const __half* Bh;
    float* C;
    int N, n0;
    if (n0g < 2048)      { Bh = Wq; C = q; N = 2048; n0 = n0g; }
    else if (n0g < 3072) { Bh = Wk; C = k; N = 1024; n0 = n0g - 2048; }
    else                 { Bh = Wv; C = v; N = 1024; n0 = n0g - 3072; }
    gemm_body(Ah, Al, Bh, C, blockIdx.y * 128, n0, N, 1024, smem_u32(dsm));
}

// Wo projection
__global__ __launch_bounds__(256, 2)
void wo_gemm_kernel(const __half* __restrict__ Ah,
                    const __half* __restrict__ Al,
                    const __half* __restrict__ Bh,
                    float* __restrict__ C) {
    extern __shared__ __align__(16) char dsm[];
    gemm_body(Ah, Al, Bh, C, blockIdx.y * 128, blockIdx.x * 128, 1024, 2048,
              smem_u32(dsm));
}

// ============================================================================
// RoPE cos/sin table
// ============================================================================
__global__ void rope_table_kernel(const int* __restrict__ pos,
                                  float* __restrict__ ctab,
                                  float* __restrict__ stab) {
    int idx = blockIdx.x * blockDim.x + threadIdx.x;
    if (idx >= S_ * 64) return;
    int s  = idx >> 6;
    int fi = idx & 63;
    float inv = (float)exp(-13.815510557964274 * (double)fi / 64.0);
    float ang = (float)pos[s] * inv;
    float c, sn;
    sincosf(ang, &sn, &c);
    ctab[idx] = c;
    stab[idx] = sn;
}

// ============================================================================
// RMSNorm + RoPE in-place over g_q and g_k.
// ============================================================================
__global__ void norm_rope_kernel(float* __restrict__ q, float* __restrict__ k,
                                 const float* __restrict__ qw,
                                 const float* __restrict__ kw,
                                 const float* __restrict__ ctab,
                                 const float* __restrict__ stab) {
    const int warp = (blockIdx.x * blockDim.x + threadIdx.x) >> 5;
    const int lane = threadIdx.x & 31;
    const int QROWS = B_ * S_ * NH_;

    float* ptr;
    const float* w;
    int s;
    if (warp < QROWS) {
        ptr = q + (size_t)warp * HD_;
        w = qw;
        s = (warp / NH_) % S_;
    } else {
        int r = warp - QROWS;
        ptr = k + (size_t)r * HD_;
        w = kw;
        s = (r / NKV_) % S_;
    }

    float4 x = ((const float4*)ptr)[lane];
    float ss = x.x * x.x + x.y * x.y + x.z * x.z + x.w * x.w;
#pragma unroll
    for (int off = 16; off; off >>= 1)
        ss += __shfl_xor_sync(0xffffffffu, ss, off);
    float rms = rsqrtf(ss * (1.0f / 128.0f) + 1e-6f);

    const int d0 = lane * 4;
    float xn[4];
    xn[0] = x.x * rms * w[d0 + 0];
    xn[1] = x.y * rms * w[d0 + 1];
    xn[2] = x.z * rms * w[d0 + 2];
    xn[3] = x.w * rms * w[d0 + 3];

    float out[4];
#pragma unroll
    for (int j = 0; j < 4; j++) {
        int fi = (d0 + j) & 63;
        float c  = ctab[s * 64 + fi];
        float sn = stab[s * 64 + fi];
        float partner = __shfl_xor_sync(0xffffffffu, xn[j], 16);
        out[j] = (lane < 16) ? (xn[j] * c - partner * sn)
                             : (xn[j] * c + partner * sn);
    }
    ((float4*)ptr)[lane] = make_float4(out[0], out[1], out[2], out[3]);
}

// ============================================================================
// Flash attention, fp16 2-term (exact R8 version — occupancy 1, no spills).
// SMEM: Qh@0 Ql@34816 | Kh@69632 | Vh@87040  => 104448 B.
// ============================================================================
#define ASTRIDE 272

__global__ __launch_bounds__(256, 1)
void attn_mma_kernel(const float* __restrict__ qg, const float* __restrict__ kg,
                     const float* __restrict__ vg,
                     __half* __restrict__ oh, __half* __restrict__ ol) {
    extern __shared__ __align__(16) char asmem[];
    const uint32_t sb = smem_u32(asmem);
    const uint32_t Qh = sb, Ql = sb + 34816u;
    const uint32_t Kh = sb + 69632u;
    const uint32_t Vh = sb + 87040u;

    const int tid = threadIdx.x;
    const int lane = tid & 31;
    const int wid = tid >> 5;
    const int bh = blockIdx.y;
    const int b  = bh >> 4;
    const int h  = bh & 15;
    const int hk = h >> 1;
    const int qt = gridDim.x - 1 - blockIdx.x;
    const int q0 = qt * 128;
    const int wr = wid * 16;
    const float qscale = 0.1275174985f;   // 1/sqrt(128) * log2(e)

    // ---- load Q tile (pre-scaled, fp16 hi/lo)
    {
        const int r = tid >> 1;
        const int hf = (tid & 1) * 64;
        const float* qp = &qg[((size_t)(b * S_ + q0 + r) * NH_ + h) * HD_ + hf];
        const uint32_t off = (uint32_t)(r * ASTRIDE + hf * 2);
#pragma unroll
        for (int j = 0; j < 8; j++) {
            float4 x0 = ((const float4*)qp)[2 * j];
            float4 x1 = ((const float4*)qp)[2 * j + 1];
            uint32_t h0, h1, h2, h3, l0, l1, l2, l3;
            split2h(x0.x * qscale, x0.y * qscale, h0, l0);
            split2h(x0.z * qscale, x0.w * qscale, h1, l1);
            split2h(x1.x * qscale, x1.y * qscale, h2, l2);
            split2h(x1.z * qscale, x1.w * qscale, h3, l3);
            sts128(Qh + off + j * 16, h0, h1, h2, h3);
            sts128(Ql + off + j * 16, l0, l1, l2, l3);
        }
    }

    float oa[16][4];
    float m_i[2], l_i[2];
#pragma unroll
    for (int nt = 0; nt < 16; nt++)
#pragma unroll
        for (int r = 0; r < 4; r++) oa[nt][r] = 0.0f;
    m_i[0] = m_i[1] = -1e30f;
    l_i[0] = l_i[1] = 0.0f;

    const int nkt = 2 * (qt + 1);
    for (int kt = 0; kt < nkt; kt++) {
        const int k0 = kt * 64;
        __syncthreads();
        // ---- load K,V tiles (fp16 hi only)
        {
            const int r = tid >> 2;
            const int qd = (tid & 3) * 32;
            const size_t gro = ((size_t)(b * S_ + k0 + r) * NKV_ + hk) * HD_ + qd;
            const uint32_t off = (uint32_t)(r * ASTRIDE + qd * 2);
            const float* kp = &kg[gro];
            const float* vp = &vg[gro];
#pragma unroll
            for (int j = 0; j < 4; j++) {
                float4 x0 = ((const float4*)kp)[2 * j];
                float4 x1 = ((const float4*)kp)[2 * j + 1];
                sts128(Kh + off + j * 16,
                       cvt2h(x0.x, x0.y), cvt2h(x0.z, x0.w),
                       cvt2h(x1.x, x1.y), cvt2h(x1.z, x1.w));
            }
#pragma unroll
            for (int j = 0; j < 4; j++) {
                float4 x0 = ((const float4*)vp)[2 * j];
                float4 x1 = ((const float4*)vp)[2 * j + 1];
                sts128(Vh + off + j * 16,
                       cvt2h(x0.x, x0.y), cvt2h(x0.z, x0.w),
                       cvt2h(x1.x, x1.y), cvt2h(x1.z, x1.w));
            }
        }
        __syncthreads();

        // ---- S = (Qh+Ql) @ Kh^T
        float sc[8][4];
#pragma unroll
        for (int nt = 0; nt < 8; nt++)
#pragma unroll
            for (int r = 0; r < 4; r++) sc[nt][r] = 0.0f;

#pragma unroll
        for (int kc = 0; kc < 8; kc++) {
            const uint32_t aoff =
                (uint32_t)((wr + (lane & 15)) * ASTRIDE +
                           (kc * 16 + ((lane >> 4) << 3)) * 2);
            uint32_t qh4[4], ql4[4];
            ldsm4(qh4, Qh + aoff);
            ldsm4(ql4, Ql + aoff);
            const uint32_t bbase =
                (uint32_t)((((lane >> 4) << 3) + (lane & 7)) * ASTRIDE +
                           (kc * 16 + ((lane >> 3) & 1) * 8) * 2);
#pragma unroll
            for (int bg = 0; bg < 4; bg++) {
                const uint32_t boff = bbase + (uint32_t)(bg * 16 * ASTRIDE);
                uint32_t kh4[4];
                ldsm4(kh4, Kh + boff);
                mma16816h(sc[2 * bg], qh4, kh4[0], kh4[1]);
                mma16816h(sc[2 * bg], ql4, kh4[0], kh4[1]);
                mma16816h(sc[2 * bg + 1], qh4, kh4[2], kh4[3]);
                mma16816h(sc[2 * bg + 1], ql4, kh4[2], kh4[3]);
            }
        }

        // ---- causal mask (diagonal tiles only)
        const int row0 = q0 + wr + (lane >> 2);
        const int row1 = row0 + 8;
        if (kt >= 2 * qt) {
#pragma unroll
            for (int nt = 0; nt < 8; nt++) {
                int cb = k0 + nt * 8 + (lane & 3) * 2;
                if (cb > row0) sc[nt][0] = -1e30f;
                if (cb + 1 > row0) sc[nt][1] = -1e30f;
                if (cb > row1) sc[nt][2] = -1e30f;
                if (cb + 1 > row1) sc[nt][3] = -1e30f;
            }
        }

        // ---- online softmax (base-2, poly exp2)
        float mx0 = sc[0][0], mx1 = sc[0][2];
#pragma unroll
        for (int nt = 0; nt < 8; nt++) {
            mx0 = fmaxf(mx0, fmaxf(sc[nt][0], sc[nt][1]));
            mx1 = fmaxf(mx1, fmaxf(sc[nt][2], sc[nt][3]));
        }
        mx0 = fmaxf(mx0, __shfl_xor_sync(0xffffffffu, mx0, 1));
        mx0 = fmaxf(mx0, __shfl_xor_sync(0xffffffffu, mx0, 2));
        mx1 = fmaxf(mx1, __shfl_xor_sync(0xffffffffu, mx1, 1));
        mx1 = fmaxf(mx1, __shfl_xor_sync(0xffffffffu, mx1, 2));
        const float mn0 = fmaxf(m_i[0], mx0);
        const float mn1 = fmaxf(m_i[1], mx1);
        const float alpha0 = exp2fast(m_i[0] - mn0);
        const float alpha1 = exp2fast(m_i[1] - mn1);
        m_i[0] = mn0;
        m_i[1] = mn1;

        float rs0 = 0.0f, rs1 = 0.0f;
#pragma unroll
        for (int nt = 0; nt < 8; nt++) {
            sc[nt][0] = exp2fast(sc[nt][0] - mn0);
            sc[nt][1] = exp2fast(sc[nt][1] - mn0);
            sc[nt][2] = exp2fast(sc[nt][2] - mn1);
            sc[nt][3] = exp2fast(sc[nt][3] - mn1);
            rs0 += sc[nt][0] + sc[nt][1];
            rs1 += sc[nt][2] + sc[nt][3];
        }
        rs0 += __shfl_xor_sync(0xffffffffu, rs0, 1);
        rs0 += __shfl_xor_sync(0xffffffffu, rs0, 2);
        rs1 += __shfl_xor_sync(0xffffffffu, rs1, 1);
        rs1 += __shfl_xor_sync(0xffffffffu, rs1, 2);
        l_i[0] = l_i[0] * alpha0 + rs0;
        l_i[1] = l_i[1] * alpha1 + rs1;
#pragma unroll
        for (int nt = 0; nt < 16; nt++) {
            oa[nt][0] *= alpha0;
            oa[nt][1] *= alpha0;
            oa[nt][2] *= alpha1;
            oa[nt][3] *= alpha1;
        }

        // ---- O += (Ph+Pl) @ Vh
#pragma unroll
        for (int kc = 0; kc < 4; kc++) {
            uint32_t ph[4], pl[4];
            split2h(sc[2 * kc][0], sc[2 * kc][1], ph[0], pl[0]);
            split2h(sc[2 * kc][2], sc[2 * kc][3], ph[1], pl[1]);
            split2h(sc[2 * kc + 1][0], sc[2 * kc + 1][1], ph[2], pl[2]);
            split2h(sc[2 * kc + 1][2], sc[2 * kc + 1][3], ph[3], pl[3]);
            const uint32_t vbase =
                (uint32_t)((kc * 16 + (lane & 15)) * ASTRIDE +
                           (((lane >> 4) << 3)) * 2);
#pragma unroll
            for (int dg = 0; dg < 8; dg++) {
                const uint32_t voff = vbase + (uint32_t)(dg * 32);
                uint32_t vh4[4];
                ldsm4t(vh4, Vh + voff);
                mma16816h(oa[2 * dg], ph, vh4[0], vh4[1]);
                mma16816h(oa[2 * dg], pl, vh4[0], vh4[1]);
                mma16816h(oa[2 * dg + 1], ph, vh4[2], vh4[3]);
                mma16816h(oa[2 * dg + 1], pl, vh4[2], vh4[3]);
            }
        }
    }

    // ---- epilogue: O /= l, write fp16 hi/lo directly (Wo-GEMM input layout)
    const float inv0 = 1.0f / l_i[0];
    const float inv1 = 1.0f / l_i[1];
    const int row0 = q0 + wr + (lane >> 2);
#pragma unroll
    for (int nt = 0; nt < 16; nt++) {
        const int d = nt * 8 + (lane & 3) * 2;
        const size_t i0 = (size_t)(b * S_ + row0) * 2048 + h * 128 + d;
        const size_t i1 = (size_t)(b * S_ + row0 + 8) * 2048 + h * 128 + d;
        uint32_t hh, hl;
        split2h(oa[nt][0] * inv0, oa[nt][1] * inv0, hh, hl);
        *(uint32_t*)&oh[i0] = hh;
        *(uint32_t*)&ol[i0] = hl;
        split2h(oa[nt][2] * inv1, oa[nt][3] * inv1, hh, hl);
        *(uint32_t*)&oh[i1] = hh;
        *(uint32_t*)&ol[i1] = hl;
    }
}

// ============================================================================
// launch
// ============================================================================
extern "C" void kernel_launch(void* const* d_in, const int* in_sizes, int n_in,
                              void* d_out, int out_size) {
    const float* hidden = (const float*)d_in[0];
    const int*   pos    = (const int*)d_in[1];
    const float* Wq     = (const float*)d_in[2];
    const float* Wk     = (const float*)d_in[3];
    const float* Wv     = (const float*)d_in[4];
    const float* Wo     = (const float*)d_in[5];
    const float* qw     = (const float*)d_in[6];
    const float* kw     = (const float*)d_in[7];
    float* out = (float*)d_out;

    float *q, *k, *v, *ct, *st;
    cudaGetSymbolAddress((void**)&q,  g_q);
    cudaGetSymbolAddress((void**)&k,  g_k);
    cudaGetSymbolAddress((void**)&v,  g_v);
    cudaGetSymbolAddress((void**)&ct, g_cos);
    cudaGetSymbolAddress((void**)&st, g_sin);

    __half *hidh, *hidl, *wqh, *wkh, *wvh, *woh, *ath, *atl;
    cudaGetSymbolAddress((void**)&hidh, g_hid_h);
    cudaGetSymbolAddress((void**)&hidl, g_hid_l);
    cudaGetSymbolAddress((void**)&wqh,  g_wq_h);
    cudaGetSymbolAddress((void**)&wkh,  g_wk_h);
    cudaGetSymbolAddress((void**)&wvh,  g_wv_h);
    cudaGetSymbolAddress((void**)&woh,  g_wo_h);
    cudaGetSymbolAddress((void**)&ath,  g_at_h);
    cudaGetSymbolAddress((void**)&atl,  g_at_l);

    // ---- pre-split inputs (activations hi/lo; all weights in one launch)
    {
        int n8 = MROWS * 1024 / 8;
        split_hl_kernel<<<(n8 + 255) / 256, 256>>>(hidden, hidh, hidl, n8);
        int tw = 2 * (1024 * 2048 / 8) + 2 * (1024 * 1024 / 8);  // 786432
        split_weights_kernel<<<(tw + 255) / 256, 256>>>(
            Wq, Wk, Wv, Wo, wqh, wkh, wvh, woh);
    }

    const int gemm_smem = 3 * (int)STG_SZ;   // 87552
    cudaFuncSetAttribute(qkv_gemm_kernel,
                         cudaFuncAttributeMaxDynamicSharedMemorySize, gemm_smem);
    cudaFuncSetAttribute(wo_gemm_kernel,
                         cudaFuncAttributeMaxDynamicSharedMemorySize, gemm_smem);

    // fused QKV projection (one launch; concatenated N = 4096)
    qkv_gemm_kernel<<<dim3(4096 / 128, MROWS / 128), 256, gemm_smem>>>(
        hidh, hidl, wqh, wkh, wvh, q, k, v);

    // RoPE table + RMSNorm/RoPE
    rope_table_kernel<<<(S_ * 64 + 255) / 256, 256>>>(pos, ct, st);
    {
        int total_warps = B_ * S_ * (NH_ + NKV_);
        norm_rope_kernel<<<total_warps / 8, 256>>>(q, k, qw, kw, ct, st);
    }

    // attention (fp16 2-term; occupancy 1 — R8 proven)
    {
        const int attn_smem = 104448;
        cudaFuncSetAttribute(attn_mma_kernel,
                             cudaFuncAttributeMaxDynamicSharedMemorySize,
                             attn_smem);
        attn_mma_kernel<<<dim3(S_ / 128, B_ * NH_), 256, attn_smem>>>(
            q, k, v, ath, atl);
    }

    // output projection (fp16 2-term)
    wo_gemm_kernel<<<dim3(1024 / 128, MROWS / 128), 256, gemm_smem>>>(
        ath, atl, woh, out);
}

// round 11
// speedup vs baseline: 1.3819x; 1.2111x over previous
#include <cuda_runtime.h>
#include <cuda_bf16.h>
#include <cuda_fp16.h>
#include <math.h>
#include <stdint.h>

#define B_   2
#define S_   2048
#define NH_  16
#define NKV_ 8
#define HD_  128
#define MROWS (B_ * S_)          // 4096

// ---------------- scratch (device globals; no allocation allowed) ----------
__device__ float g_q[(size_t)B_ * S_ * NH_ * HD_];
__device__ float g_k[(size_t)B_ * S_ * NKV_ * HD_];
__device__ float g_v[(size_t)B_ * S_ * NKV_ * HD_];
__device__ float g_cos[S_ * 64];
__device__ float g_sin[S_ * 64];
// pre-split fp16 copies
__device__ __half g_hid_h[(size_t)MROWS * 1024];
__device__ __half g_hid_l[(size_t)MROWS * 1024];
__device__ __half g_wq_h[(size_t)1024 * 2048];
__device__ __half g_wk_h[(size_t)1024 * 1024];
__device__ __half g_wv_h[(size_t)1024 * 1024];
__device__ __half g_wo_h[(size_t)2048 * 1024];
__device__ __half g_at_h[(size_t)MROWS * 2048];
__device__ __half g_at_l[(size_t)MROWS * 2048];
// fp16 q/k/v for attention (q pre-scaled hi/lo; k,v hi only)
__device__ __half g_qh[(size_t)B_ * S_ * NH_ * HD_];
__device__ __half g_ql[(size_t)B_ * S_ * NH_ * HD_];
__device__ __half g_kh[(size_t)B_ * S_ * NKV_ * HD_];
__device__ __half g_vh[(size_t)B_ * S_ * NKV_ * HD_];

// ---------------- helpers ---------------------------------------------------
__device__ __forceinline__ uint32_t smem_u32(const void* p) {
    uint32_t a;
    asm("{ .reg .u64 t; cvta.to.shared.u64 t, %1; cvt.u32.u64 %0, t; }"
        : "=r"(a) : "l"(p));
    return a;
}
__device__ __forceinline__ void ldsm4(uint32_t* r, uint32_t addr) {
    asm volatile("ldmatrix.sync.aligned.m8n8.x4.shared.b16 {%0,%1,%2,%3}, [%4];"
                 : "=r"(r[0]), "=r"(r[1]), "=r"(r[2]), "=r"(r[3]) : "r"(addr));
}
__device__ __forceinline__ void ldsm4t(uint32_t* r, uint32_t addr) {
    asm volatile("ldmatrix.sync.aligned.m8n8.x4.trans.shared.b16 {%0,%1,%2,%3}, [%4];"
                 : "=r"(r[0]), "=r"(r[1]), "=r"(r[2]), "=r"(r[3]) : "r"(addr));
}
// fp16 mma, f32 accum
__device__ __forceinline__ void mma16816h(float* c, const uint32_t* a,
                                          uint32_t b0, uint32_t b1) {
    asm volatile(
        "mma.sync.aligned.m16n8k16.row.col.f32.f16.f16.f32 "
        "{%0,%1,%2,%3}, {%4,%5,%6,%7}, {%8,%9}, {%0,%1,%2,%3};"
        : "+f"(c[0]), "+f"(c[1]), "+f"(c[2]), "+f"(c[3])
        : "r"(a[0]), "r"(a[1]), "r"(a[2]), "r"(a[3]), "r"(b0), "r"(b1));
}
__device__ __forceinline__ void sts128(uint32_t addr, uint32_t a, uint32_t b,
                                       uint32_t c, uint32_t d) {
    asm volatile("st.shared.v4.b32 [%0], {%1, %2, %3, %4};"
                 :: "r"(addr), "r"(a), "r"(b), "r"(c), "r"(d));
}
// fp16 hi/lo split (packed half2)
__device__ __forceinline__ void split2h(float a, float b, uint32_t& hi, uint32_t& lo) {
    __half2 h = __floats2half2_rn(a, b);
    float2 hf = __half22float2(h);
    __half2 l = __floats2half2_rn(a - hf.x, b - hf.y);
    hi = *(uint32_t*)&h;
    lo = *(uint32_t*)&l;
}
__device__ __forceinline__ uint32_t cvt2h(float a, float b) {
    __half2 h = __floats2half2_rn(a, b);
    return *(uint32_t*)&h;
}
// fast 2^y on the FMA pipe (no MUFU)
__device__ __forceinline__ float exp2fast(float y) {
    y = fmaxf(y, -126.0f);
    float r = y + 12582912.0f;
    float kf = r - 12582912.0f;
    float f = y - kf;
    float p = 1.3333558146e-3f;
    p = fmaf(p, f, 9.6181291076e-3f);
    p = fmaf(p, f, 5.5504108664e-2f);
    p = fmaf(p, f, 2.4022650696e-1f);
    p = fmaf(p, f, 6.9314718056e-1f);
    p = fmaf(p, f, 1.0f);
    return __int_as_float(__float_as_int(p) + (__float_as_int(r) << 23));
}

#define CP_ASYNC16(dst, src) \
    asm volatile("cp.async.cg.shared.global [%0], [%1], 16;" \
                 :: "r"(dst), "l"(src))
#define CP_COMMIT() asm volatile("cp.async.commit_group;" ::: "memory")
#define CP_WAIT1()  asm volatile("cp.async.wait_group 1;" ::: "memory")

// ============================================================================
// split kernels: fp32 -> fp16 hi (+ lo)
// ============================================================================
__global__ void split_hl_kernel(const float* __restrict__ in,
                                __half* __restrict__ hi,
                                __half* __restrict__ lo, int n8) {
    int idx = blockIdx.x * blockDim.x + threadIdx.x;
    if (idx >= n8) return;
    const float4 x0 = ((const float4*)in)[2 * idx];
    const float4 x1 = ((const float4*)in)[2 * idx + 1];
    uint4 h, l;
    split2h(x0.x, x0.y, h.x, l.x);
    split2h(x0.z, x0.w, h.y, l.y);
    split2h(x1.x, x1.y, h.z, l.z);
    split2h(x1.z, x1.w, h.w, l.w);
    ((uint4*)hi)[idx] = h;
    ((uint4*)lo)[idx] = l;
}

// all four weight matrices converted in ONE launch (segmented index space)
__global__ void split_weights_kernel(const float* __restrict__ Wq,
                                     const float* __restrict__ Wk,
                                     const float* __restrict__ Wv,
                                     const float* __restrict__ Wo,
                                     __half* __restrict__ wqh,
                                     __half* __restrict__ wkh,
                                     __half* __restrict__ wvh,
                                     __half* __restrict__ woh) {
    int idx = blockIdx.x * blockDim.x + threadIdx.x;
    const int NQ = 1024 * 2048 / 8;   // 262144
    const int NK = 1024 * 1024 / 8;   // 131072
    const float* in;
    __half* outp;
    int li;
    if (idx < NQ)                  { in = Wq; outp = wqh; li = idx; }
    else if (idx < NQ + NK)        { in = Wk; outp = wkh; li = idx - NQ; }
    else if (idx < NQ + 2 * NK)    { in = Wv; outp = wvh; li = idx - NQ - NK; }
    else if (idx < 2 * NQ + 2 * NK){ in = Wo; outp = woh; li = idx - NQ - 2 * NK; }
    else return;
    const float4 x0 = ((const float4*)in)[2 * li];
    const float4 x1 = ((const float4*)in)[2 * li + 1];
    uint4 h;
    h.x = cvt2h(x0.x, x0.y);
    h.y = cvt2h(x0.z, x0.w);
    h.z = cvt2h(x1.x, x1.y);
    h.w = cvt2h(x1.z, x1.w);
    ((uint4*)outp)[li] = h;
}

// ============================================================================
// GEMM core (fp16 2-term Ah*Bh + Al*Bh) — unchanged R10 proven.
// ============================================================================
#define STG_SZ 29184u

__device__ __forceinline__ void gemm_body(
    const __half* __restrict__ Ah, const __half* __restrict__ Al,
    const __half* __restrict__ Bh, float* __restrict__ C,
    int m0, int n0, int N, int K, uint32_t sbase) {

    const int tid  = threadIdx.x;
    const int lane = tid & 31;
    const int wid  = tid >> 5;
    const int wm = (wid >> 2) * 64;
    const int wn = (wid & 3) * 32;

    float acc[4][4][4];
#pragma unroll
    for (int i = 0; i < 4; i++)
#pragma unroll
        for (int j = 0; j < 4; j++)
#pragma unroll
            for (int r = 0; r < 4; r++) acc[i][j][r] = 0.0f;

    const int a_row = tid >> 1;
    const int a_off = (tid & 1) * 16;
    const int b_kr  = tid >> 3;
    const int b_off = (tid & 7) * 16;

    const int nch = K >> 5;

#pragma unroll
    for (int c = 0; c < 2; c++) {
        const uint32_t st = sbase + (uint32_t)c * STG_SZ;
        const __half* ah = Ah + (size_t)(m0 + a_row) * K + c * 32 + a_off;
        const __half* al = Al + (size_t)(m0 + a_row) * K + c * 32 + a_off;
        uint32_t da = st + (uint32_t)(a_row * 80 + a_off * 2);
        CP_ASYNC16(da, ah);
        CP_ASYNC16(da + 16, ah + 8);
        CP_ASYNC16(da + 10240, al);
        CP_ASYNC16(da + 10256, al + 8);
        const __half* bh = Bh + (size_t)(c * 32 + b_kr) * N + n0 + b_off;
        uint32_t db = st + 20480u + (uint32_t)(b_kr * 272 + b_off * 2);
        CP_ASYNC16(db, bh);
        CP_ASYNC16(db + 16, bh + 8);
        CP_COMMIT();
    }

    for (int c = 0; c < nch; c++) {
        CP_WAIT1();
        __syncthreads();

        const uint32_t st = sbase + (uint32_t)(c % 3) * STG_SZ;
#pragma unroll
        for (int ks = 0; ks < 2; ks++) {
            uint32_t ah[4][4], al[4][4], bh[2][4];
            const uint32_t aoff =
                st + (uint32_t)((wm + (lane & 15)) * 80 +
                                (ks * 16 + ((lane >> 4) << 3)) * 2);
#pragma unroll
            for (int mt = 0; mt < 4; mt++) {
                ldsm4(ah[mt], aoff + mt * 16 * 80);
                ldsm4(al[mt], aoff + mt * 16 * 80 + 10240);
            }
            const uint32_t bbase =
                st + 20480u + (uint32_t)((ks * 16 + (lane & 15)) * 272 +
                                         (wn + ((lane >> 4) << 3)) * 2);
#pragma unroll
            for (int ng = 0; ng < 2; ng++)
                ldsm4t(bh[ng], bbase + ng * 32);
#pragma unroll
            for (int mt = 0; mt < 4; mt++)
#pragma unroll
                for (int nt = 0; nt < 4; nt++) {
                    const int ng = nt >> 1;
                    const int hf = (nt & 1) * 2;
                    mma16816h(acc[mt][nt], ah[mt], bh[ng][hf], bh[ng][hf + 1]);
                    mma16816h(acc[mt][nt], al[mt], bh[ng][hf], bh[ng][hf + 1]);
                }
        }
        __syncthreads();

        const int nc = c + 2;
        if (nc < nch) {
            const uint32_t st2 = sbase + (uint32_t)(nc % 3) * STG_SZ;
            const __half* ahp = Ah + (size_t)(m0 + a_row) * K + nc * 32 + a_off;
            const __half* alp = Al + (size_t)(m0 + a_row) * K + nc * 32 + a_off;
            uint32_t da = st2 + (uint32_t)(a_row * 80 + a_off * 2);
            CP_ASYNC16(da, ahp);
            CP_ASYNC16(da + 16, ahp + 8);
            CP_ASYNC16(da + 10240, alp);
            CP_ASYNC16(da + 10256, alp + 8);
            const __half* bhp = Bh + (size_t)(nc * 32 + b_kr) * N + n0 + b_off;
            uint32_t db = st2 + 20480u + (uint32_t)(b_kr * 272 + b_off * 2);
            CP_ASYNC16(db, bhp);
            CP_ASYNC16(db + 16, bhp + 8);
        }
        CP_COMMIT();
    }

#pragma unroll
    for (int mt = 0; mt < 4; mt++)
#pragma unroll
        for (int nt = 0; nt < 4; nt++) {
            int row = m0 + wm + mt * 16 + (lane >> 2);
            int col = n0 + wn + nt * 8 + (lane & 3) * 2;
            *(float2*)&C[(size_t)row * N + col] =
                make_float2(acc[mt][nt][0], acc[mt][nt][1]);
            *(float2*)&C[(size_t)(row + 8) * N + col] =
                make_float2(acc[mt][nt][2], acc[mt][nt][3]);
        }
}

// Fused QKV: blockIdx.x spans concatenated N space [Wq 2048 | Wk 1024 | Wv 1024]
__global__ __launch_bounds__(256, 2)
void qkv_gemm_kernel(const __half* __restrict__ Ah,
                     const __half* __restrict__ Al,
                     const __half* __restrict__ Wq,
                     const __half* __restrict__ Wk,
                     const __half* __restrict__ Wv,
                     float* __restrict__ q, float* __restrict__ k,
                     float* __restrict__ v) {
    extern __shared__ __align__(16) char dsm[];
    const int n0g = blockIdx.x * 128;
    const __half* Bh;
    float* C;
    int N, n0;
    if (n0g < 2048)      { Bh = Wq; C = q; N = 2048; n0 = n0g; }
    else if (n0g < 3072) { Bh = Wk; C = k; N = 1024; n0 = n0g - 2048; }
    else                 { Bh = Wv; C = v; N = 1024; n0 = n0g - 3072; }
    gemm_body(Ah, Al, Bh, C, blockIdx.y * 128, n0, N, 1024, smem_u32(dsm));
}

// Wo projection
__global__ __launch_bounds__(256, 2)
void wo_gemm_kernel(const __half* __restrict__ Ah,
                    const __half* __restrict__ Al,
                    const __half* __restrict__ Bh,
                    float* __restrict__ C) {
    extern __shared__ __align__(16) char dsm[];
    gemm_body(Ah, Al, Bh, C, blockIdx.y * 128, blockIdx.x * 128, 1024, 2048,
              smem_u32(dsm));
}

// ============================================================================
// RoPE cos/sin table
// ============================================================================
__global__ void rope_table_kernel(const int* __restrict__ pos,
                                  float* __restrict__ ctab,
                                  float* __restrict__ stab) {
    int idx = blockIdx.x * blockDim.x + threadIdx.x;
    if (idx >= S_ * 64) return;
    int s  = idx >> 6;
    int fi = idx & 63;
    float inv = (float)exp(-13.815510557964274 * (double)fi / 64.0);
    float ang = (float)pos[s] * inv;
    float c, sn;
    sincosf(ang, &sn, &c);
    ctab[idx] = c;
    stab[idx] = sn;
}

// ============================================================================
// RMSNorm + RoPE + fp16 conversion, one kernel:
//   q rows -> qh/ql (pre-scaled by 1/sqrt(128)*log2e, hi/lo split)
//   k rows -> kh (hi only)
//   v rows -> vh (hi only, plain convert)
// ============================================================================
__global__ void norm_rope_split_kernel(
    const float* __restrict__ q, const float* __restrict__ k,
    const float* __restrict__ v,
    const float* __restrict__ qw, const float* __restrict__ kw,
    const float* __restrict__ ctab, const float* __restrict__ stab,
    __half* __restrict__ qh, __half* __restrict__ ql,
    __half* __restrict__ kh, __half* __restrict__ vh) {
    const int warp = (blockIdx.x * blockDim.x + threadIdx.x) >> 5;
    const int lane = threadIdx.x & 31;
    const int QROWS = B_ * S_ * NH_;   // 65536
    const int KROWS = B_ * S_ * NKV_;  // 32768

    if (warp >= QROWS + KROWS) {       // ---- v path: plain hi convert
        const int r = warp - QROWS - KROWS;
        float4 x = ((const float4*)(v + (size_t)r * HD_))[lane];
        uint2 hh;
        hh.x = cvt2h(x.x, x.y);
        hh.y = cvt2h(x.z, x.w);
        ((uint2*)(vh + (size_t)r * HD_))[lane] = hh;
        return;
    }

    const float* ptr;
    const float* w;
    int s;
    bool isq = (warp < QROWS);
    int row;
    if (isq) {
        row = warp;
        ptr = q + (size_t)row * HD_;
        w = qw;
        s = (row / NH_) % S_;
    } else {
        row = warp - QROWS;
        ptr = k + (size_t)row * HD_;
        w = kw;
        s = (row / NKV_) % S_;
    }

    float4 x = ((const float4*)ptr)[lane];
    float ss = x.x * x.x + x.y * x.y + x.z * x.z + x.w * x.w;
#pragma unroll
    for (int off = 16; off; off >>= 1)
        ss += __shfl_xor_sync(0xffffffffu, ss, off);
    float rms = rsqrtf(ss * (1.0f / 128.0f) + 1e-6f);

    const int d0 = lane * 4;
    float xn[4];
    xn[0] = x.x * rms * w[d0 + 0];
    xn[1] = x.y * rms * w[d0 + 1];
    xn[2] = x.z * rms * w[d0 + 2];
    xn[3] = x.w * rms * w[d0 + 3];

    float out[4];
#pragma unroll
    for (int j = 0; j < 4; j++) {
        int fi = (d0 + j) & 63;
        float c  = ctab[s * 64 + fi];
        float sn = stab[s * 64 + fi];
        float partner = __shfl_xor_sync(0xffffffffu, xn[j], 16);
        out[j] = (lane < 16) ? (xn[j] * c - partner * sn)
                             : (xn[j] * c + partner * sn);
    }

    if (isq) {
        const float qscale = 0.1275174985f;   // 1/sqrt(128) * log2(e)
        uint32_t h0, l0, h1, l1;
        split2h(out[0] * qscale, out[1] * qscale, h0, l0);
        split2h(out[2] * qscale, out[3] * qscale, h1, l1);
        uint2 hh = make_uint2(h0, h1);
        uint2 ll = make_uint2(l0, l1);
        ((uint2*)(qh + (size_t)row * HD_))[lane] = hh;
        ((uint2*)(ql + (size_t)row * HD_))[lane] = ll;
    } else {
        uint2 hh;
        hh.x = cvt2h(out[0], out[1]);
        hh.y = cvt2h(out[2], out[3]);
        ((uint2*)(kh + (size_t)row * HD_))[lane] = hh;
    }
}

// ============================================================================
// Flash attention, fp16 2-term; inputs pre-converted fp16.
// cp.async loads: Q once, K/V double-buffered (2 stages).
// SMEM: Qh@0 Ql@34816 | K0@69632 V0@87040 | K1@104448 V1@121856 => 139264 B.
// ============================================================================
#define ASTRIDE 272

__global__ __launch_bounds__(256, 1)
void attn_mma_kernel(const __half* __restrict__ qh_g,
                     const __half* __restrict__ ql_g,
                     const __half* __restrict__ kh_g,
                     const __half* __restrict__ vh_g,
                     __half* __restrict__ oh, __half* __restrict__ ol) {
    extern __shared__ __align__(16) char asmem[];
    const uint32_t sb = smem_u32(asmem);
    const uint32_t Qh = sb, Ql = sb + 34816u;
    const uint32_t KV0 = sb + 69632u;   // K at +0, V at +17408; stage step 34816

    const int tid = threadIdx.x;
    const int lane = tid & 31;
    const int wid = tid >> 5;
    const int bh = blockIdx.y;
    const int b  = bh >> 4;
    const int h  = bh & 15;
    const int hk = h >> 1;
    const int qt = gridDim.x - 1 - blockIdx.x;
    const int q0 = qt * 128;
    const int wr = wid * 16;

    const int nkt = 2 * (qt + 1);

    // ---- prologue: Q tile + K/V stage 0 (one cp.async group)
    {
        const int r = tid >> 1;
        const int hf = (tid & 1) * 64;
        const __half* qph = qh_g + ((size_t)(b * S_ + q0 + r) * NH_ + h) * HD_ + hf;
        const __half* qpl = ql_g + ((size_t)(b * S_ + q0 + r) * NH_ + h) * HD_ + hf;
        const uint32_t off = (uint32_t)(r * ASTRIDE + hf * 2);
#pragma unroll
        for (int j = 0; j < 8; j++) {
            CP_ASYNC16(Qh + off + j * 16, qph + j * 8);
            CP_ASYNC16(Ql + off + j * 16, qpl + j * 8);
        }
        const int kr = tid >> 2;
        const int qd = (tid & 3) * 32;
        const size_t gro = ((size_t)(b * S_ + kr) * NKV_ + hk) * HD_ + qd;
        const uint32_t koff = KV0 + (uint32_t)(kr * ASTRIDE + qd * 2);
#pragma unroll
        for (int j = 0; j < 4; j++) {
            CP_ASYNC16(koff + j * 16, kh_g + gro + j * 8);
            CP_ASYNC16(koff + 17408u + j * 16, vh_g + gro + j * 8);
        }
        CP_COMMIT();
    }

    float oa[16][4];
    float m_i[2], l_i[2];
#pragma unroll
    for (int nt = 0; nt < 16; nt++)
#pragma unroll
        for (int r = 0; r < 4; r++) oa[nt][r] = 0.0f;
    m_i[0] = m_i[1] = -1e30f;
    l_i[0] = l_i[1] = 0.0f;

    for (int kt = 0; kt < nkt; kt++) {
        __syncthreads();   // all warps done reading the stage we're about to fill
        if (kt + 1 < nkt) {
            const int kr = tid >> 2;
            const int qd = (tid & 3) * 32;
            const size_t gro =
                ((size_t)(b * S_ + (kt + 1) * 64 + kr) * NKV_ + hk) * HD_ + qd;
            const uint32_t koff = KV0 + (uint32_t)(((kt + 1) & 1) * 34816) +
                                  (uint32_t)(kr * ASTRIDE + qd * 2);
#pragma unroll
            for (int j = 0; j < 4; j++) {
                CP_ASYNC16(koff + j * 16, kh_g + gro + j * 8);
                CP_ASYNC16(koff + 17408u + j * 16, vh_g + gro + j * 8);
            }
        }
        CP_COMMIT();
        CP_WAIT1();
        __syncthreads();

        const int k0 = kt * 64;
        const uint32_t Kst = KV0 + (uint32_t)((kt & 1) * 34816);
        const uint32_t Vst = Kst + 17408u;

        // ---- S = (Qh+Ql) @ Kh^T
        float sc[8][4];
#pragma unroll
        for (int nt = 0; nt < 8; nt++)
#pragma unroll
            for (int r = 0; r < 4; r++) sc[nt][r] = 0.0f;

#pragma unroll
        for (int kc = 0; kc < 8; kc++) {
            const uint32_t aoff =
                (uint32_t)((wr + (lane & 15)) * ASTRIDE +
                           (kc * 16 + ((lane >> 4) << 3)) * 2);
            uint32_t qh4[4], ql4[4];
            ldsm4(qh4, Qh + aoff);
            ldsm4(ql4, Ql + aoff);
            const uint32_t bbase =
                Kst + (uint32_t)((((lane >> 4) << 3) + (lane & 7)) * ASTRIDE +
                                 (kc * 16 + ((lane >> 3) & 1) * 8) * 2);
#pragma unroll
            for (int bg = 0; bg < 4; bg++) {
                const uint32_t boff = bbase + (uint32_t)(bg * 16 * ASTRIDE);
                uint32_t kh4[4];
                ldsm4(kh4, boff);
                mma16816h(sc[2 * bg], qh4, kh4[0], kh4[1]);
                mma16816h(sc[2 * bg], ql4, kh4[0], kh4[1]);
                mma16816h(sc[2 * bg + 1], qh4, kh4[2], kh4[3]);
                mma16816h(sc[2 * bg + 1], ql4, kh4[2], kh4[3]);
            }
        }

        // ---- causal mask (diagonal tiles only)
        const int row0 = q0 + wr + (lane >> 2);
        const int row1 = row0 + 8;
        if (kt >= 2 * qt) {
#pragma unroll
            for (int nt = 0; nt < 8; nt++) {
                int cb = k0 + nt * 8 + (lane & 3) * 2;
                if (cb > row0) sc[nt][0] = -1e30f;
                if (cb + 1 > row0) sc[nt][1] = -1e30f;
                if (cb > row1) sc[nt][2] = -1e30f;
                if (cb + 1 > row1) sc[nt][3] = -1e30f;
            }
        }

        // ---- online softmax (base-2, poly exp2)
        float mx0 = sc[0][0], mx1 = sc[0][2];
#pragma unroll
        for (int nt = 0; nt < 8; nt++) {
            mx0 = fmaxf(mx0, fmaxf(sc[nt][0], sc[nt][1]));
            mx1 = fmaxf(mx1, fmaxf(sc[nt][2], sc[nt][3]));
        }
        mx0 = fmaxf(mx0, __shfl_xor_sync(0xffffffffu, mx0, 1));
        mx0 = fmaxf(mx0, __shfl_xor_sync(0xffffffffu, mx0, 2));
        mx1 = fmaxf(mx1, __shfl_xor_sync(0xffffffffu, mx1, 1));
        mx1 = fmaxf(mx1, __shfl_xor_sync(0xffffffffu, mx1, 2));
        const float mn0 = fmaxf(m_i[0], mx0);
        const float mn1 = fmaxf(m_i[1], mx1);
        const float alpha0 = exp2fast(m_i[0] - mn0);
        const float alpha1 = exp2fast(m_i[1] - mn1);
        m_i[0] = mn0;
        m_i[1] = mn1;

        float rs0 = 0.0f, rs1 = 0.0f;
#pragma unroll
        for (int nt = 0; nt < 8; nt++) {
            sc[nt][0] = exp2fast(sc[nt][0] - mn0);
            sc[nt][1] = exp2fast(sc[nt][1] - mn0);
            sc[nt][2] = exp2fast(sc[nt][2] - mn1);
            sc[nt][3] = exp2fast(sc[nt][3] - mn1);
            rs0 += sc[nt][0] + sc[nt][1];
            rs1 += sc[nt][2] + sc[nt][3];
        }
        rs0 += __shfl_xor_sync(0xffffffffu, rs0, 1);
        rs0 += __shfl_xor_sync(0xffffffffu, rs0, 2);
        rs1 += __shfl_xor_sync(0xffffffffu, rs1, 1);
        rs1 += __shfl_xor_sync(0xffffffffu, rs1, 2);
        l_i[0] = l_i[0] * alpha0 + rs0;
        l_i[1] = l_i[1] * alpha1 + rs1;
#pragma unroll
        for (int nt = 0; nt < 16; nt++) {
            oa[nt][0] *= alpha0;
            oa[nt][1] *= alpha0;
            oa[nt][2] *= alpha1;
            oa[nt][3] *= alpha1;
        }

        // ---- O += (Ph+Pl) @ Vh
#pragma unroll
        for (int kc = 0; kc < 4; kc++) {
            uint32_t ph[4], pl[4];
            split2h(sc[2 * kc][0], sc[2 * kc][1], ph[0], pl[0]);
            split2h(sc[2 * kc][2], sc[2 * kc][3], ph[1], pl[1]);
            split2h(sc[2 * kc + 1][0], sc[2 * kc + 1][1], ph[2], pl[2]);
            split2h(sc[2 * kc + 1][2], sc[2 * kc + 1][3], ph[3], pl[3]);
            const uint32_t vbase =
                Vst + (uint32_t)((kc * 16 + (lane & 15)) * ASTRIDE +
                                 (((lane >> 4) << 3)) * 2);
#pragma unroll
            for (int dg = 0; dg < 8; dg++) {
                const uint32_t voff = vbase + (uint32_t)(dg * 32);
                uint32_t vh4[4];
                ldsm4t(vh4, voff);
                mma16816h(oa[2 * dg], ph, vh4[0], vh4[1]);
                mma16816h(oa[2 * dg], pl, vh4[0], vh4[1]);
                mma16816h(oa[2 * dg + 1], ph, vh4[2], vh4[3]);
                mma16816h(oa[2 * dg + 1], pl, vh4[2], vh4[3]);
            }
        }
    }

    // ---- epilogue: O /= l, write fp16 hi/lo directly (Wo-GEMM input layout)
    const float inv0 = 1.0f / l_i[0];
    const float inv1 = 1.0f / l_i[1];
    const int row0 = q0 + wr + (lane >> 2);
#pragma unroll
    for (int nt = 0; nt < 16; nt++) {
        const int d = nt * 8 + (lane & 3) * 2;
        const size_t i0 = (size_t)(b * S_ + row0) * 2048 + h * 128 + d;
        const size_t i1 = (size_t)(b * S_ + row0 + 8) * 2048 + h * 128 + d;
        uint32_t hh, hl;
        split2h(oa[nt][0] * inv0, oa[nt][1] * inv0, hh, hl);
        *(uint32_t*)&oh[i0] = hh;
        *(uint32_t*)&ol[i0] = hl;
        split2h(oa[nt][2] * inv1, oa[nt][3] * inv1, hh, hl);
        *(uint32_t*)&oh[i1] = hh;
        *(uint32_t*)&ol[i1] = hl;
    }
}

// ============================================================================
// launch
// ============================================================================
extern "C" void kernel_launch(void* const* d_in, const int* in_sizes, int n_in,
                              void* d_out, int out_size) {
    const float* hidden = (const float*)d_in[0];
    const int*   pos    = (const int*)d_in[1];
    const float* Wq     = (const float*)d_in[2];
    const float* Wk     = (const float*)d_in[3];
    const float* Wv     = (const float*)d_in[4];
    const float* Wo     = (const float*)d_in[5];
    const float* qw     = (const float*)d_in[6];
    const float* kw     = (const float*)d_in[7];
    float* out = (float*)d_out;

    float *q, *k, *v, *ct, *st;
    cudaGetSymbolAddress((void**)&q,  g_q);
    cudaGetSymbolAddress((void**)&k,  g_k);
    cudaGetSymbolAddress((void**)&v,  g_v);
    cudaGetSymbolAddress((void**)&ct, g_cos);
    cudaGetSymbolAddress((void**)&st, g_sin);

    __half *hidh, *hidl, *wqh, *wkh, *wvh, *woh, *ath, *atl;
    __half *qh, *ql, *kh, *vh;
    cudaGetSymbolAddress((void**)&hidh, g_hid_h);
    cudaGetSymbolAddress((void**)&hidl, g_hid_l);
    cudaGetSymbolAddress((void**)&wqh,  g_wq_h);
    cudaGetSymbolAddress((void**)&wkh,  g_wk_h);
    cudaGetSymbolAddress((void**)&wvh,  g_wv_h);
    cudaGetSymbolAddress((void**)&woh,  g_wo_h);
    cudaGetSymbolAddress((void**)&ath,  g_at_h);
    cudaGetSymbolAddress((void**)&atl,  g_at_l);
    cudaGetSymbolAddress((void**)&qh,   g_qh);
    cudaGetSymbolAddress((void**)&ql,   g_ql);
    cudaGetSymbolAddress((void**)&kh,   g_kh);
    cudaGetSymbolAddress((void**)&vh,   g_vh);

    // ---- pre-split inputs (activations hi/lo; all weights in one launch)
    {
        int n8 = MROWS * 1024 / 8;
        split_hl_kernel<<<(n8 + 255) / 256, 256>>>(hidden, hidh, hidl, n8);
        int tw = 2 * (1024 * 2048 / 8) + 2 * (1024 * 1024 / 8);  // 786432
        split_weights_kernel<<<(tw + 255) / 256, 256>>>(
            Wq, Wk, Wv, Wo, wqh, wkh, wvh, woh);
    }

    const int gemm_smem = 3 * (int)STG_SZ;   // 87552
    cudaFuncSetAttribute(qkv_gemm_kernel,
                         cudaFuncAttributeMaxDynamicSharedMemorySize, gemm_smem);
    cudaFuncSetAttribute(wo_gemm_kernel,
                         cudaFuncAttributeMaxDynamicSharedMemorySize, gemm_smem);

    // fused QKV projection (one launch; concatenated N = 4096)
    qkv_gemm_kernel<<<dim3(4096 / 128, MROWS / 128), 256, gemm_smem>>>(
        hidh, hidl, wqh, wkh, wvh, q, k, v);

    // RoPE table + RMSNorm/RoPE + fp16 conversion (q hi/lo, k hi, v hi)
    rope_table_kernel<<<(S_ * 64 + 255) / 256, 256>>>(pos, ct, st);
    {
        int total_warps = B_ * S_ * (NH_ + NKV_ + NKV_);   // 131072
        norm_rope_split_kernel<<<total_warps / 8, 256>>>(
            q, k, v, qw, kw, ct, st, qh, ql, kh, vh);
    }

    // attention (fp16 2-term; pre-converted inputs; double-buffered K/V)
    {
        const int attn_smem = 139264;
        cudaFuncSetAttribute(attn_mma_kernel,
                             cudaFuncAttributeMaxDynamicSharedMemorySize,
                             attn_smem);
        attn_mma_kernel<<<dim3(S_ / 128, B_ * NH_), 256, attn_smem>>>(
            qh, ql, kh, vh, ath, atl);
    }

    // output projection (fp16 2-term)
    wo_gemm_kernel<<<dim3(1024 / 128, MROWS / 128), 256, gemm_smem>>>(
        ath, atl, woh, out);
}

// round 12
// speedup vs baseline: 1.4627x; 1.0585x over previous
#include <cuda_runtime.h>
#include <cuda_bf16.h>
#include <cuda_fp16.h>
#include <math.h>
#include <stdint.h>

#define B_   2
#define S_   2048
#define NH_  16
#define NKV_ 8
#define HD_  128
#define MROWS (B_ * S_)          // 4096

// ---------------- scratch (device globals; no allocation allowed) ----------
__device__ float g_q[(size_t)B_ * S_ * NH_ * HD_];
__device__ float g_k[(size_t)B_ * S_ * NKV_ * HD_];
__device__ float g_v[(size_t)B_ * S_ * NKV_ * HD_];
__device__ float g_cos[S_ * 64];
__device__ float g_sin[S_ * 64];
// pre-split fp16 copies
__device__ __half g_hid_h[(size_t)MROWS * 1024];
__device__ __half g_hid_l[(size_t)MROWS * 1024];
__device__ __half g_wq_h[(size_t)1024 * 2048];
__device__ __half g_wk_h[(size_t)1024 * 1024];
__device__ __half g_wv_h[(size_t)1024 * 1024];
__device__ __half g_wo_h[(size_t)2048 * 1024];
__device__ __half g_at_h[(size_t)MROWS * 2048];
__device__ __half g_at_l[(size_t)MROWS * 2048];
// fp16 q/k/v for attention (q pre-scaled hi only; k,v hi only)
__device__ __half g_qh[(size_t)B_ * S_ * NH_ * HD_];
__device__ __half g_kh[(size_t)B_ * S_ * NKV_ * HD_];
__device__ __half g_vh[(size_t)B_ * S_ * NKV_ * HD_];

// ---------------- helpers ---------------------------------------------------
__device__ __forceinline__ uint32_t smem_u32(const void* p) {
    uint32_t a;
    asm("{ .reg .u64 t; cvta.to.shared.u64 t, %1; cvt.u32.u64 %0, t; }"
        : "=r"(a) : "l"(p));
    return a;
}
__device__ __forceinline__ void ldsm4(uint32_t* r, uint32_t addr) {
    asm volatile("ldmatrix.sync.aligned.m8n8.x4.shared.b16 {%0,%1,%2,%3}, [%4];"
                 : "=r"(r[0]), "=r"(r[1]), "=r"(r[2]), "=r"(r[3]) : "r"(addr));
}
__device__ __forceinline__ void ldsm4t(uint32_t* r, uint32_t addr) {
    asm volatile("ldmatrix.sync.aligned.m8n8.x4.trans.shared.b16 {%0,%1,%2,%3}, [%4];"
                 : "=r"(r[0]), "=r"(r[1]), "=r"(r[2]), "=r"(r[3]) : "r"(addr));
}
// fp16 mma, f32 accum
__device__ __forceinline__ void mma16816h(float* c, const uint32_t* a,
                                          uint32_t b0, uint32_t b1) {
    asm volatile(
        "mma.sync.aligned.m16n8k16.row.col.f32.f16.f16.f32 "
        "{%0,%1,%2,%3}, {%4,%5,%6,%7}, {%8,%9}, {%0,%1,%2,%3};"
        : "+f"(c[0]), "+f"(c[1]), "+f"(c[2]), "+f"(c[3])
        : "r"(a[0]), "r"(a[1]), "r"(a[2]), "r"(a[3]), "r"(b0), "r"(b1));
}
__device__ __forceinline__ void sts128(uint32_t addr, uint32_t a, uint32_t b,
                                       uint32_t c, uint32_t d) {
    asm volatile("st.shared.v4.b32 [%0], {%1, %2, %3, %4};"
                 :: "r"(addr), "r"(a), "r"(b), "r"(c), "r"(d));
}
// fp16 hi/lo split (packed half2)
__device__ __forceinline__ void split2h(float a, float b, uint32_t& hi, uint32_t& lo) {
    __half2 h = __floats2half2_rn(a, b);
    float2 hf = __half22float2(h);
    __half2 l = __floats2half2_rn(a - hf.x, b - hf.y);
    hi = *(uint32_t*)&h;
    lo = *(uint32_t*)&l;
}
__device__ __forceinline__ uint32_t cvt2h(float a, float b) {
    __half2 h = __floats2half2_rn(a, b);
    return *(uint32_t*)&h;
}
// fast 2^y on the FMA pipe (no MUFU)
__device__ __forceinline__ float exp2fast(float y) {
    y = fmaxf(y, -126.0f);
    float r = y + 12582912.0f;
    float kf = r - 12582912.0f;
    float f = y - kf;
    float p = 1.3333558146e-3f;
    p = fmaf(p, f, 9.6181291076e-3f);
    p = fmaf(p, f, 5.5504108664e-2f);
    p = fmaf(p, f, 2.4022650696e-1f);
    p = fmaf(p, f, 6.9314718056e-1f);
    p = fmaf(p, f, 1.0f);
    return __int_as_float(__float_as_int(p) + (__float_as_int(r) << 23));
}

#define CP_ASYNC16(dst, src) \
    asm volatile("cp.async.cg.shared.global [%0], [%1], 16;" \
                 :: "r"(dst), "l"(src))
#define CP_COMMIT() asm volatile("cp.async.commit_group;" ::: "memory")
#define CP_WAIT1()  asm volatile("cp.async.wait_group 1;" ::: "memory")

// ============================================================================
// split kernels: fp32 -> fp16 hi (+ lo)
// ============================================================================
__global__ void split_hl_kernel(const float* __restrict__ in,
                                __half* __restrict__ hi,
                                __half* __restrict__ lo, int n8) {
    int idx = blockIdx.x * blockDim.x + threadIdx.x;
    if (idx >= n8) return;
    const float4 x0 = ((const float4*)in)[2 * idx];
    const float4 x1 = ((const float4*)in)[2 * idx + 1];
    uint4 h, l;
    split2h(x0.x, x0.y, h.x, l.x);
    split2h(x0.z, x0.w, h.y, l.y);
    split2h(x1.x, x1.y, h.z, l.z);
    split2h(x1.z, x1.w, h.w, l.w);
    ((uint4*)hi)[idx] = h;
    ((uint4*)lo)[idx] = l;
}

// all four weight matrices converted in ONE launch (segmented index space)
__global__ void split_weights_kernel(const float* __restrict__ Wq,
                                     const float* __restrict__ Wk,
                                     const float* __restrict__ Wv,
                                     const float* __restrict__ Wo,
                                     __half* __restrict__ wqh,
                                     __half* __restrict__ wkh,
                                     __half* __restrict__ wvh,
                                     __half* __restrict__ woh) {
    int idx = blockIdx.x * blockDim.x + threadIdx.x;
    const int NQ = 1024 * 2048 / 8;   // 262144
    const int NK = 1024 * 1024 / 8;   // 131072
    const float* in;
    __half* outp;
    int li;
    if (idx < NQ)                  { in = Wq; outp = wqh; li = idx; }
    else if (idx < NQ + NK)        { in = Wk; outp = wkh; li = idx - NQ; }
    else if (idx < NQ + 2 * NK)    { in = Wv; outp = wvh; li = idx - NQ - NK; }
    else if (idx < 2 * NQ + 2 * NK){ in = Wo; outp = woh; li = idx - NQ - 2 * NK; }
    else return;
    const float4 x0 = ((const float4*)in)[2 * li];
    const float4 x1 = ((const float4*)in)[2 * li + 1];
    uint4 h;
    h.x = cvt2h(x0.x, x0.y);
    h.y = cvt2h(x0.z, x0.w);
    h.z = cvt2h(x1.x, x1.y);
    h.w = cvt2h(x1.z, x1.w);
    ((uint4*)outp)[li] = h;
}

// ============================================================================
// GEMM core (fp16 2-term Ah*Bh + Al*Bh) — unchanged, proven.
// ============================================================================
#define STG_SZ 29184u

__device__ __forceinline__ void gemm_body(
    const __half* __restrict__ Ah, const __half* __restrict__ Al,
    const __half* __restrict__ Bh, float* __restrict__ C,
    int m0, int n0, int N, int K, uint32_t sbase) {

    const int tid  = threadIdx.x;
    const int lane = tid & 31;
    const int wid  = tid >> 5;
    const int wm = (wid >> 2) * 64;
    const int wn = (wid & 3) * 32;

    float acc[4][4][4];
#pragma unroll
    for (int i = 0; i < 4; i++)
#pragma unroll
        for (int j = 0; j < 4; j++)
#pragma unroll
            for (int r = 0; r < 4; r++) acc[i][j][r] = 0.0f;

    const int a_row = tid >> 1;
    const int a_off = (tid & 1) * 16;
    const int b_kr  = tid >> 3;
    const int b_off = (tid & 7) * 16;

    const int nch = K >> 5;

#pragma unroll
    for (int c = 0; c < 2; c++) {
        const uint32_t st = sbase + (uint32_t)c * STG_SZ;
        const __half* ah = Ah + (size_t)(m0 + a_row) * K + c * 32 + a_off;
        const __half* al = Al + (size_t)(m0 + a_row) * K + c * 32 + a_off;
        uint32_t da = st + (uint32_t)(a_row * 80 + a_off * 2);
        CP_ASYNC16(da, ah);
        CP_ASYNC16(da + 16, ah + 8);
        CP_ASYNC16(da + 10240, al);
        CP_ASYNC16(da + 10256, al + 8);
        const __half* bh = Bh + (size_t)(c * 32 + b_kr) * N + n0 + b_off;
        uint32_t db = st + 20480u + (uint32_t)(b_kr * 272 + b_off * 2);
        CP_ASYNC16(db, bh);
        CP_ASYNC16(db + 16, bh + 8);
        CP_COMMIT();
    }

    for (int c = 0; c < nch; c++) {
        CP_WAIT1();
        __syncthreads();

        const uint32_t st = sbase + (uint32_t)(c % 3) * STG_SZ;
#pragma unroll
        for (int ks = 0; ks < 2; ks++) {
            uint32_t ah[4][4], al[4][4], bh[2][4];
            const uint32_t aoff =
                st + (uint32_t)((wm + (lane & 15)) * 80 +
                                (ks * 16 + ((lane >> 4) << 3)) * 2);
#pragma unroll
            for (int mt = 0; mt < 4; mt++) {
                ldsm4(ah[mt], aoff + mt * 16 * 80);
                ldsm4(al[mt], aoff + mt * 16 * 80 + 10240);
            }
            const uint32_t bbase =
                st + 20480u + (uint32_t)((ks * 16 + (lane & 15)) * 272 +
                                         (wn + ((lane >> 4) << 3)) * 2);
#pragma unroll
            for (int ng = 0; ng < 2; ng++)
                ldsm4t(bh[ng], bbase + ng * 32);
#pragma unroll
            for (int mt = 0; mt < 4; mt++)
#pragma unroll
                for (int nt = 0; nt < 4; nt++) {
                    const int ng = nt >> 1;
                    const int hf = (nt & 1) * 2;
                    mma16816h(acc[mt][nt], ah[mt], bh[ng][hf], bh[ng][hf + 1]);
                    mma16816h(acc[mt][nt], al[mt], bh[ng][hf], bh[ng][hf + 1]);
                }
        }
        __syncthreads();

        const int nc = c + 2;
        if (nc < nch) {
            const uint32_t st2 = sbase + (uint32_t)(nc % 3) * STG_SZ;
            const __half* ahp = Ah + (size_t)(m0 + a_row) * K + nc * 32 + a_off;
            const __half* alp = Al + (size_t)(m0 + a_row) * K + nc * 32 + a_off;
            uint32_t da = st2 + (uint32_t)(a_row * 80 + a_off * 2);
            CP_ASYNC16(da, ahp);
            CP_ASYNC16(da + 16, ahp + 8);
            CP_ASYNC16(da + 10240, alp);
            CP_ASYNC16(da + 10256, alp + 8);
            const __half* bhp = Bh + (size_t)(nc * 32 + b_kr) * N + n0 + b_off;
            uint32_t db = st2 + 20480u + (uint32_t)(b_kr * 272 + b_off * 2);
            CP_ASYNC16(db, bhp);
            CP_ASYNC16(db + 16, bhp + 8);
        }
        CP_COMMIT();
    }

#pragma unroll
    for (int mt = 0; mt < 4; mt++)
#pragma unroll
        for (int nt = 0; nt < 4; nt++) {
            int row = m0 + wm + mt * 16 + (lane >> 2);
            int col = n0 + wn + nt * 8 + (lane & 3) * 2;
            *(float2*)&C[(size_t)row * N + col] =
                make_float2(acc[mt][nt][0], acc[mt][nt][1]);
            *(float2*)&C[(size_t)(row + 8) * N + col] =
                make_float2(acc[mt][nt][2], acc[mt][nt][3]);
        }
}

// Fused QKV: blockIdx.x spans concatenated N space [Wq 2048 | Wk 1024 | Wv 1024]
__global__ __launch_bounds__(256, 2)
void qkv_gemm_kernel(const __half* __restrict__ Ah,
                     const __half* __restrict__ Al,
                     const __half* __restrict__ Wq,
                     const __half* __restrict__ Wk,
                     const __half* __restrict__ Wv,
                     float* __restrict__ q, float* __restrict__ k,
                     float* __restrict__ v) {
    extern __shared__ __align__(16) char dsm[];
    const int n0g = blockIdx.x * 128;
    const __half* Bh;
    float* C;
    int N, n0;
    if (n0g < 2048)      { Bh = Wq; C = q; N = 2048; n0 = n0g; }
    else if (n0g < 3072) { Bh = Wk; C = k; N = 1024; n0 = n0g - 2048; }
    else                 { Bh = Wv; C = v; N = 1024; n0 = n0g - 3072; }
    gemm_body(Ah, Al, Bh, C, blockIdx.y * 128, n0, N, 1024, smem_u32(dsm));
}

// Wo projection
__global__ __launch_bounds__(256, 2)
void wo_gemm_kernel(const __half* __restrict__ Ah,
                    const __half* __restrict__ Al,
                    const __half* __restrict__ Bh,
                    float* __restrict__ C) {
    extern __shared__ __align__(16) char dsm[];
    gemm_body(Ah, Al, Bh, C, blockIdx.y * 128, blockIdx.x * 128, 1024, 2048,
              smem_u32(dsm));
}

// ============================================================================
// RoPE cos/sin table
// ============================================================================
__global__ void rope_table_kernel(const int* __restrict__ pos,
                                  float* __restrict__ ctab,
                                  float* __restrict__ stab) {
    int idx = blockIdx.x * blockDim.x + threadIdx.x;
    if (idx >= S_ * 64) return;
    int s  = idx >> 6;
    int fi = idx & 63;
    float inv = (float)exp(-13.815510557964274 * (double)fi / 64.0);
    float ang = (float)pos[s] * inv;
    float c, sn;
    sincosf(ang, &sn, &c);
    ctab[idx] = c;
    stab[idx] = sn;
}

// ============================================================================
// RMSNorm + RoPE + fp16 conversion, one kernel:
//   q rows -> qh (pre-scaled by 1/sqrt(128)*log2e, hi only)
//   k rows -> kh (hi only)
//   v rows -> vh (hi only, plain convert)
// ============================================================================
__global__ void norm_rope_split_kernel(
    const float* __restrict__ q, const float* __restrict__ k,
    const float* __restrict__ v,
    const float* __restrict__ qw, const float* __restrict__ kw,
    const float* __restrict__ ctab, const float* __restrict__ stab,
    __half* __restrict__ qh, __half* __restrict__ kh,
    __half* __restrict__ vh) {
    const int warp = (blockIdx.x * blockDim.x + threadIdx.x) >> 5;
    const int lane = threadIdx.x & 31;
    const int QROWS = B_ * S_ * NH_;   // 65536
    const int KROWS = B_ * S_ * NKV_;  // 32768

    if (warp >= QROWS + KROWS) {       // ---- v path: plain hi convert
        const int r = warp - QROWS - KROWS;
        float4 x = ((const float4*)(v + (size_t)r * HD_))[lane];
        uint2 hh;
        hh.x = cvt2h(x.x, x.y);
        hh.y = cvt2h(x.z, x.w);
        ((uint2*)(vh + (size_t)r * HD_))[lane] = hh;
        return;
    }

    const float* ptr;
    const float* w;
    int s;
    bool isq = (warp < QROWS);
    int row;
    if (isq) {
        row = warp;
        ptr = q + (size_t)row * HD_;
        w = qw;
        s = (row / NH_) % S_;
    } else {
        row = warp - QROWS;
        ptr = k + (size_t)row * HD_;
        w = kw;
        s = (row / NKV_) % S_;
    }

    float4 x = ((const float4*)ptr)[lane];
    float ss = x.x * x.x + x.y * x.y + x.z * x.z + x.w * x.w;
#pragma unroll
    for (int off = 16; off; off >>= 1)
        ss += __shfl_xor_sync(0xffffffffu, ss, off);
    float rms = rsqrtf(ss * (1.0f / 128.0f) + 1e-6f);

    const int d0 = lane * 4;
    float xn[4];
    xn[0] = x.x * rms * w[d0 + 0];
    xn[1] = x.y * rms * w[d0 + 1];
    xn[2] = x.z * rms * w[d0 + 2];
    xn[3] = x.w * rms * w[d0 + 3];

    float out[4];
#pragma unroll
    for (int j = 0; j < 4; j++) {
        int fi = (d0 + j) & 63;
        float c  = ctab[s * 64 + fi];
        float sn = stab[s * 64 + fi];
        float partner = __shfl_xor_sync(0xffffffffu, xn[j], 16);
        out[j] = (lane < 16) ? (xn[j] * c - partner * sn)
                             : (xn[j] * c + partner * sn);
    }

    if (isq) {
        const float qscale = 0.1275174985f;   // 1/sqrt(128) * log2(e)
        uint2 hh;
        hh.x = cvt2h(out[0] * qscale, out[1] * qscale);
        hh.y = cvt2h(out[2] * qscale, out[3] * qscale);
        ((uint2*)(qh + (size_t)row * HD_))[lane] = hh;
    } else {
        uint2 hh;
        hh.x = cvt2h(out[0], out[1]);
        hh.y = cvt2h(out[2], out[3]);
        ((uint2*)(kh + (size_t)row * HD_))[lane] = hh;
    }
}

// ============================================================================
// Flash attention; QK = Qh*Kh (hi only), PV = (Ph+Pl)*Vh.
// cp.async loads: Q once, K/V double-buffered (2 stages).
// SMEM: Qh@0 | K0@34816 V0@52224 | K1@69632 V1@87040 => 104448 B.
// ============================================================================
#define ASTRIDE 272

__global__ __launch_bounds__(256, 1)
void attn_mma_kernel(const __half* __restrict__ qh_g,
                     const __half* __restrict__ kh_g,
                     const __half* __restrict__ vh_g,
                     __half* __restrict__ oh, __half* __restrict__ ol) {
    extern __shared__ __align__(16) char asmem[];
    const uint32_t sb = smem_u32(asmem);
    const uint32_t Qh = sb;
    const uint32_t KV0 = sb + 34816u;   // K at +0, V at +17408; stage step 34816

    const int tid = threadIdx.x;
    const int lane = tid & 31;
    const int wid = tid >> 5;
    const int bh = blockIdx.y;
    const int b  = bh >> 4;
    const int h  = bh & 15;
    const int hk = h >> 1;
    const int qt = gridDim.x - 1 - blockIdx.x;
    const int q0 = qt * 128;
    const int wr = wid * 16;

    const int nkt = 2 * (qt + 1);

    // ---- prologue: Q tile + K/V stage 0 (one cp.async group)
    {
        const int r = tid >> 1;
        const int hf = (tid & 1) * 64;
        const __half* qph = qh_g + ((size_t)(b * S_ + q0 + r) * NH_ + h) * HD_ + hf;
        const uint32_t off = (uint32_t)(r * ASTRIDE + hf * 2);
#pragma unroll
        for (int j = 0; j < 8; j++)
            CP_ASYNC16(Qh + off + j * 16, qph + j * 8);
        const int kr = tid >> 2;
        const int qd = (tid & 3) * 32;
        const size_t gro = ((size_t)(b * S_ + kr) * NKV_ + hk) * HD_ + qd;
        const uint32_t koff = KV0 + (uint32_t)(kr * ASTRIDE + qd * 2);
#pragma unroll
        for (int j = 0; j < 4; j++) {
            CP_ASYNC16(koff + j * 16, kh_g + gro + j * 8);
            CP_ASYNC16(koff + 17408u + j * 16, vh_g + gro + j * 8);
        }
        CP_COMMIT();
    }

    float oa[16][4];
    float m_i[2], l_i[2];
#pragma unroll
    for (int nt = 0; nt < 16; nt++)
#pragma unroll
        for (int r = 0; r < 4; r++) oa[nt][r] = 0.0f;
    m_i[0] = m_i[1] = -1e30f;
    l_i[0] = l_i[1] = 0.0f;

    for (int kt = 0; kt < nkt; kt++) {
        __syncthreads();   // all warps done reading the stage we're about to fill
        if (kt + 1 < nkt) {
            const int kr = tid >> 2;
            const int qd = (tid & 3) * 32;
            const size_t gro =
                ((size_t)(b * S_ + (kt + 1) * 64 + kr) * NKV_ + hk) * HD_ + qd;
            const uint32_t koff = KV0 + (uint32_t)(((kt + 1) & 1) * 34816) +
                                  (uint32_t)(kr * ASTRIDE + qd * 2);
#pragma unroll
            for (int j = 0; j < 4; j++) {
                CP_ASYNC16(koff + j * 16, kh_g + gro + j * 8);
                CP_ASYNC16(koff + 17408u + j * 16, vh_g + gro + j * 8);
            }
        }
        CP_COMMIT();
        CP_WAIT1();
        __syncthreads();

        const int k0 = kt * 64;
        const uint32_t Kst = KV0 + (uint32_t)((kt & 1) * 34816);
        const uint32_t Vst = Kst + 17408u;

        // ---- S = Qh @ Kh^T (hi only)
        float sc[8][4];
#pragma unroll
        for (int nt = 0; nt < 8; nt++)
#pragma unroll
            for (int r = 0; r < 4; r++) sc[nt][r] = 0.0f;

#pragma unroll
        for (int kc = 0; kc < 8; kc++) {
            const uint32_t aoff =
                (uint32_t)((wr + (lane & 15)) * ASTRIDE +
                           (kc * 16 + ((lane >> 4) << 3)) * 2);
            uint32_t qh4[4];
            ldsm4(qh4, Qh + aoff);
            const uint32_t bbase =
                Kst + (uint32_t)((((lane >> 4) << 3) + (lane & 7)) * ASTRIDE +
                                 (kc * 16 + ((lane >> 3) & 1) * 8) * 2);
#pragma unroll
            for (int bg = 0; bg < 4; bg++) {
                const uint32_t boff = bbase + (uint32_t)(bg * 16 * ASTRIDE);
                uint32_t kh4[4];
                ldsm4(kh4, boff);
                mma16816h(sc[2 * bg], qh4, kh4[0], kh4[1]);
                mma16816h(sc[2 * bg + 1], qh4, kh4[2], kh4[3]);
            }
        }

        // ---- causal mask (diagonal tiles only)
        const int row0 = q0 + wr + (lane >> 2);
        const int row1 = row0 + 8;
        if (kt >= 2 * qt) {
#pragma unroll
            for (int nt = 0; nt < 8; nt++) {
                int cb = k0 + nt * 8 + (lane & 3) * 2;
                if (cb > row0) sc[nt][0] = -1e30f;
                if (cb + 1 > row0) sc[nt][1] = -1e30f;
                if (cb > row1) sc[nt][2] = -1e30f;
                if (cb + 1 > row1) sc[nt][3] = -1e30f;
            }
        }

        // ---- online softmax (base-2, poly exp2)
        float mx0 = sc[0][0], mx1 = sc[0][2];
#pragma unroll
        for (int nt = 0; nt < 8; nt++) {
            mx0 = fmaxf(mx0, fmaxf(sc[nt][0], sc[nt][1]));
            mx1 = fmaxf(mx1, fmaxf(sc[nt][2], sc[nt][3]));
        }
        mx0 = fmaxf(mx0, __shfl_xor_sync(0xffffffffu, mx0, 1));
        mx0 = fmaxf(mx0, __shfl_xor_sync(0xffffffffu, mx0, 2));
        mx1 = fmaxf(mx1, __shfl_xor_sync(0xffffffffu, mx1, 1));
        mx1 = fmaxf(mx1, __shfl_xor_sync(0xffffffffu, mx1, 2));
        const float mn0 = fmaxf(m_i[0], mx0);
        const float mn1 = fmaxf(m_i[1], mx1);
        const float alpha0 = exp2fast(m_i[0] - mn0);
        const float alpha1 = exp2fast(m_i[1] - mn1);
        m_i[0] = mn0;
        m_i[1] = mn1;

        float rs0 = 0.0f, rs1 = 0.0f;
#pragma unroll
        for (int nt = 0; nt < 8; nt++) {
            sc[nt][0] = exp2fast(sc[nt][0] - mn0);
            sc[nt][1] = exp2fast(sc[nt][1] - mn0);
            sc[nt][2] = exp2fast(sc[nt][2] - mn1);
            sc[nt][3] = exp2fast(sc[nt][3] - mn1);
            rs0 += sc[nt][0] + sc[nt][1];
            rs1 += sc[nt][2] + sc[nt][3];
        }
        rs0 += __shfl_xor_sync(0xffffffffu, rs0, 1);
        rs0 += __shfl_xor_sync(0xffffffffu, rs0, 2);
        rs1 += __shfl_xor_sync(0xffffffffu, rs1, 1);
        rs1 += __shfl_xor_sync(0xffffffffu, rs1, 2);
        l_i[0] = l_i[0] * alpha0 + rs0;
        l_i[1] = l_i[1] * alpha1 + rs1;
#pragma unroll
        for (int nt = 0; nt < 16; nt++) {
            oa[nt][0] *= alpha0;
            oa[nt][1] *= alpha0;
            oa[nt][2] *= alpha1;
            oa[nt][3] *= alpha1;
        }

        // ---- O += (Ph+Pl) @ Vh
#pragma unroll
        for (int kc = 0; kc < 4; kc++) {
            uint32_t ph[4], pl[4];
            split2h(sc[2 * kc][0], sc[2 * kc][1], ph[0], pl[0]);
            split2h(sc[2 * kc][2], sc[2 * kc][3], ph[1], pl[1]);
            split2h(sc[2 * kc + 1][0], sc[2 * kc + 1][1], ph[2], pl[2]);
            split2h(sc[2 * kc + 1][2], sc[2 * kc + 1][3], ph[3], pl[3]);
            const uint32_t vbase =
                Vst + (uint32_t)((kc * 16 + (lane & 15)) * ASTRIDE +
                                 (((lane >> 4) << 3)) * 2);
#pragma unroll
            for (int dg = 0; dg < 8; dg++) {
                const uint32_t voff = vbase + (uint32_t)(dg * 32);
                uint32_t vh4[4];
                ldsm4t(vh4, voff);
                mma16816h(oa[2 * dg], ph, vh4[0], vh4[1]);
                mma16816h(oa[2 * dg], pl, vh4[0], vh4[1]);
                mma16816h(oa[2 * dg + 1], ph, vh4[2], vh4[3]);
                mma16816h(oa[2 * dg + 1], pl, vh4[2], vh4[3]);
            }
        }
    }

    // ---- epilogue: O /= l, write fp16 hi/lo directly (Wo-GEMM input layout)
    const float inv0 = 1.0f / l_i[0];
    const float inv1 = 1.0f / l_i[1];
    const int row0 = q0 + wr + (lane >> 2);
#pragma unroll
    for (int nt = 0; nt < 16; nt++) {
        const int d = nt * 8 + (lane & 3) * 2;
        const size_t i0 = (size_t)(b * S_ + row0) * 2048 + h * 128 + d;
        const size_t i1 = (size_t)(b * S_ + row0 + 8) * 2048 + h * 128 + d;
        uint32_t hh, hl;
        split2h(oa[nt][0] * inv0, oa[nt][1] * inv0, hh, hl);
        *(uint32_t*)&oh[i0] = hh;
        *(uint32_t*)&ol[i0] = hl;
        split2h(oa[nt][2] * inv1, oa[nt][3] * inv1, hh, hl);
        *(uint32_t*)&oh[i1] = hh;
        *(uint32_t*)&ol[i1] = hl;
    }
}

// ============================================================================
// launch
// ============================================================================
extern "C" void kernel_launch(void* const* d_in, const int* in_sizes, int n_in,
                              void* d_out, int out_size) {
    const float* hidden = (const float*)d_in[0];
    const int*   pos    = (const int*)d_in[1];
    const float* Wq     = (const float*)d_in[2];
    const float* Wk     = (const float*)d_in[3];
    const float* Wv     = (const float*)d_in[4];
    const float* Wo     = (const float*)d_in[5];
    const float* qw     = (const float*)d_in[6];
    const float* kw     = (const float*)d_in[7];
    float* out = (float*)d_out;

    float *q, *k, *v, *ct, *st;
    cudaGetSymbolAddress((void**)&q,  g_q);
    cudaGetSymbolAddress((void**)&k,  g_k);
    cudaGetSymbolAddress((void**)&v,  g_v);
    cudaGetSymbolAddress((void**)&ct, g_cos);
    cudaGetSymbolAddress((void**)&st, g_sin);

    __half *hidh, *hidl, *wqh, *wkh, *wvh, *woh, *ath, *atl;
    __half *qh, *kh, *vh;
    cudaGetSymbolAddress((void**)&hidh, g_hid_h);
    cudaGetSymbolAddress((void**)&hidl, g_hid_l);
    cudaGetSymbolAddress((void**)&wqh,  g_wq_h);
    cudaGetSymbolAddress((void**)&wkh,  g_wk_h);
    cudaGetSymbolAddress((void**)&wvh,  g_wv_h);
    cudaGetSymbolAddress((void**)&woh,  g_wo_h);
    cudaGetSymbolAddress((void**)&ath,  g_at_h);
    cudaGetSymbolAddress((void**)&atl,  g_at_l);
    cudaGetSymbolAddress((void**)&qh,   g_qh);
    cudaGetSymbolAddress((void**)&kh,   g_kh);
    cudaGetSymbolAddress((void**)&vh,   g_vh);

    // ---- pre-split inputs (activations hi/lo; all weights in one launch)
    {
        int n8 = MROWS * 1024 / 8;
        split_hl_kernel<<<(n8 + 255) / 256, 256>>>(hidden, hidh, hidl, n8);
        int tw = 2 * (1024 * 2048 / 8) + 2 * (1024 * 1024 / 8);  // 786432
        split_weights_kernel<<<(tw + 255) / 256, 256>>>(
            Wq, Wk, Wv, Wo, wqh, wkh, wvh, woh);
    }

    const int gemm_smem = 3 * (int)STG_SZ;   // 87552
    cudaFuncSetAttribute(qkv_gemm_kernel,
                         cudaFuncAttributeMaxDynamicSharedMemorySize, gemm_smem);
    cudaFuncSetAttribute(wo_gemm_kernel,
                         cudaFuncAttributeMaxDynamicSharedMemorySize, gemm_smem);

    // fused QKV projection (one launch; concatenated N = 4096)
    qkv_gemm_kernel<<<dim3(4096 / 128, MROWS / 128), 256, gemm_smem>>>(
        hidh, hidl, wqh, wkh, wvh, q, k, v);

    // RoPE table + RMSNorm/RoPE + fp16 conversion (q hi, k hi, v hi)
    rope_table_kernel<<<(S_ * 64 + 255) / 256, 256>>>(pos, ct, st);
    {
        int total_warps = B_ * S_ * (NH_ + NKV_ + NKV_);   // 131072
        norm_rope_split_kernel<<<total_warps / 8, 256>>>(
            q, k, v, qw, kw, ct, st, qh, kh, vh);
    }

    // attention (QK hi-only; PV 2-term; double-buffered K/V)
    {
        const int attn_smem = 104448;
        cudaFuncSetAttribute(attn_mma_kernel,
                             cudaFuncAttributeMaxDynamicSharedMemorySize,
                             attn_smem);
        attn_mma_kernel<<<dim3(S_ / 128, B_ * NH_), 256, attn_smem>>>(
            qh, kh, vh, ath, atl);
    }

    // output projection (fp16 2-term)
    wo_gemm_kernel<<<dim3(1024 / 128, MROWS / 128), 256, gemm_smem>>>(
        ath, atl, woh, out);
}

// round 13
// speedup vs baseline: 1.7429x; 1.1916x over previous
#include <cuda_runtime.h>
#include <cuda_bf16.h>
#include <cuda_fp16.h>
#include <math.h>
#include <stdint.h>

#define B_   2
#define S_   2048
#define NH_  16
#define NKV_ 8
#define HD_  128
#define MROWS (B_ * S_)          // 4096

// ---------------- scratch (device globals; no allocation allowed) ----------
__device__ float g_q[(size_t)B_ * S_ * NH_ * HD_];
__device__ float g_k[(size_t)B_ * S_ * NKV_ * HD_];
__device__ float g_v[(size_t)B_ * S_ * NKV_ * HD_];
__device__ float g_cos[S_ * 64];
__device__ float g_sin[S_ * 64];
// pre-converted fp16 copies (hidden + weights: hi only)
__device__ __half g_hid_h[(size_t)MROWS * 1024];
__device__ __half g_wq_h[(size_t)1024 * 2048];
__device__ __half g_wk_h[(size_t)1024 * 1024];
__device__ __half g_wv_h[(size_t)1024 * 1024];
__device__ __half g_wo_h[(size_t)2048 * 1024];
// attention output: hi/lo (Wo stays 2-term)
__device__ __half g_at_h[(size_t)MROWS * 2048];
__device__ __half g_at_l[(size_t)MROWS * 2048];
// fp16 q/k/v for attention (q pre-scaled hi only; k,v hi only)
__device__ __half g_qh[(size_t)B_ * S_ * NH_ * HD_];
__device__ __half g_kh[(size_t)B_ * S_ * NKV_ * HD_];
__device__ __half g_vh[(size_t)B_ * S_ * NKV_ * HD_];

// ---------------- helpers ---------------------------------------------------
__device__ __forceinline__ uint32_t smem_u32(const void* p) {
    uint32_t a;
    asm("{ .reg .u64 t; cvta.to.shared.u64 t, %1; cvt.u32.u64 %0, t; }"
        : "=r"(a) : "l"(p));
    return a;
}
__device__ __forceinline__ void ldsm4(uint32_t* r, uint32_t addr) {
    asm volatile("ldmatrix.sync.aligned.m8n8.x4.shared.b16 {%0,%1,%2,%3}, [%4];"
                 : "=r"(r[0]), "=r"(r[1]), "=r"(r[2]), "=r"(r[3]) : "r"(addr));
}
__device__ __forceinline__ void ldsm4t(uint32_t* r, uint32_t addr) {
    asm volatile("ldmatrix.sync.aligned.m8n8.x4.trans.shared.b16 {%0,%1,%2,%3}, [%4];"
                 : "=r"(r[0]), "=r"(r[1]), "=r"(r[2]), "=r"(r[3]) : "r"(addr));
}
// fp16 mma, f32 accum
__device__ __forceinline__ void mma16816h(float* c, const uint32_t* a,
                                          uint32_t b0, uint32_t b1) {
    asm volatile(
        "mma.sync.aligned.m16n8k16.row.col.f32.f16.f16.f32 "
        "{%0,%1,%2,%3}, {%4,%5,%6,%7}, {%8,%9}, {%0,%1,%2,%3};"
        : "+f"(c[0]), "+f"(c[1]), "+f"(c[2]), "+f"(c[3])
        : "r"(a[0]), "r"(a[1]), "r"(a[2]), "r"(a[3]), "r"(b0), "r"(b1));
}
// fp16 hi/lo split (packed half2)
__device__ __forceinline__ void split2h(float a, float b, uint32_t& hi, uint32_t& lo) {
    __half2 h = __floats2half2_rn(a, b);
    float2 hf = __half22float2(h);
    __half2 l = __floats2half2_rn(a - hf.x, b - hf.y);
    hi = *(uint32_t*)&h;
    lo = *(uint32_t*)&l;
}
__device__ __forceinline__ uint32_t cvt2h(float a, float b) {
    __half2 h = __floats2half2_rn(a, b);
    return *(uint32_t*)&h;
}
// fast 2^y on the FMA pipe (no MUFU)
__device__ __forceinline__ float exp2fast(float y) {
    y = fmaxf(y, -126.0f);
    float r = y + 12582912.0f;
    float kf = r - 12582912.0f;
    float f = y - kf;
    float p = 1.3333558146e-3f;
    p = fmaf(p, f, 9.6181291076e-3f);
    p = fmaf(p, f, 5.5504108664e-2f);
    p = fmaf(p, f, 2.4022650696e-1f);
    p = fmaf(p, f, 6.9314718056e-1f);
    p = fmaf(p, f, 1.0f);
    return __int_as_float(__float_as_int(p) + (__float_as_int(r) << 23));
}

#define CP_ASYNC16(dst, src) \
    asm volatile("cp.async.cg.shared.global [%0], [%1], 16;" \
                 :: "r"(dst), "l"(src))
#define CP_COMMIT() asm volatile("cp.async.commit_group;" ::: "memory")
#define CP_WAIT1()  asm volatile("cp.async.wait_group 1;" ::: "memory")

// ============================================================================
// ONE conversion kernel: fp32 -> fp16 hi for hidden + all four weights.
// Segments (n8 = 8-element units):
//   hid 524288 | Wq 262144 | Wk 131072 | Wv 131072 | Wo 262144
// ============================================================================
__global__ void convert_all_kernel(const float* __restrict__ hid,
                                   const float* __restrict__ Wq,
                                   const float* __restrict__ Wk,
                                   const float* __restrict__ Wv,
                                   const float* __restrict__ Wo,
                                   __half* __restrict__ hidh,
                                   __half* __restrict__ wqh,
                                   __half* __restrict__ wkh,
                                   __half* __restrict__ wvh,
                                   __half* __restrict__ woh) {
    int idx = blockIdx.x * blockDim.x + threadIdx.x;
    const int NH8 = MROWS * 1024 / 8;   // 524288
    const int NQ  = 1024 * 2048 / 8;    // 262144
    const int NK  = 1024 * 1024 / 8;    // 131072
    const float* in;
    __half* outp;
    int li;
    if (idx < NH8)                        { in = hid; outp = hidh; li = idx; }
    else if (idx < NH8 + NQ)              { in = Wq; outp = wqh; li = idx - NH8; }
    else if (idx < NH8 + NQ + NK)         { in = Wk; outp = wkh; li = idx - NH8 - NQ; }
    else if (idx < NH8 + NQ + 2 * NK)     { in = Wv; outp = wvh; li = idx - NH8 - NQ - NK; }
    else if (idx < NH8 + 2 * NQ + 2 * NK) { in = Wo; outp = woh; li = idx - NH8 - NQ - 2 * NK; }
    else return;
    const float4 x0 = ((const float4*)in)[2 * li];
    const float4 x1 = ((const float4*)in)[2 * li + 1];
    uint4 h;
    h.x = cvt2h(x0.x, x0.y);
    h.y = cvt2h(x0.z, x0.w);
    h.z = cvt2h(x1.x, x1.y);
    h.w = cvt2h(x1.z, x1.w);
    ((uint4*)outp)[li] = h;
}

// ============================================================================
// GEMM core, templated on term count:
//   TWO=true : C = Ah*Bh + Al*Bh  (Wo path)
//   TWO=false: C = Ah*Bh          (QKV path)
// CTA tile 128x128, KC=32, cp.async 3 stages, 256 threads, 2 CTAs/SM.
// Stage: Ah (128x80B=10240) [Al +10240 if TWO] | Bh (32x272B=8704).
// ============================================================================
template <bool TWO>
__device__ __forceinline__ void gemm_body(
    const __half* __restrict__ Ah, const __half* __restrict__ Al,
    const __half* __restrict__ Bh, float* __restrict__ C,
    int m0, int n0, int N, int K, uint32_t sbase) {

    constexpr uint32_t BOFF = TWO ? 20480u : 10240u;
    constexpr uint32_t STG  = TWO ? 29184u : 18944u;

    const int tid  = threadIdx.x;
    const int lane = tid & 31;
    const int wid  = tid >> 5;
    const int wm = (wid >> 2) * 64;
    const int wn = (wid & 3) * 32;

    float acc[4][4][4];
#pragma unroll
    for (int i = 0; i < 4; i++)
#pragma unroll
        for (int j = 0; j < 4; j++)
#pragma unroll
            for (int r = 0; r < 4; r++) acc[i][j][r] = 0.0f;

    const int a_row = tid >> 1;
    const int a_off = (tid & 1) * 16;
    const int b_kr  = tid >> 3;
    const int b_off = (tid & 7) * 16;

    const int nch = K >> 5;

#pragma unroll
    for (int c = 0; c < 2; c++) {
        const uint32_t st = sbase + (uint32_t)c * STG;
        const __half* ah = Ah + (size_t)(m0 + a_row) * K + c * 32 + a_off;
        uint32_t da = st + (uint32_t)(a_row * 80 + a_off * 2);
        CP_ASYNC16(da, ah);
        CP_ASYNC16(da + 16, ah + 8);
        if (TWO) {
            const __half* al = Al + (size_t)(m0 + a_row) * K + c * 32 + a_off;
            CP_ASYNC16(da + 10240, al);
            CP_ASYNC16(da + 10256, al + 8);
        }
        const __half* bh = Bh + (size_t)(c * 32 + b_kr) * N + n0 + b_off;
        uint32_t db = st + BOFF + (uint32_t)(b_kr * 272 + b_off * 2);
        CP_ASYNC16(db, bh);
        CP_ASYNC16(db + 16, bh + 8);
        CP_COMMIT();
    }

    for (int c = 0; c < nch; c++) {
        CP_WAIT1();
        __syncthreads();

        const uint32_t st = sbase + (uint32_t)(c % 3) * STG;
#pragma unroll
        for (int ks = 0; ks < 2; ks++) {
            uint32_t ah[4][4], al[4][4], bh[2][4];
            const uint32_t aoff =
                st + (uint32_t)((wm + (lane & 15)) * 80 +
                                (ks * 16 + ((lane >> 4) << 3)) * 2);
#pragma unroll
            for (int mt = 0; mt < 4; mt++) {
                ldsm4(ah[mt], aoff + mt * 16 * 80);
                if (TWO) ldsm4(al[mt], aoff + mt * 16 * 80 + 10240);
            }
            const uint32_t bbase =
                st + BOFF + (uint32_t)((ks * 16 + (lane & 15)) * 272 +
                                       (wn + ((lane >> 4) << 3)) * 2);
#pragma unroll
            for (int ng = 0; ng < 2; ng++)
                ldsm4t(bh[ng], bbase + ng * 32);
#pragma unroll
            for (int mt = 0; mt < 4; mt++)
#pragma unroll
                for (int nt = 0; nt < 4; nt++) {
                    const int ng = nt >> 1;
                    const int hf = (nt & 1) * 2;
                    mma16816h(acc[mt][nt], ah[mt], bh[ng][hf], bh[ng][hf + 1]);
                    if (TWO)
                        mma16816h(acc[mt][nt], al[mt], bh[ng][hf], bh[ng][hf + 1]);
                }
        }
        __syncthreads();

        const int nc = c + 2;
        if (nc < nch) {
            const uint32_t st2 = sbase + (uint32_t)(nc % 3) * STG;
            const __half* ahp = Ah + (size_t)(m0 + a_row) * K + nc * 32 + a_off;
            uint32_t da = st2 + (uint32_t)(a_row * 80 + a_off * 2);
            CP_ASYNC16(da, ahp);
            CP_ASYNC16(da + 16, ahp + 8);
            if (TWO) {
                const __half* alp = Al + (size_t)(m0 + a_row) * K + nc * 32 + a_off;
                CP_ASYNC16(da + 10240, alp);
                CP_ASYNC16(da + 10256, alp + 8);
            }
            const __half* bhp = Bh + (size_t)(nc * 32 + b_kr) * N + n0 + b_off;
            uint32_t db = st2 + BOFF + (uint32_t)(b_kr * 272 + b_off * 2);
            CP_ASYNC16(db, bhp);
            CP_ASYNC16(db + 16, bhp + 8);
        }
        CP_COMMIT();
    }

#pragma unroll
    for (int mt = 0; mt < 4; mt++)
#pragma unroll
        for (int nt = 0; nt < 4; nt++) {
            int row = m0 + wm + mt * 16 + (lane >> 2);
            int col = n0 + wn + nt * 8 + (lane & 3) * 2;
            *(float2*)&C[(size_t)row * N + col] =
                make_float2(acc[mt][nt][0], acc[mt][nt][1]);
            *(float2*)&C[(size_t)(row + 8) * N + col] =
                make_float2(acc[mt][nt][2], acc[mt][nt][3]);
        }
}

// Fused QKV (1-term): blockIdx.x spans [Wq 2048 | Wk 1024 | Wv 1024]
__global__ __launch_bounds__(256, 2)
void qkv_gemm_kernel(const __half* __restrict__ Ah,
                     const __half* __restrict__ Wq,
                     const __half* __restrict__ Wk,
                     const __half* __restrict__ Wv,
                     float* __restrict__ q, float* __restrict__ k,
                     float* __restrict__ v) {
    extern __shared__ __align__(16) char dsm[];
    const int n0g = blockIdx.x * 128;
    const __half* Bh;
    float* C;
    int N, n0;
    if (n0g < 2048)      { Bh = Wq; C = q; N = 2048; n0 = n0g; }
    else if (n0g < 3072) { Bh = Wk; C = k; N = 1024; n0 = n0g - 2048; }
    else                 { Bh = Wv; C = v; N = 1024; n0 = n0g - 3072; }
    gemm_body<false>(Ah, nullptr, Bh, C, blockIdx.y * 128, n0, N, 1024,
                     smem_u32(dsm));
}

// Wo projection (2-term)
__global__ __launch_bounds__(256, 2)
void wo_gemm_kernel(const __half* __restrict__ Ah,
                    const __half* __restrict__ Al,
                    const __half* __restrict__ Bh,
                    float* __restrict__ C) {
    extern __shared__ __align__(16) char dsm[];
    gemm_body<true>(Ah, Al, Bh, C, blockIdx.y * 128, blockIdx.x * 128, 1024,
                    2048, smem_u32(dsm));
}

// ============================================================================
// RoPE cos/sin table
// ============================================================================
__global__ void rope_table_kernel(const int* __restrict__ pos,
                                  float* __restrict__ ctab,
                                  float* __restrict__ stab) {
    int idx = blockIdx.x * blockDim.x + threadIdx.x;
    if (idx >= S_ * 64) return;
    int s  = idx >> 6;
    int fi = idx & 63;
    float inv = (float)exp(-13.815510557964274 * (double)fi / 64.0);
    float ang = (float)pos[s] * inv;
    float c, sn;
    sincosf(ang, &sn, &c);
    ctab[idx] = c;
    stab[idx] = sn;
}

// ============================================================================
// RMSNorm + RoPE + fp16 conversion (unchanged R12 — proven)
// ============================================================================
__global__ void norm_rope_split_kernel(
    const float* __restrict__ q, const float* __restrict__ k,
    const float* __restrict__ v,
    const float* __restrict__ qw, const float* __restrict__ kw,
    const float* __restrict__ ctab, const float* __restrict__ stab,
    __half* __restrict__ qh, __half* __restrict__ kh,
    __half* __restrict__ vh) {
    const int warp = (blockIdx.x * blockDim.x + threadIdx.x) >> 5;
    const int lane = threadIdx.x & 31;
    const int QROWS = B_ * S_ * NH_;   // 65536
    const int KROWS = B_ * S_ * NKV_;  // 32768

    if (warp >= QROWS + KROWS) {       // ---- v path: plain hi convert
        const int r = warp - QROWS - KROWS;
        float4 x = ((const float4*)(v + (size_t)r * HD_))[lane];
        uint2 hh;
        hh.x = cvt2h(x.x, x.y);
        hh.y = cvt2h(x.z, x.w);
        ((uint2*)(vh + (size_t)r * HD_))[lane] = hh;
        return;
    }

    const float* ptr;
    const float* w;
    int s;
    bool isq = (warp < QROWS);
    int row;
    if (isq) {
        row = warp;
        ptr = q + (size_t)row * HD_;
        w = qw;
        s = (row / NH_) % S_;
    } else {
        row = warp - QROWS;
        ptr = k + (size_t)row * HD_;
        w = kw;
        s = (row / NKV_) % S_;
    }

    float4 x = ((const float4*)ptr)[lane];
    float ss = x.x * x.x + x.y * x.y + x.z * x.z + x.w * x.w;
#pragma unroll
    for (int off = 16; off; off >>= 1)
        ss += __shfl_xor_sync(0xffffffffu, ss, off);
    float rms = rsqrtf(ss * (1.0f / 128.0f) + 1e-6f);

    const int d0 = lane * 4;
    float xn[4];
    xn[0] = x.x * rms * w[d0 + 0];
    xn[1] = x.y * rms * w[d0 + 1];
    xn[2] = x.z * rms * w[d0 + 2];
    xn[3] = x.w * rms * w[d0 + 3];

    float out[4];
#pragma unroll
    for (int j = 0; j < 4; j++) {
        int fi = (d0 + j) & 63;
        float c  = ctab[s * 64 + fi];
        float sn = stab[s * 64 + fi];
        float partner = __shfl_xor_sync(0xffffffffu, xn[j], 16);
        out[j] = (lane < 16) ? (xn[j] * c - partner * sn)
                             : (xn[j] * c + partner * sn);
    }

    if (isq) {
        const float qscale = 0.1275174985f;   // 1/sqrt(128) * log2(e)
        uint2 hh;
        hh.x = cvt2h(out[0] * qscale, out[1] * qscale);
        hh.y = cvt2h(out[2] * qscale, out[3] * qscale);
        ((uint2*)(qh + (size_t)row * HD_))[lane] = hh;
    } else {
        uint2 hh;
        hh.x = cvt2h(out[0], out[1]);
        hh.y = cvt2h(out[2], out[3]);
        ((uint2*)(kh + (size_t)row * HD_))[lane] = hh;
    }
}

// ============================================================================
// Flash attention (unchanged R12 — proven).
// QK = Qh*Kh (hi only), PV = (Ph+Pl)*Vh. K/V double-buffered cp.async.
// SMEM: Qh@0 | K0@34816 V0@52224 | K1@69632 V1@87040 => 104448 B.
// ============================================================================
#define ASTRIDE 272

__global__ __launch_bounds__(256, 1)
void attn_mma_kernel(const __half* __restrict__ qh_g,
                     const __half* __restrict__ kh_g,
                     const __half* __restrict__ vh_g,
                     __half* __restrict__ oh, __half* __restrict__ ol) {
    extern __shared__ __align__(16) char asmem[];
    const uint32_t sb = smem_u32(asmem);
    const uint32_t Qh = sb;
    const uint32_t KV0 = sb + 34816u;

    const int tid = threadIdx.x;
    const int lane = tid & 31;
    const int wid = tid >> 5;
    const int bh = blockIdx.y;
    const int b  = bh >> 4;
    const int h  = bh & 15;
    const int hk = h >> 1;
    const int qt = gridDim.x - 1 - blockIdx.x;
    const int q0 = qt * 128;
    const int wr = wid * 16;

    const int nkt = 2 * (qt + 1);

    // ---- prologue: Q tile + K/V stage 0
    {
        const int r = tid >> 1;
        const int hf = (tid & 1) * 64;
        const __half* qph = qh_g + ((size_t)(b * S_ + q0 + r) * NH_ + h) * HD_ + hf;
        const uint32_t off = (uint32_t)(r * ASTRIDE + hf * 2);
#pragma unroll
        for (int j = 0; j < 8; j++)
            CP_ASYNC16(Qh + off + j * 16, qph + j * 8);
        const int kr = tid >> 2;
        const int qd = (tid & 3) * 32;
        const size_t gro = ((size_t)(b * S_ + kr) * NKV_ + hk) * HD_ + qd;
        const uint32_t koff = KV0 + (uint32_t)(kr * ASTRIDE + qd * 2);
#pragma unroll
        for (int j = 0; j < 4; j++) {
            CP_ASYNC16(koff + j * 16, kh_g + gro + j * 8);
            CP_ASYNC16(koff + 17408u + j * 16, vh_g + gro + j * 8);
        }
        CP_COMMIT();
    }

    float oa[16][4];
    float m_i[2], l_i[2];
#pragma unroll
    for (int nt = 0; nt < 16; nt++)
#pragma unroll
        for (int r = 0; r < 4; r++) oa[nt][r] = 0.0f;
    m_i[0] = m_i[1] = -1e30f;
    l_i[0] = l_i[1] = 0.0f;

    for (int kt = 0; kt < nkt; kt++) {
        __syncthreads();
        if (kt + 1 < nkt) {
            const int kr = tid >> 2;
            const int qd = (tid & 3) * 32;
            const size_t gro =
                ((size_t)(b * S_ + (kt + 1) * 64 + kr) * NKV_ + hk) * HD_ + qd;
            const uint32_t koff = KV0 + (uint32_t)(((kt + 1) & 1) * 34816) +
                                  (uint32_t)(kr * ASTRIDE + qd * 2);
#pragma unroll
            for (int j = 0; j < 4; j++) {
                CP_ASYNC16(koff + j * 16, kh_g + gro + j * 8);
                CP_ASYNC16(koff + 17408u + j * 16, vh_g + gro + j * 8);
            }
        }
        CP_COMMIT();
        CP_WAIT1();
        __syncthreads();

        const int k0 = kt * 64;
        const uint32_t Kst = KV0 + (uint32_t)((kt & 1) * 34816);
        const uint32_t Vst = Kst + 17408u;

        // ---- S = Qh @ Kh^T
        float sc[8][4];
#pragma unroll
        for (int nt = 0; nt < 8; nt++)
#pragma unroll
            for (int r = 0; r < 4; r++) sc[nt][r] = 0.0f;

#pragma unroll
        for (int kc = 0; kc < 8; kc++) {
            const uint32_t aoff =
                (uint32_t)((wr + (lane & 15)) * ASTRIDE +
                           (kc * 16 + ((lane >> 4) << 3)) * 2);
            uint32_t qh4[4];
            ldsm4(qh4, Qh + aoff);
            const uint32_t bbase =
                Kst + (uint32_t)((((lane >> 4) << 3) + (lane & 7)) * ASTRIDE +
                                 (kc * 16 + ((lane >> 3) & 1) * 8) * 2);
#pragma unroll
            for (int bg = 0; bg < 4; bg++) {
                const uint32_t boff = bbase + (uint32_t)(bg * 16 * ASTRIDE);
                uint32_t kh4[4];
                ldsm4(kh4, boff);
                mma16816h(sc[2 * bg], qh4, kh4[0], kh4[1]);
                mma16816h(sc[2 * bg + 1], qh4, kh4[2], kh4[3]);
            }
        }

        // ---- causal mask (diagonal tiles only)
        const int row0 = q0 + wr + (lane >> 2);
        const int row1 = row0 + 8;
        if (kt >= 2 * qt) {
#pragma unroll
            for (int nt = 0; nt < 8; nt++) {
                int cb = k0 + nt * 8 + (lane & 3) * 2;
                if (cb > row0) sc[nt][0] = -1e30f;
                if (cb + 1 > row0) sc[nt][1] = -1e30f;
                if (cb > row1) sc[nt][2] = -1e30f;
                if (cb + 1 > row1) sc[nt][3] = -1e30f;
            }
        }

        // ---- online softmax (base-2, poly exp2)
        float mx0 = sc[0][0], mx1 = sc[0][2];
#pragma unroll
        for (int nt = 0; nt < 8; nt++) {
            mx0 = fmaxf(mx0, fmaxf(sc[nt][0], sc[nt][1]));
            mx1 = fmaxf(mx1, fmaxf(sc[nt][2], sc[nt][3]));
        }
        mx0 = fmaxf(mx0, __shfl_xor_sync(0xffffffffu, mx0, 1));
        mx0 = fmaxf(mx0, __shfl_xor_sync(0xffffffffu, mx0, 2));
        mx1 = fmaxf(mx1, __shfl_xor_sync(0xffffffffu, mx1, 1));
        mx1 = fmaxf(mx1, __shfl_xor_sync(0xffffffffu, mx1, 2));
        const float mn0 = fmaxf(m_i[0], mx0);
        const float mn1 = fmaxf(m_i[1], mx1);
        const float alpha0 = exp2fast(m_i[0] - mn0);
        const float alpha1 = exp2fast(m_i[1] - mn1);
        m_i[0] = mn0;
        m_i[1] = mn1;

        float rs0 = 0.0f, rs1 = 0.0f;
#pragma unroll
        for (int nt = 0; nt < 8; nt++) {
            sc[nt][0] = exp2fast(sc[nt][0] - mn0);
            sc[nt][1] = exp2fast(sc[nt][1] - mn0);
            sc[nt][2] = exp2fast(sc[nt][2] - mn1);
            sc[nt][3] = exp2fast(sc[nt][3] - mn1);
            rs0 += sc[nt][0] + sc[nt][1];
            rs1 += sc[nt][2] + sc[nt][3];
        }
        rs0 += __shfl_xor_sync(0xffffffffu, rs0, 1);
        rs0 += __shfl_xor_sync(0xffffffffu, rs0, 2);
        rs1 += __shfl_xor_sync(0xffffffffu, rs1, 1);
        rs1 += __shfl_xor_sync(0xffffffffu, rs1, 2);
        l_i[0] = l_i[0] * alpha0 + rs0;
        l_i[1] = l_i[1] * alpha1 + rs1;
#pragma unroll
        for (int nt = 0; nt < 16; nt++) {
            oa[nt][0] *= alpha0;
            oa[nt][1] *= alpha0;
            oa[nt][2] *= alpha1;
            oa[nt][3] *= alpha1;
        }

        // ---- O += (Ph+Pl) @ Vh
#pragma unroll
        for (int kc = 0; kc < 4; kc++) {
            uint32_t ph[4], pl[4];
            split2h(sc[2 * kc][0], sc[2 * kc][1], ph[0], pl[0]);
            split2h(sc[2 * kc][2], sc[2 * kc][3], ph[1], pl[1]);
            split2h(sc[2 * kc + 1][0], sc[2 * kc + 1][1], ph[2], pl[2]);
            split2h(sc[2 * kc + 1][2], sc[2 * kc + 1][3], ph[3], pl[3]);
            const uint32_t vbase =
                Vst + (uint32_t)((kc * 16 + (lane & 15)) * ASTRIDE +
                                 (((lane >> 4) << 3)) * 2);
#pragma unroll
            for (int dg = 0; dg < 8; dg++) {
                const uint32_t voff = vbase + (uint32_t)(dg * 32);
                uint32_t vh4[4];
                ldsm4t(vh4, voff);
                mma16816h(oa[2 * dg], ph, vh4[0], vh4[1]);
                mma16816h(oa[2 * dg], pl, vh4[0], vh4[1]);
                mma16816h(oa[2 * dg + 1], ph, vh4[2], vh4[3]);
                mma16816h(oa[2 * dg + 1], pl, vh4[2], vh4[3]);
            }
        }
    }

    // ---- epilogue: O /= l, write fp16 hi/lo directly (Wo-GEMM input layout)
    const float inv0 = 1.0f / l_i[0];
    const float inv1 = 1.0f / l_i[1];
    const int row0 = q0 + wr + (lane >> 2);
#pragma unroll
    for (int nt = 0; nt < 16; nt++) {
        const int d = nt * 8 + (lane & 3) * 2;
        const size_t i0 = (size_t)(b * S_ + row0) * 2048 + h * 128 + d;
        const size_t i1 = (size_t)(b * S_ + row0 + 8) * 2048 + h * 128 + d;
        uint32_t hh, hl;
        split2h(oa[nt][0] * inv0, oa[nt][1] * inv0, hh, hl);
        *(uint32_t*)&oh[i0] = hh;
        *(uint32_t*)&ol[i0] = hl;
        split2h(oa[nt][2] * inv1, oa[nt][3] * inv1, hh, hl);
        *(uint32_t*)&oh[i1] = hh;
        *(uint32_t*)&ol[i1] = hl;
    }
}

// ============================================================================
// launch
// ============================================================================
extern "C" void kernel_launch(void* const* d_in, const int* in_sizes, int n_in,
                              void* d_out, int out_size) {
    const float* hidden = (const float*)d_in[0];
    const int*   pos    = (const int*)d_in[1];
    const float* Wq     = (const float*)d_in[2];
    const float* Wk     = (const float*)d_in[3];
    const float* Wv     = (const float*)d_in[4];
    const float* Wo     = (const float*)d_in[5];
    const float* qw     = (const float*)d_in[6];
    const float* kw     = (const float*)d_in[7];
    float* out = (float*)d_out;

    float *q, *k, *v, *ct, *st;
    cudaGetSymbolAddress((void**)&q,  g_q);
    cudaGetSymbolAddress((void**)&k,  g_k);
    cudaGetSymbolAddress((void**)&v,  g_v);
    cudaGetSymbolAddress((void**)&ct, g_cos);
    cudaGetSymbolAddress((void**)&st, g_sin);

    __half *hidh, *wqh, *wkh, *wvh, *woh, *ath, *atl;
    __half *qh, *kh, *vh;
    cudaGetSymbolAddress((void**)&hidh, g_hid_h);
    cudaGetSymbolAddress((void**)&wqh,  g_wq_h);
    cudaGetSymbolAddress((void**)&wkh,  g_wk_h);
    cudaGetSymbolAddress((void**)&wvh,  g_wv_h);
    cudaGetSymbolAddress((void**)&woh,  g_wo_h);
    cudaGetSymbolAddress((void**)&ath,  g_at_h);
    cudaGetSymbolAddress((void**)&atl,  g_at_l);
    cudaGetSymbolAddress((void**)&qh,   g_qh);
    cudaGetSymbolAddress((void**)&kh,   g_kh);
    cudaGetSymbolAddress((void**)&vh,   g_vh);

    // ---- all fp32->fp16 conversions in ONE launch
    {
        int total = MROWS * 1024 / 8 + 2 * (1024 * 2048 / 8) +
                    2 * (1024 * 1024 / 8);            // 1310720
        convert_all_kernel<<<(total + 255) / 256, 256>>>(
            hidden, Wq, Wk, Wv, Wo, hidh, wqh, wkh, wvh, woh);
    }

    const int qkv_smem = 3 * 18944;   // 56832
    const int wo_smem  = 3 * 29184;   // 87552
    cudaFuncSetAttribute(qkv_gemm_kernel,
                         cudaFuncAttributeMaxDynamicSharedMemorySize, qkv_smem);
    cudaFuncSetAttribute(wo_gemm_kernel,
                         cudaFuncAttributeMaxDynamicSharedMemorySize, wo_smem);

    // fused QKV projection (1-term fp16; one launch; concatenated N = 4096)
    qkv_gemm_kernel<<<dim3(4096 / 128, MROWS / 128), 256, qkv_smem>>>(
        hidh, wqh, wkh, wvh, q, k, v);

    // RoPE table + RMSNorm/RoPE + fp16 conversion (q hi, k hi, v hi)
    rope_table_kernel<<<(S_ * 64 + 255) / 256, 256>>>(pos, ct, st);
    {
        int total_warps = B_ * S_ * (NH_ + NKV_ + NKV_);   // 131072
        norm_rope_split_kernel<<<total_warps / 8, 256>>>(
            q, k, v, qw, kw, ct, st, qh, kh, vh);
    }

    // attention (QK hi-only; PV 2-term; double-buffered K/V)
    {
        const int attn_smem = 104448;
        cudaFuncSetAttribute(attn_mma_kernel,
                             cudaFuncAttributeMaxDynamicSharedMemorySize,
                             attn_smem);
        attn_mma_kernel<<<dim3(S_ / 128, B_ * NH_), 256, attn_smem>>>(
            qh, kh, vh, ath, atl);
    }

    // output projection (fp16 2-term)
    wo_gemm_kernel<<<dim3(1024 / 128, MROWS / 128), 256, wo_smem>>>(
        ath, atl, woh, out);
}

// round 14
// speedup vs baseline: 1.9044x; 1.0927x over previous
#include <cuda_runtime.h>
#include <cuda_bf16.h>
#include <cuda_fp16.h>
#include <math.h>
#include <stdint.h>

#define B_   2
#define S_   2048
#define NH_  16
#define NKV_ 8
#define HD_  128
#define MROWS (B_ * S_)          // 4096

// ---------------- scratch (device globals; no allocation allowed) ----------
__device__ float g_q[(size_t)B_ * S_ * NH_ * HD_];
__device__ float g_k[(size_t)B_ * S_ * NKV_ * HD_];
__device__ float g_v[(size_t)B_ * S_ * NKV_ * HD_];
__device__ float g_cos[S_ * 64];
__device__ float g_sin[S_ * 64];
// pre-converted fp16 copies (hidden + weights: hi only)
__device__ __half g_hid_h[(size_t)MROWS * 1024];
__device__ __half g_wq_h[(size_t)1024 * 2048];
__device__ __half g_wk_h[(size_t)1024 * 1024];
__device__ __half g_wv_h[(size_t)1024 * 1024];
__device__ __half g_wo_h[(size_t)2048 * 1024];
// attention output: hi/lo (Wo stays 2-term)
__device__ __half g_at_h[(size_t)MROWS * 2048];
__device__ __half g_at_l[(size_t)MROWS * 2048];
// fp16 q/k/v for attention (q pre-scaled hi only; k,v hi only)
__device__ __half g_qh[(size_t)B_ * S_ * NH_ * HD_];
__device__ __half g_kh[(size_t)B_ * S_ * NKV_ * HD_];
__device__ __half g_vh[(size_t)B_ * S_ * NKV_ * HD_];

// ---------------- helpers ---------------------------------------------------
__device__ __forceinline__ uint32_t smem_u32(const void* p) {
    uint32_t a;
    asm("{ .reg .u64 t; cvta.to.shared.u64 t, %1; cvt.u32.u64 %0, t; }"
        : "=r"(a) : "l"(p));
    return a;
}
__device__ __forceinline__ void ldsm4(uint32_t* r, uint32_t addr) {
    asm volatile("ldmatrix.sync.aligned.m8n8.x4.shared.b16 {%0,%1,%2,%3}, [%4];"
                 : "=r"(r[0]), "=r"(r[1]), "=r"(r[2]), "=r"(r[3]) : "r"(addr));
}
__device__ __forceinline__ void ldsm4t(uint32_t* r, uint32_t addr) {
    asm volatile("ldmatrix.sync.aligned.m8n8.x4.trans.shared.b16 {%0,%1,%2,%3}, [%4];"
                 : "=r"(r[0]), "=r"(r[1]), "=r"(r[2]), "=r"(r[3]) : "r"(addr));
}
// fp16 mma, f32 accum
__device__ __forceinline__ void mma16816h(float* c, const uint32_t* a,
                                          uint32_t b0, uint32_t b1) {
    asm volatile(
        "mma.sync.aligned.m16n8k16.row.col.f32.f16.f16.f32 "
        "{%0,%1,%2,%3}, {%4,%5,%6,%7}, {%8,%9}, {%0,%1,%2,%3};"
        : "+f"(c[0]), "+f"(c[1]), "+f"(c[2]), "+f"(c[3])
        : "r"(a[0]), "r"(a[1]), "r"(a[2]), "r"(a[3]), "r"(b0), "r"(b1));
}
// fp16 hi/lo split (packed half2)
__device__ __forceinline__ void split2h(float a, float b, uint32_t& hi, uint32_t& lo) {
    __half2 h = __floats2half2_rn(a, b);
    float2 hf = __half22float2(h);
    __half2 l = __floats2half2_rn(a - hf.x, b - hf.y);
    hi = *(uint32_t*)&h;
    lo = *(uint32_t*)&l;
}
__device__ __forceinline__ uint32_t cvt2h(float a, float b) {
    __half2 h = __floats2half2_rn(a, b);
    return *(uint32_t*)&h;
}
// fast 2^y on the FMA pipe (no MUFU)
__device__ __forceinline__ float exp2fast(float y) {
    y = fmaxf(y, -126.0f);
    float r = y + 12582912.0f;
    float kf = r - 12582912.0f;
    float f = y - kf;
    float p = 1.3333558146e-3f;
    p = fmaf(p, f, 9.6181291076e-3f);
    p = fmaf(p, f, 5.5504108664e-2f);
    p = fmaf(p, f, 2.4022650696e-1f);
    p = fmaf(p, f, 6.9314718056e-1f);
    p = fmaf(p, f, 1.0f);
    return __int_as_float(__float_as_int(p) + (__float_as_int(r) << 23));
}

#define CP_ASYNC16(dst, src) \
    asm volatile("cp.async.cg.shared.global [%0], [%1], 16;" \
                 :: "r"(dst), "l"(src))
#define CP_COMMIT() asm volatile("cp.async.commit_group;" ::: "memory")
#define CP_WAIT1()  asm volatile("cp.async.wait_group 1;" ::: "memory")

// ============================================================================
// ONE conversion kernel: fp32 -> fp16 hi for hidden + all four weights.
// ============================================================================
__global__ void convert_all_kernel(const float* __restrict__ hid,
                                   const float* __restrict__ Wq,
                                   const float* __restrict__ Wk,
                                   const float* __restrict__ Wv,
                                   const float* __restrict__ Wo,
                                   __half* __restrict__ hidh,
                                   __half* __restrict__ wqh,
                                   __half* __restrict__ wkh,
                                   __half* __restrict__ wvh,
                                   __half* __restrict__ woh) {
    int idx = blockIdx.x * blockDim.x + threadIdx.x;
    const int NH8 = MROWS * 1024 / 8;   // 524288
    const int NQ  = 1024 * 2048 / 8;    // 262144
    const int NK  = 1024 * 1024 / 8;    // 131072
    const float* in;
    __half* outp;
    int li;
    if (idx < NH8)                        { in = hid; outp = hidh; li = idx; }
    else if (idx < NH8 + NQ)              { in = Wq; outp = wqh; li = idx - NH8; }
    else if (idx < NH8 + NQ + NK)         { in = Wk; outp = wkh; li = idx - NH8 - NQ; }
    else if (idx < NH8 + NQ + 2 * NK)     { in = Wv; outp = wvh; li = idx - NH8 - NQ - NK; }
    else if (idx < NH8 + 2 * NQ + 2 * NK) { in = Wo; outp = woh; li = idx - NH8 - NQ - 2 * NK; }
    else return;
    const float4 x0 = ((const float4*)in)[2 * li];
    const float4 x1 = ((const float4*)in)[2 * li + 1];
    uint4 h;
    h.x = cvt2h(x0.x, x0.y);
    h.y = cvt2h(x0.z, x0.w);
    h.z = cvt2h(x1.x, x1.y);
    h.w = cvt2h(x1.z, x1.w);
    ((uint4*)outp)[li] = h;
}

// ============================================================================
// GEMM core, templated on term count (unchanged R13 — proven).
// ============================================================================
template <bool TWO>
__device__ __forceinline__ void gemm_body(
    const __half* __restrict__ Ah, const __half* __restrict__ Al,
    const __half* __restrict__ Bh, float* __restrict__ C,
    int m0, int n0, int N, int K, uint32_t sbase) {

    constexpr uint32_t BOFF = TWO ? 20480u : 10240u;
    constexpr uint32_t STG  = TWO ? 29184u : 18944u;

    const int tid  = threadIdx.x;
    const int lane = tid & 31;
    const int wid  = tid >> 5;
    const int wm = (wid >> 2) * 64;
    const int wn = (wid & 3) * 32;

    float acc[4][4][4];
#pragma unroll
    for (int i = 0; i < 4; i++)
#pragma unroll
        for (int j = 0; j < 4; j++)
#pragma unroll
            for (int r = 0; r < 4; r++) acc[i][j][r] = 0.0f;

    const int a_row = tid >> 1;
    const int a_off = (tid & 1) * 16;
    const int b_kr  = tid >> 3;
    const int b_off = (tid & 7) * 16;

    const int nch = K >> 5;

#pragma unroll
    for (int c = 0; c < 2; c++) {
        const uint32_t st = sbase + (uint32_t)c * STG;
        const __half* ah = Ah + (size_t)(m0 + a_row) * K + c * 32 + a_off;
        uint32_t da = st + (uint32_t)(a_row * 80 + a_off * 2);
        CP_ASYNC16(da, ah);
        CP_ASYNC16(da + 16, ah + 8);
        if (TWO) {
            const __half* al = Al + (size_t)(m0 + a_row) * K + c * 32 + a_off;
            CP_ASYNC16(da + 10240, al);
            CP_ASYNC16(da + 10256, al + 8);
        }
        const __half* bh = Bh + (size_t)(c * 32 + b_kr) * N + n0 + b_off;
        uint32_t db = st + BOFF + (uint32_t)(b_kr * 272 + b_off * 2);
        CP_ASYNC16(db, bh);
        CP_ASYNC16(db + 16, bh + 8);
        CP_COMMIT();
    }

    for (int c = 0; c < nch; c++) {
        CP_WAIT1();
        __syncthreads();

        const uint32_t st = sbase + (uint32_t)(c % 3) * STG;
#pragma unroll
        for (int ks = 0; ks < 2; ks++) {
            uint32_t ah[4][4], al[4][4], bh[2][4];
            const uint32_t aoff =
                st + (uint32_t)((wm + (lane & 15)) * 80 +
                                (ks * 16 + ((lane >> 4) << 3)) * 2);
#pragma unroll
            for (int mt = 0; mt < 4; mt++) {
                ldsm4(ah[mt], aoff + mt * 16 * 80);
                if (TWO) ldsm4(al[mt], aoff + mt * 16 * 80 + 10240);
            }
            const uint32_t bbase =
                st + BOFF + (uint32_t)((ks * 16 + (lane & 15)) * 272 +
                                       (wn + ((lane >> 4) << 3)) * 2);
#pragma unroll
            for (int ng = 0; ng < 2; ng++)
                ldsm4t(bh[ng], bbase + ng * 32);
#pragma unroll
            for (int mt = 0; mt < 4; mt++)
#pragma unroll
                for (int nt = 0; nt < 4; nt++) {
                    const int ng = nt >> 1;
                    const int hf = (nt & 1) * 2;
                    mma16816h(acc[mt][nt], ah[mt], bh[ng][hf], bh[ng][hf + 1]);
                    if (TWO)
                        mma16816h(acc[mt][nt], al[mt], bh[ng][hf], bh[ng][hf + 1]);
                }
        }
        __syncthreads();

        const int nc = c + 2;
        if (nc < nch) {
            const uint32_t st2 = sbase + (uint32_t)(nc % 3) * STG;
            const __half* ahp = Ah + (size_t)(m0 + a_row) * K + nc * 32 + a_off;
            uint32_t da = st2 + (uint32_t)(a_row * 80 + a_off * 2);
            CP_ASYNC16(da, ahp);
            CP_ASYNC16(da + 16, ahp + 8);
            if (TWO) {
                const __half* alp = Al + (size_t)(m0 + a_row) * K + nc * 32 + a_off;
                CP_ASYNC16(da + 10240, alp);
                CP_ASYNC16(da + 10256, alp + 8);
            }
            const __half* bhp = Bh + (size_t)(nc * 32 + b_kr) * N + n0 + b_off;
            uint32_t db = st2 + BOFF + (uint32_t)(b_kr * 272 + b_off * 2);
            CP_ASYNC16(db, bhp);
            CP_ASYNC16(db + 16, bhp + 8);
        }
        CP_COMMIT();
    }

#pragma unroll
    for (int mt = 0; mt < 4; mt++)
#pragma unroll
        for (int nt = 0; nt < 4; nt++) {
            int row = m0 + wm + mt * 16 + (lane >> 2);
            int col = n0 + wn + nt * 8 + (lane & 3) * 2;
            *(float2*)&C[(size_t)row * N + col] =
                make_float2(acc[mt][nt][0], acc[mt][nt][1]);
            *(float2*)&C[(size_t)(row + 8) * N + col] =
                make_float2(acc[mt][nt][2], acc[mt][nt][3]);
        }
}

// Fused QKV (1-term): blockIdx.x spans [Wq 2048 | Wk 1024 | Wv 1024]
__global__ __launch_bounds__(256, 2)
void qkv_gemm_kernel(const __half* __restrict__ Ah,
                     const __half* __restrict__ Wq,
                     const __half* __restrict__ Wk,
                     const __half* __restrict__ Wv,
                     float* __restrict__ q, float* __restrict__ k,
                     float* __restrict__ v) {
    extern __shared__ __align__(16) char dsm[];
    const int n0g = blockIdx.x * 128;
    const __half* Bh;
    float* C;
    int N, n0;
    if (n0g < 2048)      { Bh = Wq; C = q; N = 2048; n0 = n0g; }
    else if (n0g < 3072) { Bh = Wk; C = k; N = 1024; n0 = n0g - 2048; }
    else                 { Bh = Wv; C = v; N = 1024; n0 = n0g - 3072; }
    gemm_body<false>(Ah, nullptr, Bh, C, blockIdx.y * 128, n0, N, 1024,
                     smem_u32(dsm));
}

// Wo projection (2-term)
__global__ __launch_bounds__(256, 2)
void wo_gemm_kernel(const __half* __restrict__ Ah,
                    const __half* __restrict__ Al,
                    const __half* __restrict__ Bh,
                    float* __restrict__ C) {
    extern __shared__ __align__(16) char dsm[];
    gemm_body<true>(Ah, Al, Bh, C, blockIdx.y * 128, blockIdx.x * 128, 1024,
                    2048, smem_u32(dsm));
}

// ============================================================================
// RoPE cos/sin table
// ============================================================================
__global__ void rope_table_kernel(const int* __restrict__ pos,
                                  float* __restrict__ ctab,
                                  float* __restrict__ stab) {
    int idx = blockIdx.x * blockDim.x + threadIdx.x;
    if (idx >= S_ * 64) return;
    int s  = idx >> 6;
    int fi = idx & 63;
    float inv = (float)exp(-13.815510557964274 * (double)fi / 64.0);
    float ang = (float)pos[s] * inv;
    float c, sn;
    sincosf(ang, &sn, &c);
    ctab[idx] = c;
    stab[idx] = sn;
}

// ============================================================================
// RMSNorm + RoPE + fp16 conversion (unchanged R12/R13 — proven)
// ============================================================================
__global__ void norm_rope_split_kernel(
    const float* __restrict__ q, const float* __restrict__ k,
    const float* __restrict__ v,
    const float* __restrict__ qw, const float* __restrict__ kw,
    const float* __restrict__ ctab, const float* __restrict__ stab,
    __half* __restrict__ qh, __half* __restrict__ kh,
    __half* __restrict__ vh) {
    const int warp = (blockIdx.x * blockDim.x + threadIdx.x) >> 5;
    const int lane = threadIdx.x & 31;
    const int QROWS = B_ * S_ * NH_;   // 65536
    const int KROWS = B_ * S_ * NKV_;  // 32768

    if (warp >= QROWS + KROWS) {       // ---- v path: plain hi convert
        const int r = warp - QROWS - KROWS;
        float4 x = ((const float4*)(v + (size_t)r * HD_))[lane];
        uint2 hh;
        hh.x = cvt2h(x.x, x.y);
        hh.y = cvt2h(x.z, x.w);
        ((uint2*)(vh + (size_t)r * HD_))[lane] = hh;
        return;
    }

    const float* ptr;
    const float* w;
    int s;
    bool isq = (warp < QROWS);
    int row;
    if (isq) {
        row = warp;
        ptr = q + (size_t)row * HD_;
        w = qw;
        s = (row / NH_) % S_;
    } else {
        row = warp - QROWS;
        ptr = k + (size_t)row * HD_;
        w = kw;
        s = (row / NKV_) % S_;
    }

    float4 x = ((const float4*)ptr)[lane];
    float ss = x.x * x.x + x.y * x.y + x.z * x.z + x.w * x.w;
#pragma unroll
    for (int off = 16; off; off >>= 1)
        ss += __shfl_xor_sync(0xffffffffu, ss, off);
    float rms = rsqrtf(ss * (1.0f / 128.0f) + 1e-6f);

    const int d0 = lane * 4;
    float xn[4];
    xn[0] = x.x * rms * w[d0 + 0];
    xn[1] = x.y * rms * w[d0 + 1];
    xn[2] = x.z * rms * w[d0 + 2];
    xn[3] = x.w * rms * w[d0 + 3];

    float out[4];
#pragma unroll
    for (int j = 0; j < 4; j++) {
        int fi = (d0 + j) & 63;
        float c  = ctab[s * 64 + fi];
        float sn = stab[s * 64 + fi];
        float partner = __shfl_xor_sync(0xffffffffu, xn[j], 16);
        out[j] = (lane < 16) ? (xn[j] * c - partner * sn)
                             : (xn[j] * c + partner * sn);
    }

    if (isq) {
        const float qscale = 0.1275174985f;   // 1/sqrt(128) * log2(e)
        uint2 hh;
        hh.x = cvt2h(out[0] * qscale, out[1] * qscale);
        hh.y = cvt2h(out[2] * qscale, out[3] * qscale);
        ((uint2*)(qh + (size_t)row * HD_))[lane] = hh;
    } else {
        uint2 hh;
        hh.x = cvt2h(out[0], out[1]);
        hh.y = cvt2h(out[2], out[3]);
        ((uint2*)(kh + (size_t)row * HD_))[lane] = hh;
    }
}

// ============================================================================
// Flash attention, fully hi-only: QK = Qh*Kh, PV = Ph*Vh.
// K/V double-buffered cp.async.
// SMEM: Qh@0 | K0@34816 V0@52224 | K1@69632 V1@87040 => 104448 B.
// ============================================================================
#define ASTRIDE 272

__global__ __launch_bounds__(256, 1)
void attn_mma_kernel(const __half* __restrict__ qh_g,
                     const __half* __restrict__ kh_g,
                     const __half* __restrict__ vh_g,
                     __half* __restrict__ oh, __half* __restrict__ ol) {
    extern __shared__ __align__(16) char asmem[];
    const uint32_t sb = smem_u32(asmem);
    const uint32_t Qh = sb;
    const uint32_t KV0 = sb + 34816u;

    const int tid = threadIdx.x;
    const int lane = tid & 31;
    const int wid = tid >> 5;
    const int bh = blockIdx.y;
    const int b  = bh >> 4;
    const int h  = bh & 15;
    const int hk = h >> 1;
    const int qt = gridDim.x - 1 - blockIdx.x;
    const int q0 = qt * 128;
    const int wr = wid * 16;

    const int nkt = 2 * (qt + 1);

    // ---- prologue: Q tile + K/V stage 0
    {
        const int r = tid >> 1;
        const int hf = (tid & 1) * 64;
        const __half* qph = qh_g + ((size_t)(b * S_ + q0 + r) * NH_ + h) * HD_ + hf;
        const uint32_t off = (uint32_t)(r * ASTRIDE + hf * 2);
#pragma unroll
        for (int j = 0; j < 8; j++)
            CP_ASYNC16(Qh + off + j * 16, qph + j * 8);
        const int kr = tid >> 2;
        const int qd = (tid & 3) * 32;
        const size_t gro = ((size_t)(b * S_ + kr) * NKV_ + hk) * HD_ + qd;
        const uint32_t koff = KV0 + (uint32_t)(kr * ASTRIDE + qd * 2);
#pragma unroll
        for (int j = 0; j < 4; j++) {
            CP_ASYNC16(koff + j * 16, kh_g + gro + j * 8);
            CP_ASYNC16(koff + 17408u + j * 16, vh_g + gro + j * 8);
        }
        CP_COMMIT();
    }

    float oa[16][4];
    float m_i[2], l_i[2];
#pragma unroll
    for (int nt = 0; nt < 16; nt++)
#pragma unroll
        for (int r = 0; r < 4; r++) oa[nt][r] = 0.0f;
    m_i[0] = m_i[1] = -1e30f;
    l_i[0] = l_i[1] = 0.0f;

    for (int kt = 0; kt < nkt; kt++) {
        __syncthreads();
        if (kt + 1 < nkt) {
            const int kr = tid >> 2;
            const int qd = (tid & 3) * 32;
            const size_t gro =
                ((size_t)(b * S_ + (kt + 1) * 64 + kr) * NKV_ + hk) * HD_ + qd;
            const uint32_t koff = KV0 + (uint32_t)(((kt + 1) & 1) * 34816) +
                                  (uint32_t)(kr * ASTRIDE + qd * 2);
#pragma unroll
            for (int j = 0; j < 4; j++) {
                CP_ASYNC16(koff + j * 16, kh_g + gro + j * 8);
                CP_ASYNC16(koff + 17408u + j * 16, vh_g + gro + j * 8);
            }
        }
        CP_COMMIT();
        CP_WAIT1();
        __syncthreads();

        const int k0 = kt * 64;
        const uint32_t Kst = KV0 + (uint32_t)((kt & 1) * 34816);
        const uint32_t Vst = Kst + 17408u;

        // ---- S = Qh @ Kh^T
        float sc[8][4];
#pragma unroll
        for (int nt = 0; nt < 8; nt++)
#pragma unroll
            for (int r = 0; r < 4; r++) sc[nt][r] = 0.0f;

#pragma unroll
        for (int kc = 0; kc < 8; kc++) {
            const uint32_t aoff =
                (uint32_t)((wr + (lane & 15)) * ASTRIDE +
                           (kc * 16 + ((lane >> 4) << 3)) * 2);
            uint32_t qh4[4];
            ldsm4(qh4, Qh + aoff);
            const uint32_t bbase =
                Kst + (uint32_t)((((lane >> 4) << 3) + (lane & 7)) * ASTRIDE +
                                 (kc * 16 + ((lane >> 3) & 1) * 8) * 2);
#pragma unroll
            for (int bg = 0; bg < 4; bg++) {
                const uint32_t boff = bbase + (uint32_t)(bg * 16 * ASTRIDE);
                uint32_t kh4[4];
                ldsm4(kh4, boff);
                mma16816h(sc[2 * bg], qh4, kh4[0], kh4[1]);
                mma16816h(sc[2 * bg + 1], qh4, kh4[2], kh4[3]);
            }
        }

        // ---- causal mask (diagonal tiles only)
        const int row0 = q0 + wr + (lane >> 2);
        const int row1 = row0 + 8;
        if (kt >= 2 * qt) {
#pragma unroll
            for (int nt = 0; nt < 8; nt++) {
                int cb = k0 + nt * 8 + (lane & 3) * 2;
                if (cb > row0) sc[nt][0] = -1e30f;
                if (cb + 1 > row0) sc[nt][1] = -1e30f;
                if (cb > row1) sc[nt][2] = -1e30f;
                if (cb + 1 > row1) sc[nt][3] = -1e30f;
            }
        }

        // ---- online softmax (base-2, poly exp2)
        float mx0 = sc[0][0], mx1 = sc[0][2];
#pragma unroll
        for (int nt = 0; nt < 8; nt++) {
            mx0 = fmaxf(mx0, fmaxf(sc[nt][0], sc[nt][1]));
            mx1 = fmaxf(mx1, fmaxf(sc[nt][2], sc[nt][3]));
        }
        mx0 = fmaxf(mx0, __shfl_xor_sync(0xffffffffu, mx0, 1));
        mx0 = fmaxf(mx0, __shfl_xor_sync(0xffffffffu, mx0, 2));
        mx1 = fmaxf(mx1, __shfl_xor_sync(0xffffffffu, mx1, 1));
        mx1 = fmaxf(mx1, __shfl_xor_sync(0xffffffffu, mx1, 2));
        const float mn0 = fmaxf(m_i[0], mx0);
        const float mn1 = fmaxf(m_i[1], mx1);
        const float alpha0 = exp2fast(m_i[0] - mn0);
        const float alpha1 = exp2fast(m_i[1] - mn1);
        m_i[0] = mn0;
        m_i[1] = mn1;

        float rs0 = 0.0f, rs1 = 0.0f;
#pragma unroll
        for (int nt = 0; nt < 8; nt++) {
            sc[nt][0] = exp2fast(sc[nt][0] - mn0);
            sc[nt][1] = exp2fast(sc[nt][1] - mn0);
            sc[nt][2] = exp2fast(sc[nt][2] - mn1);
            sc[nt][3] = exp2fast(sc[nt][3] - mn1);
            rs0 += sc[nt][0] + sc[nt][1];
            rs1 += sc[nt][2] + sc[nt][3];
        }
        rs0 += __shfl_xor_sync(0xffffffffu, rs0, 1);
        rs0 += __shfl_xor_sync(0xffffffffu, rs0, 2);
        rs1 += __shfl_xor_sync(0xffffffffu, rs1, 1);
        rs1 += __shfl_xor_sync(0xffffffffu, rs1, 2);
        l_i[0] = l_i[0] * alpha0 + rs0;
        l_i[1] = l_i[1] * alpha1 + rs1;
#pragma unroll
        for (int nt = 0; nt < 16; nt++) {
            oa[nt][0] *= alpha0;
            oa[nt][1] *= alpha0;
            oa[nt][2] *= alpha1;
            oa[nt][3] *= alpha1;
        }

        // ---- O += Ph @ Vh (hi only)
#pragma unroll
        for (int kc = 0; kc < 4; kc++) {
            uint32_t ph[4];
            ph[0] = cvt2h(sc[2 * kc][0], sc[2 * kc][1]);
            ph[1] = cvt2h(sc[2 * kc][2], sc[2 * kc][3]);
            ph[2] = cvt2h(sc[2 * kc + 1][0], sc[2 * kc + 1][1]);
            ph[3] = cvt2h(sc[2 * kc + 1][2], sc[2 * kc + 1][3]);
            const uint32_t vbase =
                Vst + (uint32_t)((kc * 16 + (lane & 15)) * ASTRIDE +
                                 (((lane >> 4) << 3)) * 2);
#pragma unroll
            for (int dg = 0; dg < 8; dg++) {
                const uint32_t voff = vbase + (uint32_t)(dg * 32);
                uint32_t vh4[4];
                ldsm4t(vh4, voff);
                mma16816h(oa[2 * dg], ph, vh4[0], vh4[1]);
                mma16816h(oa[2 * dg + 1], ph, vh4[2], vh4[3]);
            }
        }
    }

    // ---- epilogue: O /= l, write fp16 hi/lo directly (Wo-GEMM input layout)
    const float inv0 = 1.0f / l_i[0];
    const float inv1 = 1.0f / l_i[1];
    const int row0 = q0 + wr + (lane >> 2);
#pragma unroll
    for (int nt = 0; nt < 16; nt++) {
        const int d = nt * 8 + (lane & 3) * 2;
        const size_t i0 = (size_t)(b * S_ + row0) * 2048 + h * 128 + d;
        const size_t i1 = (size_t)(b * S_ + row0 + 8) * 2048 + h * 128 + d;
        uint32_t hh, hl;
        split2h(oa[nt][0] * inv0, oa[nt][1] * inv0, hh, hl);
        *(uint32_t*)&oh[i0] = hh;
        *(uint32_t*)&ol[i0] = hl;
        split2h(oa[nt][2] * inv1, oa[nt][3] * inv1, hh, hl);
        *(uint32_t*)&oh[i1] = hh;
        *(uint32_t*)&ol[i1] = hl;
    }
}

// ============================================================================
// launch
// ============================================================================
extern "C" void kernel_launch(void* const* d_in, const int* in_sizes, int n_in,
                              void* d_out, int out_size) {
    const float* hidden = (const float*)d_in[0];
    const int*   pos    = (const int*)d_in[1];
    const float* Wq     = (const float*)d_in[2];
    const float* Wk     = (const float*)d_in[3];
    const float* Wv     = (const float*)d_in[4];
    const float* Wo     = (const float*)d_in[5];
    const float* qw     = (const float*)d_in[6];
    const float* kw     = (const float*)d_in[7];
    float* out = (float*)d_out;

    float *q, *k, *v, *ct, *st;
    cudaGetSymbolAddress((void**)&q,  g_q);
    cudaGetSymbolAddress((void**)&k,  g_k);
    cudaGetSymbolAddress((void**)&v,  g_v);
    cudaGetSymbolAddress((void**)&ct, g_cos);
    cudaGetSymbolAddress((void**)&st, g_sin);

    __half *hidh, *wqh, *wkh, *wvh, *woh, *ath, *atl;
    __half *qh, *kh, *vh;
    cudaGetSymbolAddress((void**)&hidh, g_hid_h);
    cudaGetSymbolAddress((void**)&wqh,  g_wq_h);
    cudaGetSymbolAddress((void**)&wkh,  g_wk_h);
    cudaGetSymbolAddress((void**)&wvh,  g_wv_h);
    cudaGetSymbolAddress((void**)&woh,  g_wo_h);
    cudaGetSymbolAddress((void**)&ath,  g_at_h);
    cudaGetSymbolAddress((void**)&atl,  g_at_l);
    cudaGetSymbolAddress((void**)&qh,   g_qh);
    cudaGetSymbolAddress((void**)&kh,   g_kh);
    cudaGetSymbolAddress((void**)&vh,   g_vh);

    // ---- all fp32->fp16 conversions in ONE launch
    {
        int total = MROWS * 1024 / 8 + 2 * (1024 * 2048 / 8) +
                    2 * (1024 * 1024 / 8);            // 1310720
        convert_all_kernel<<<(total + 255) / 256, 256>>>(
            hidden, Wq, Wk, Wv, Wo, hidh, wqh, wkh, wvh, woh);
    }

    const int qkv_smem = 3 * 18944;   // 56832
    const int wo_smem  = 3 * 29184;   // 87552
    cudaFuncSetAttribute(qkv_gemm_kernel,
                         cudaFuncAttributeMaxDynamicSharedMemorySize, qkv_smem);
    cudaFuncSetAttribute(wo_gemm_kernel,
                         cudaFuncAttributeMaxDynamicSharedMemorySize, wo_smem);

    // fused QKV projection (1-term fp16)
    qkv_gemm_kernel<<<dim3(4096 / 128, MROWS / 128), 256, qkv_smem>>>(
        hidh, wqh, wkh, wvh, q, k, v);

    // RoPE table + RMSNorm/RoPE + fp16 conversion
    rope_table_kernel<<<(S_ * 64 + 255) / 256, 256>>>(pos, ct, st);
    {
        int total_warps = B_ * S_ * (NH_ + NKV_ + NKV_);   // 131072
        norm_rope_split_kernel<<<total_warps / 8, 256>>>(
            q, k, v, qw, kw, ct, st, qh, kh, vh);
    }

    // attention (QK hi-only; PV hi-only; double-buffered K/V)
    {
        const int attn_smem = 104448;
        cudaFuncSetAttribute(attn_mma_kernel,
                             cudaFuncAttributeMaxDynamicSharedMemorySize,
                             attn_smem);
        attn_mma_kernel<<<dim3(S_ / 128, B_ * NH_), 256, attn_smem>>>(
            qh, kh, vh, ath, atl);
    }

    // output projection (fp16 2-term)
    wo_gemm_kernel<<<dim3(1024 / 128, MROWS / 128), 256, wo_smem>>>(
        ath, atl, woh, out);
}

// round 15
// speedup vs baseline: 2.1322x; 1.1196x over previous
#include <cuda_runtime.h>
#include <cuda_bf16.h>
#include <cuda_fp16.h>
#include <math.h>
#include <stdint.h>

#define B_   2
#define S_   2048
#define NH_  16
#define NKV_ 8
#define HD_  128
#define MROWS (B_ * S_)          // 4096

// ---------------- scratch (device globals; no allocation allowed) ----------
__device__ float g_q[(size_t)B_ * S_ * NH_ * HD_];
__device__ float g_k[(size_t)B_ * S_ * NKV_ * HD_];
__device__ float g_v[(size_t)B_ * S_ * NKV_ * HD_];
__device__ float g_cos[S_ * 64];
__device__ float g_sin[S_ * 64];
// pre-converted fp16 copies (hidden + weights: hi only)
__device__ __half g_hid_h[(size_t)MROWS * 1024];
__device__ __half g_wq_h[(size_t)1024 * 2048];
__device__ __half g_wk_h[(size_t)1024 * 1024];
__device__ __half g_wv_h[(size_t)1024 * 1024];
__device__ __half g_wo_h[(size_t)2048 * 1024];
// attention output (hi only — Wo is 1-term now)
__device__ __half g_at_h[(size_t)MROWS * 2048];
// fp16 q/k/v for attention (q pre-scaled hi only; k,v hi only)
__device__ __half g_qh[(size_t)B_ * S_ * NH_ * HD_];
__device__ __half g_kh[(size_t)B_ * S_ * NKV_ * HD_];
__device__ __half g_vh[(size_t)B_ * S_ * NKV_ * HD_];

// ---------------- helpers ---------------------------------------------------
__device__ __forceinline__ uint32_t smem_u32(const void* p) {
    uint32_t a;
    asm("{ .reg .u64 t; cvta.to.shared.u64 t, %1; cvt.u32.u64 %0, t; }"
        : "=r"(a) : "l"(p));
    return a;
}
__device__ __forceinline__ void ldsm4(uint32_t* r, uint32_t addr) {
    asm volatile("ldmatrix.sync.aligned.m8n8.x4.shared.b16 {%0,%1,%2,%3}, [%4];"
                 : "=r"(r[0]), "=r"(r[1]), "=r"(r[2]), "=r"(r[3]) : "r"(addr));
}
__device__ __forceinline__ void ldsm4t(uint32_t* r, uint32_t addr) {
    asm volatile("ldmatrix.sync.aligned.m8n8.x4.trans.shared.b16 {%0,%1,%2,%3}, [%4];"
                 : "=r"(r[0]), "=r"(r[1]), "=r"(r[2]), "=r"(r[3]) : "r"(addr));
}
// fp16 mma, f32 accum
__device__ __forceinline__ void mma16816h(float* c, const uint32_t* a,
                                          uint32_t b0, uint32_t b1) {
    asm volatile(
        "mma.sync.aligned.m16n8k16.row.col.f32.f16.f16.f32 "
        "{%0,%1,%2,%3}, {%4,%5,%6,%7}, {%8,%9}, {%0,%1,%2,%3};"
        : "+f"(c[0]), "+f"(c[1]), "+f"(c[2]), "+f"(c[3])
        : "r"(a[0]), "r"(a[1]), "r"(a[2]), "r"(a[3]), "r"(b0), "r"(b1));
}
__device__ __forceinline__ uint32_t cvt2h(float a, float b) {
    __half2 h = __floats2half2_rn(a, b);
    return *(uint32_t*)&h;
}
// fast 2^y on the FMA pipe (no MUFU)
__device__ __forceinline__ float exp2fast(float y) {
    y = fmaxf(y, -126.0f);
    float r = y + 12582912.0f;
    float kf = r - 12582912.0f;
    float f = y - kf;
    float p = 1.3333558146e-3f;
    p = fmaf(p, f, 9.6181291076e-3f);
    p = fmaf(p, f, 5.5504108664e-2f);
    p = fmaf(p, f, 2.4022650696e-1f);
    p = fmaf(p, f, 6.9314718056e-1f);
    p = fmaf(p, f, 1.0f);
    return __int_as_float(__float_as_int(p) + (__float_as_int(r) << 23));
}

#define CP_ASYNC16(dst, src) \
    asm volatile("cp.async.cg.shared.global [%0], [%1], 16;" \
                 :: "r"(dst), "l"(src))
#define CP_COMMIT() asm volatile("cp.async.commit_group;" ::: "memory")
#define CP_WAIT1()  asm volatile("cp.async.wait_group 1;" ::: "memory")

// ============================================================================
// ONE conversion kernel: fp32 -> fp16 hi for hidden + all four weights.
// ============================================================================
__global__ void convert_all_kernel(const float* __restrict__ hid,
                                   const float* __restrict__ Wq,
                                   const float* __restrict__ Wk,
                                   const float* __restrict__ Wv,
                                   const float* __restrict__ Wo,
                                   __half* __restrict__ hidh,
                                   __half* __restrict__ wqh,
                                   __half* __restrict__ wkh,
                                   __half* __restrict__ wvh,
                                   __half* __restrict__ woh) {
    int idx = blockIdx.x * blockDim.x + threadIdx.x;
    const int NH8 = MROWS * 1024 / 8;   // 524288
    const int NQ  = 1024 * 2048 / 8;    // 262144
    const int NK  = 1024 * 1024 / 8;    // 131072
    const float* in;
    __half* outp;
    int li;
    if (idx < NH8)                        { in = hid; outp = hidh; li = idx; }
    else if (idx < NH8 + NQ)              { in = Wq; outp = wqh; li = idx - NH8; }
    else if (idx < NH8 + NQ + NK)         { in = Wk; outp = wkh; li = idx - NH8 - NQ; }
    else if (idx < NH8 + NQ + 2 * NK)     { in = Wv; outp = wvh; li = idx - NH8 - NQ - NK; }
    else if (idx < NH8 + 2 * NQ + 2 * NK) { in = Wo; outp = woh; li = idx - NH8 - NQ - 2 * NK; }
    else return;
    const float4 x0 = ((const float4*)in)[2 * li];
    const float4 x1 = ((const float4*)in)[2 * li + 1];
    uint4 h;
    h.x = cvt2h(x0.x, x0.y);
    h.y = cvt2h(x0.z, x0.w);
    h.z = cvt2h(x1.x, x1.y);
    h.w = cvt2h(x1.z, x1.w);
    ((uint4*)outp)[li] = h;
}

// ============================================================================
// GEMM core, 1-term fp16: C = Ah*Bh.
// CTA tile 128x128, KC=32, cp.async 3 stages, 256 threads, 2 CTAs/SM.
// Stage: Ah (128x80B=10240) | Bh (32x272B=8704) => 18944 B.
// ============================================================================
#define STG_SZ 18944u

__device__ __forceinline__ void gemm_body(
    const __half* __restrict__ Ah, const __half* __restrict__ Bh,
    float* __restrict__ C, int m0, int n0, int N, int K, uint32_t sbase) {

    const int tid  = threadIdx.x;
    const int lane = tid & 31;
    const int wid  = tid >> 5;
    const int wm = (wid >> 2) * 64;
    const int wn = (wid & 3) * 32;

    float acc[4][4][4];
#pragma unroll
    for (int i = 0; i < 4; i++)
#pragma unroll
        for (int j = 0; j < 4; j++)
#pragma unroll
            for (int r = 0; r < 4; r++) acc[i][j][r] = 0.0f;

    const int a_row = tid >> 1;
    const int a_off = (tid & 1) * 16;
    const int b_kr  = tid >> 3;
    const int b_off = (tid & 7) * 16;

    const int nch = K >> 5;

#pragma unroll
    for (int c = 0; c < 2; c++) {
        const uint32_t st = sbase + (uint32_t)c * STG_SZ;
        const __half* ah = Ah + (size_t)(m0 + a_row) * K + c * 32 + a_off;
        uint32_t da = st + (uint32_t)(a_row * 80 + a_off * 2);
        CP_ASYNC16(da, ah);
        CP_ASYNC16(da + 16, ah + 8);
        const __half* bh = Bh + (size_t)(c * 32 + b_kr) * N + n0 + b_off;
        uint32_t db = st + 10240u + (uint32_t)(b_kr * 272 + b_off * 2);
        CP_ASYNC16(db, bh);
        CP_ASYNC16(db + 16, bh + 8);
        CP_COMMIT();
    }

    for (int c = 0; c < nch; c++) {
        CP_WAIT1();
        __syncthreads();

        const uint32_t st = sbase + (uint32_t)(c % 3) * STG_SZ;
#pragma unroll
        for (int ks = 0; ks < 2; ks++) {
            uint32_t ah[4][4], bh[2][4];
            const uint32_t aoff =
                st + (uint32_t)((wm + (lane & 15)) * 80 +
                                (ks * 16 + ((lane >> 4) << 3)) * 2);
#pragma unroll
            for (int mt = 0; mt < 4; mt++)
                ldsm4(ah[mt], aoff + mt * 16 * 80);
            const uint32_t bbase =
                st + 10240u + (uint32_t)((ks * 16 + (lane & 15)) * 272 +
                                         (wn + ((lane >> 4) << 3)) * 2);
#pragma unroll
            for (int ng = 0; ng < 2; ng++)
                ldsm4t(bh[ng], bbase + ng * 32);
#pragma unroll
            for (int mt = 0; mt < 4; mt++)
#pragma unroll
                for (int nt = 0; nt < 4; nt++) {
                    const int ng = nt >> 1;
                    const int hf = (nt & 1) * 2;
                    mma16816h(acc[mt][nt], ah[mt], bh[ng][hf], bh[ng][hf + 1]);
                }
        }
        __syncthreads();

        const int nc = c + 2;
        if (nc < nch) {
            const uint32_t st2 = sbase + (uint32_t)(nc % 3) * STG_SZ;
            const __half* ahp = Ah + (size_t)(m0 + a_row) * K + nc * 32 + a_off;
            uint32_t da = st2 + (uint32_t)(a_row * 80 + a_off * 2);
            CP_ASYNC16(da, ahp);
            CP_ASYNC16(da + 16, ahp + 8);
            const __half* bhp = Bh + (size_t)(nc * 32 + b_kr) * N + n0 + b_off;
            uint32_t db = st2 + 10240u + (uint32_t)(b_kr * 272 + b_off * 2);
            CP_ASYNC16(db, bhp);
            CP_ASYNC16(db + 16, bhp + 8);
        }
        CP_COMMIT();
    }

#pragma unroll
    for (int mt = 0; mt < 4; mt++)
#pragma unroll
        for (int nt = 0; nt < 4; nt++) {
            int row = m0 + wm + mt * 16 + (lane >> 2);
            int col = n0 + wn + nt * 8 + (lane & 3) * 2;
            *(float2*)&C[(size_t)row * N + col] =
                make_float2(acc[mt][nt][0], acc[mt][nt][1]);
            *(float2*)&C[(size_t)(row + 8) * N + col] =
                make_float2(acc[mt][nt][2], acc[mt][nt][3]);
        }
}

// Fused QKV: blockIdx.x spans [Wq 2048 | Wk 1024 | Wv 1024]
__global__ __launch_bounds__(256, 2)
void qkv_gemm_kernel(const __half* __restrict__ Ah,
                     const __half* __restrict__ Wq,
                     const __half* __restrict__ Wk,
                     const __half* __restrict__ Wv,
                     float* __restrict__ q, float* __restrict__ k,
                     float* __restrict__ v) {
    extern __shared__ __align__(16) char dsm[];
    const int n0g = blockIdx.x * 128;
    const __half* Bh;
    float* C;
    int N, n0;
    if (n0g < 2048)      { Bh = Wq; C = q; N = 2048; n0 = n0g; }
    else if (n0g < 3072) { Bh = Wk; C = k; N = 1024; n0 = n0g - 2048; }
    else                 { Bh = Wv; C = v; N = 1024; n0 = n0g - 3072; }
    gemm_body(Ah, Bh, C, blockIdx.y * 128, n0, N, 1024, smem_u32(dsm));
}

// Wo projection (1-term now)
__global__ __launch_bounds__(256, 2)
void wo_gemm_kernel(const __half* __restrict__ Ah,
                    const __half* __restrict__ Bh,
                    float* __restrict__ C) {
    extern __shared__ __align__(16) char dsm[];
    gemm_body(Ah, Bh, C, blockIdx.y * 128, blockIdx.x * 128, 1024, 2048,
              smem_u32(dsm));
}

// ============================================================================
// RoPE cos/sin table
// ============================================================================
__global__ void rope_table_kernel(const int* __restrict__ pos,
                                  float* __restrict__ ctab,
                                  float* __restrict__ stab) {
    int idx = blockIdx.x * blockDim.x + threadIdx.x;
    if (idx >= S_ * 64) return;
    int s  = idx >> 6;
    int fi = idx & 63;
    float inv = (float)exp(-13.815510557964274 * (double)fi / 64.0);
    float ang = (float)pos[s] * inv;
    float c, sn;
    sincosf(ang, &sn, &c);
    ctab[idx] = c;
    stab[idx] = sn;
}

// ============================================================================
// RMSNorm + RoPE + fp16 conversion (unchanged R12–R14 — proven)
// ============================================================================
__global__ void norm_rope_split_kernel(
    const float* __restrict__ q, const float* __restrict__ k,
    const float* __restrict__ v,
    const float* __restrict__ qw, const float* __restrict__ kw,
    const float* __restrict__ ctab, const float* __restrict__ stab,
    __half* __restrict__ qh, __half* __restrict__ kh,
    __half* __restrict__ vh) {
    const int warp = (blockIdx.x * blockDim.x + threadIdx.x) >> 5;
    const int lane = threadIdx.x & 31;
    const int QROWS = B_ * S_ * NH_;   // 65536
    const int KROWS = B_ * S_ * NKV_;  // 32768

    if (warp >= QROWS + KROWS) {       // ---- v path: plain hi convert
        const int r = warp - QROWS - KROWS;
        float4 x = ((const float4*)(v + (size_t)r * HD_))[lane];
        uint2 hh;
        hh.x = cvt2h(x.x, x.y);
        hh.y = cvt2h(x.z, x.w);
        ((uint2*)(vh + (size_t)r * HD_))[lane] = hh;
        return;
    }

    const float* ptr;
    const float* w;
    int s;
    bool isq = (warp < QROWS);
    int row;
    if (isq) {
        row = warp;
        ptr = q + (size_t)row * HD_;
        w = qw;
        s = (row / NH_) % S_;
    } else {
        row = warp - QROWS;
        ptr = k + (size_t)row * HD_;
        w = kw;
        s = (row / NKV_) % S_;
    }

    float4 x = ((const float4*)ptr)[lane];
    float ss = x.x * x.x + x.y * x.y + x.z * x.z + x.w * x.w;
#pragma unroll
    for (int off = 16; off; off >>= 1)
        ss += __shfl_xor_sync(0xffffffffu, ss, off);
    float rms = rsqrtf(ss * (1.0f / 128.0f) + 1e-6f);

    const int d0 = lane * 4;
    float xn[4];
    xn[0] = x.x * rms * w[d0 + 0];
    xn[1] = x.y * rms * w[d0 + 1];
    xn[2] = x.z * rms * w[d0 + 2];
    xn[3] = x.w * rms * w[d0 + 3];

    float out[4];
#pragma unroll
    for (int j = 0; j < 4; j++) {
        int fi = (d0 + j) & 63;
        float c  = ctab[s * 64 + fi];
        float sn = stab[s * 64 + fi];
        float partner = __shfl_xor_sync(0xffffffffu, xn[j], 16);
        out[j] = (lane < 16) ? (xn[j] * c - partner * sn)
                             : (xn[j] * c + partner * sn);
    }

    if (isq) {
        const float qscale = 0.1275174985f;   // 1/sqrt(128) * log2(e)
        uint2 hh;
        hh.x = cvt2h(out[0] * qscale, out[1] * qscale);
        hh.y = cvt2h(out[2] * qscale, out[3] * qscale);
        ((uint2*)(qh + (size_t)row * HD_))[lane] = hh;
    } else {
        uint2 hh;
        hh.x = cvt2h(out[0], out[1]);
        hh.y = cvt2h(out[2], out[3]);
        ((uint2*)(kh + (size_t)row * HD_))[lane] = hh;
    }
}

// ============================================================================
// Flash attention, fully hi-only (unchanged R14 core); epilogue writes hi only.
// SMEM: Qh@0 | K0@34816 V0@52224 | K1@69632 V1@87040 => 104448 B.
// ============================================================================
#define ASTRIDE 272

__global__ __launch_bounds__(256, 1)
void attn_mma_kernel(const __half* __restrict__ qh_g,
                     const __half* __restrict__ kh_g,
                     const __half* __restrict__ vh_g,
                     __half* __restrict__ oh) {
    extern __shared__ __align__(16) char asmem[];
    const uint32_t sb = smem_u32(asmem);
    const uint32_t Qh = sb;
    const uint32_t KV0 = sb + 34816u;

    const int tid = threadIdx.x;
    const int lane = tid & 31;
    const int wid = tid >> 5;
    const int bh = blockIdx.y;
    const int b  = bh >> 4;
    const int h  = bh & 15;
    const int hk = h >> 1;
    const int qt = gridDim.x - 1 - blockIdx.x;
    const int q0 = qt * 128;
    const int wr = wid * 16;

    const int nkt = 2 * (qt + 1);

    // ---- prologue: Q tile + K/V stage 0
    {
        const int r = tid >> 1;
        const int hf = (tid & 1) * 64;
        const __half* qph = qh_g + ((size_t)(b * S_ + q0 + r) * NH_ + h) * HD_ + hf;
        const uint32_t off = (uint32_t)(r * ASTRIDE + hf * 2);
#pragma unroll
        for (int j = 0; j < 8; j++)
            CP_ASYNC16(Qh + off + j * 16, qph + j * 8);
        const int kr = tid >> 2;
        const int qd = (tid & 3) * 32;
        const size_t gro = ((size_t)(b * S_ + kr) * NKV_ + hk) * HD_ + qd;
        const uint32_t koff = KV0 + (uint32_t)(kr * ASTRIDE + qd * 2);
#pragma unroll
        for (int j = 0; j < 4; j++) {
            CP_ASYNC16(koff + j * 16, kh_g + gro + j * 8);
            CP_ASYNC16(koff + 17408u + j * 16, vh_g + gro + j * 8);
        }
        CP_COMMIT();
    }

    float oa[16][4];
    float m_i[2], l_i[2];
#pragma unroll
    for (int nt = 0; nt < 16; nt++)
#pragma unroll
        for (int r = 0; r < 4; r++) oa[nt][r] = 0.0f;
    m_i[0] = m_i[1] = -1e30f;
    l_i[0] = l_i[1] = 0.0f;

    for (int kt = 0; kt < nkt; kt++) {
        __syncthreads();
        if (kt + 1 < nkt) {
            const int kr = tid >> 2;
            const int qd = (tid & 3) * 32;
            const size_t gro =
                ((size_t)(b * S_ + (kt + 1) * 64 + kr) * NKV_ + hk) * HD_ + qd;
            const uint32_t koff = KV0 + (uint32_t)(((kt + 1) & 1) * 34816) +
                                  (uint32_t)(kr * ASTRIDE + qd * 2);
#pragma unroll
            for (int j = 0; j < 4; j++) {
                CP_ASYNC16(koff + j * 16, kh_g + gro + j * 8);
                CP_ASYNC16(koff + 17408u + j * 16, vh_g + gro + j * 8);
            }
        }
        CP_COMMIT();
        CP_WAIT1();
        __syncthreads();

        const int k0 = kt * 64;
        const uint32_t Kst = KV0 + (uint32_t)((kt & 1) * 34816);
        const uint32_t Vst = Kst + 17408u;

        // ---- S = Qh @ Kh^T
        float sc[8][4];
#pragma unroll
        for (int nt = 0; nt < 8; nt++)
#pragma unroll
            for (int r = 0; r < 4; r++) sc[nt][r] = 0.0f;

#pragma unroll
        for (int kc = 0; kc < 8; kc++) {
            const uint32_t aoff =
                (uint32_t)((wr + (lane & 15)) * ASTRIDE +
                           (kc * 16 + ((lane >> 4) << 3)) * 2);
            uint32_t qh4[4];
            ldsm4(qh4, Qh + aoff);
            const uint32_t bbase =
                Kst + (uint32_t)((((lane >> 4) << 3) + (lane & 7)) * ASTRIDE +
                                 (kc * 16 + ((lane >> 3) & 1) * 8) * 2);
#pragma unroll
            for (int bg = 0; bg < 4; bg++) {
                const uint32_t boff = bbase + (uint32_t)(bg * 16 * ASTRIDE);
                uint32_t kh4[4];
                ldsm4(kh4, boff);
                mma16816h(sc[2 * bg], qh4, kh4[0], kh4[1]);
                mma16816h(sc[2 * bg + 1], qh4, kh4[2], kh4[3]);
            }
        }

        // ---- causal mask (diagonal tiles only)
        const int row0 = q0 + wr + (lane >> 2);
        const int row1 = row0 + 8;
        if (kt >= 2 * qt) {
#pragma unroll
            for (int nt = 0; nt < 8; nt++) {
                int cb = k0 + nt * 8 + (lane & 3) * 2;
                if (cb > row0) sc[nt][0] = -1e30f;
                if (cb + 1 > row0) sc[nt][1] = -1e30f;
                if (cb > row1) sc[nt][2] = -1e30f;
                if (cb + 1 > row1) sc[nt][3] = -1e30f;
            }
        }

        // ---- online softmax (base-2, poly exp2)
        float mx0 = sc[0][0], mx1 = sc[0][2];
#pragma unroll
        for (int nt = 0; nt < 8; nt++) {
            mx0 = fmaxf(mx0, fmaxf(sc[nt][0], sc[nt][1]));
            mx1 = fmaxf(mx1, fmaxf(sc[nt][2], sc[nt][3]));
        }
        mx0 = fmaxf(mx0, __shfl_xor_sync(0xffffffffu, mx0, 1));
        mx0 = fmaxf(mx0, __shfl_xor_sync(0xffffffffu, mx0, 2));
        mx1 = fmaxf(mx1, __shfl_xor_sync(0xffffffffu, mx1, 1));
        mx1 = fmaxf(mx1, __shfl_xor_sync(0xffffffffu, mx1, 2));
        const float mn0 = fmaxf(m_i[0], mx0);
        const float mn1 = fmaxf(m_i[1], mx1);
        const float alpha0 = exp2fast(m_i[0] - mn0);
        const float alpha1 = exp2fast(m_i[1] - mn1);
        m_i[0] = mn0;
        m_i[1] = mn1;

        float rs0 = 0.0f, rs1 = 0.0f;
#pragma unroll
        for (int nt = 0; nt < 8; nt++) {
            sc[nt][0] = exp2fast(sc[nt][0] - mn0);
            sc[nt][1] = exp2fast(sc[nt][1] - mn0);
            sc[nt][2] = exp2fast(sc[nt][2] - mn1);
            sc[nt][3] = exp2fast(sc[nt][3] - mn1);
            rs0 += sc[nt][0] + sc[nt][1];
            rs1 += sc[nt][2] + sc[nt][3];
        }
        rs0 += __shfl_xor_sync(0xffffffffu, rs0, 1);
        rs0 += __shfl_xor_sync(0xffffffffu, rs0, 2);
        rs1 += __shfl_xor_sync(0xffffffffu, rs1, 1);
        rs1 += __shfl_xor_sync(0xffffffffu, rs1, 2);
        l_i[0] = l_i[0] * alpha0 + rs0;
        l_i[1] = l_i[1] * alpha1 + rs1;
#pragma unroll
        for (int nt = 0; nt < 16; nt++) {
            oa[nt][0] *= alpha0;
            oa[nt][1] *= alpha0;
            oa[nt][2] *= alpha1;
            oa[nt][3] *= alpha1;
        }

        // ---- O += Ph @ Vh (hi only)
#pragma unroll
        for (int kc = 0; kc < 4; kc++) {
            uint32_t ph[4];
            ph[0] = cvt2h(sc[2 * kc][0], sc[2 * kc][1]);
            ph[1] = cvt2h(sc[2 * kc][2], sc[2 * kc][3]);
            ph[2] = cvt2h(sc[2 * kc + 1][0], sc[2 * kc + 1][1]);
            ph[3] = cvt2h(sc[2 * kc + 1][2], sc[2 * kc + 1][3]);
            const uint32_t vbase =
                Vst + (uint32_t)((kc * 16 + (lane & 15)) * ASTRIDE +
                                 (((lane >> 4) << 3)) * 2);
#pragma unroll
            for (int dg = 0; dg < 8; dg++) {
                const uint32_t voff = vbase + (uint32_t)(dg * 32);
                uint32_t vh4[4];
                ldsm4t(vh4, voff);
                mma16816h(oa[2 * dg], ph, vh4[0], vh4[1]);
                mma16816h(oa[2 * dg + 1], ph, vh4[2], vh4[3]);
            }
        }
    }

    // ---- epilogue: O /= l, write fp16 hi only (Wo-GEMM input layout)
    const float inv0 = 1.0f / l_i[0];
    const float inv1 = 1.0f / l_i[1];
    const int row0 = q0 + wr + (lane >> 2);
#pragma unroll
    for (int nt = 0; nt < 16; nt++) {
        const int d = nt * 8 + (lane & 3) * 2;
        const size_t i0 = (size_t)(b * S_ + row0) * 2048 + h * 128 + d;
        const size_t i1 = (size_t)(b * S_ + row0 + 8) * 2048 + h * 128 + d;
        *(uint32_t*)&oh[i0] = cvt2h(oa[nt][0] * inv0, oa[nt][1] * inv0);
        *(uint32_t*)&oh[i1] = cvt2h(oa[nt][2] * inv1, oa[nt][3] * inv1);
    }
}

// ============================================================================
// launch
// ============================================================================
extern "C" void kernel_launch(void* const* d_in, const int* in_sizes, int n_in,
                              void* d_out, int out_size) {
    const float* hidden = (const float*)d_in[0];
    const int*   pos    = (const int*)d_in[1];
    const float* Wq     = (const float*)d_in[2];
    const float* Wk     = (const float*)d_in[3];
    const float* Wv     = (const float*)d_in[4];
    const float* Wo     = (const float*)d_in[5];
    const float* qw     = (const float*)d_in[6];
    const float* kw     = (const float*)d_in[7];
    float* out = (float*)d_out;

    float *q, *k, *v, *ct, *st;
    cudaGetSymbolAddress((void**)&q,  g_q);
    cudaGetSymbolAddress((void**)&k,  g_k);
    cudaGetSymbolAddress((void**)&v,  g_v);
    cudaGetSymbolAddress((void**)&ct, g_cos);
    cudaGetSymbolAddress((void**)&st, g_sin);

    __half *hidh, *wqh, *wkh, *wvh, *woh, *ath;
    __half *qh, *kh, *vh;
    cudaGetSymbolAddress((void**)&hidh, g_hid_h);
    cudaGetSymbolAddress((void**)&wqh,  g_wq_h);
    cudaGetSymbolAddress((void**)&wkh,  g_wk_h);
    cudaGetSymbolAddress((void**)&wvh,  g_wv_h);
    cudaGetSymbolAddress((void**)&woh,  g_wo_h);
    cudaGetSymbolAddress((void**)&ath,  g_at_h);
    cudaGetSymbolAddress((void**)&qh,   g_qh);
    cudaGetSymbolAddress((void**)&kh,   g_kh);
    cudaGetSymbolAddress((void**)&vh,   g_vh);

    // ---- all fp32->fp16 conversions in ONE launch
    {
        int total = MROWS * 1024 / 8 + 2 * (1024 * 2048 / 8) +
                    2 * (1024 * 1024 / 8);            // 1310720
        convert_all_kernel<<<(total + 255) / 256, 256>>>(
            hidden, Wq, Wk, Wv, Wo, hidh, wqh, wkh, wvh, woh);
    }

    const int gemm_smem = 3 * (int)STG_SZ;   // 56832
    cudaFuncSetAttribute(qkv_gemm_kernel,
                         cudaFuncAttributeMaxDynamicSharedMemorySize, gemm_smem);
    cudaFuncSetAttribute(wo_gemm_kernel,
                         cudaFuncAttributeMaxDynamicSharedMemorySize, gemm_smem);

    // fused QKV projection (1-term fp16)
    qkv_gemm_kernel<<<dim3(4096 / 128, MROWS / 128), 256, gemm_smem>>>(
        hidh, wqh, wkh, wvh, q, k, v);

    // RoPE table + RMSNorm/RoPE + fp16 conversion
    rope_table_kernel<<<(S_ * 64 + 255) / 256, 256>>>(pos, ct, st);
    {
        int total_warps = B_ * S_ * (NH_ + NKV_ + NKV_);   // 131072
        norm_rope_split_kernel<<<total_warps / 8, 256>>>(
            q, k, v, qw, kw, ct, st, qh, kh, vh);
    }

    // attention (fully hi-only; double-buffered K/V)
    {
        const int attn_smem = 104448;
        cudaFuncSetAttribute(attn_mma_kernel,
                             cudaFuncAttributeMaxDynamicSharedMemorySize,
                             attn_smem);
        attn_mma_kernel<<<dim3(S_ / 128, B_ * NH_), 256, attn_smem>>>(
            qh, kh, vh, ath);
    }

    // output projection (1-term fp16)
    wo_gemm_kernel<<<dim3(1024 / 128, MROWS / 128), 256, gemm_smem>>>(
        ath, woh, out);
}